// round 1
// baseline (speedup 1.0000x reference)
#include <cuda_runtime.h>
#include <math.h>
#include <stdint.h>

// Problem constants
#define B_     2
#define NQ_    1024
#define NK_    2048
#define D_     1024
#define H_     16
#define HD_    64
#define SCALE_ 0.125f   // 64^-0.5

// Scratch (static device globals: allocation-free per harness rules)
__device__ float g_Q[(size_t)B_ * NQ_ * D_];     // 8 MB
__device__ float g_K[(size_t)B_ * NK_ * D_];     // 16 MB
__device__ float g_V[(size_t)B_ * NK_ * D_];     // 16 MB
__device__ float g_ctx[(size_t)B_ * NQ_ * D_];   // 8 MB
__device__ float g_maskf[B_ * NK_];
__device__ int   g_mask_mode;                    // 0=u8, 1=i32, 2=f32

// ---------------------------------------------------------------------------
// Mask dtype detection: scan first B_*NK_ bytes (safe under every candidate
// dtype). bytes>1 => float32 (0x80/0x3F bytes of 1.0f). A '1' byte at an
// unaligned offset => uint8 bool. Otherwise int32 0/1.
// ---------------------------------------------------------------------------
__global__ void detect_mask_kernel(const unsigned char* __restrict__ p) {
    __shared__ int s_nonbin, s_unal;
    int tid = threadIdx.x;
    if (tid == 0) { s_nonbin = 0; s_unal = 0; }
    __syncthreads();
    for (int i = tid; i < B_ * NK_; i += 256) {
        unsigned char v = p[i];
        if (v > 1) s_nonbin = 1;
        else if (v == 1 && (i & 3)) s_unal = 1;
    }
    __syncthreads();
    if (tid == 0) g_mask_mode = s_nonbin ? 2 : (s_unal ? 0 : 1);
}

// ---------------------------------------------------------------------------
// Build float mask (1 = masked) with the reference "safe mask": if an entire
// batch row is masked, unmask position 0.  One block per batch.
// ---------------------------------------------------------------------------
__global__ void prep_mask_kernel(const void* __restrict__ mptr) {
    int b = blockIdx.x;
    int tid = threadIdx.x;          // 256 threads
    __shared__ int anyUnmasked;
    if (tid == 0) anyUnmasked = 0;
    __syncthreads();
    int mode = g_mask_mode;
    float vals[NK_ / 256];
    #pragma unroll
    for (int x = 0; x < NK_ / 256; x++) {
        int i = tid + x * 256;
        float m;
        if (mode == 0)      m = ((const unsigned char*)mptr)[b * NK_ + i] ? 1.f : 0.f;
        else if (mode == 1) m = ((const int*)mptr)[b * NK_ + i] ? 1.f : 0.f;
        else                m = (((const float*)mptr)[b * NK_ + i] != 0.f) ? 1.f : 0.f;
        vals[x] = m;
        if (m == 0.f) anyUnmasked = 1;   // benign race, all writers write 1
    }
    __syncthreads();
    #pragma unroll
    for (int x = 0; x < NK_ / 256; x++) {
        int i = tid + x * 256;
        float m = vals[x];
        if (i == 0 && !anyUnmasked) m = 0.f;  // safe mask
        g_maskf[b * NK_ + i] = m;
    }
}

// ---------------------------------------------------------------------------
// fp32 GEMM + bias:  Y[M,1024] = X[M,1024] @ W[1024,1024] + bias[1024]
// 128x128 block tile, BK=8, 256 threads, 8x8 per thread (2x2 of 4x4 frags).
// ---------------------------------------------------------------------------
__global__ __launch_bounds__(256) void gemm_bias_kernel(
    const float* __restrict__ X, const float* __restrict__ W,
    const float* __restrict__ bias, float* __restrict__ Y)
{
    const int N = 1024, K = 1024;
    __shared__ float As[8][128];   // A transposed: As[k][m]
    __shared__ float Bs[8][128];

    int tid = threadIdx.x;
    int tx = tid % 16, ty = tid / 16;
    int m0 = blockIdx.y * 128, n0 = blockIdx.x * 128;

    int rowA = tid >> 1;            // 0..127
    int colA = (tid & 1) * 4;       // 0 or 4
    int rowB = tid >> 5;            // 0..7
    int colB = (tid & 31) * 4;      // 0..124

    float acc[8][8];
    #pragma unroll
    for (int i = 0; i < 8; i++)
        #pragma unroll
        for (int j = 0; j < 8; j++) acc[i][j] = 0.f;

    for (int k0 = 0; k0 < K; k0 += 8) {
        float4 a4 = *(const float4*)&X[(size_t)(m0 + rowA) * K + k0 + colA];
        As[colA + 0][rowA] = a4.x;
        As[colA + 1][rowA] = a4.y;
        As[colA + 2][rowA] = a4.z;
        As[colA + 3][rowA] = a4.w;
        *(float4*)&Bs[rowB][colB] =
            *(const float4*)&W[(size_t)(k0 + rowB) * N + n0 + colB];
        __syncthreads();

        #pragma unroll
        for (int kk = 0; kk < 8; kk++) {
            float a[8], b[8];
            *(float4*)&a[0] = *(float4*)&As[kk][ty * 4];
            *(float4*)&a[4] = *(float4*)&As[kk][64 + ty * 4];
            *(float4*)&b[0] = *(float4*)&Bs[kk][tx * 4];
            *(float4*)&b[4] = *(float4*)&Bs[kk][64 + tx * 4];
            #pragma unroll
            for (int i = 0; i < 8; i++)
                #pragma unroll
                for (int j = 0; j < 8; j++)
                    acc[i][j] += a[i] * b[j];
        }
        __syncthreads();
    }

    #pragma unroll
    for (int ib = 0; ib < 2; ib++)
        #pragma unroll
        for (int ii = 0; ii < 4; ii++) {
            int m = m0 + ib * 64 + ty * 4 + ii;
            #pragma unroll
            for (int jb = 0; jb < 2; jb++) {
                int n = n0 + jb * 64 + tx * 4;
                float4 o;
                o.x = acc[ib * 4 + ii][jb * 4 + 0] + bias[n + 0];
                o.y = acc[ib * 4 + ii][jb * 4 + 1] + bias[n + 1];
                o.z = acc[ib * 4 + ii][jb * 4 + 2] + bias[n + 2];
                o.w = acc[ib * 4 + ii][jb * 4 + 3] + bias[n + 3];
                *(float4*)&Y[(size_t)m * N + n] = o;
            }
        }
}

// ---------------------------------------------------------------------------
// Flash-attention style: one block = 64 query rows of one (b,h).
// 256 threads; each thread owns a 4x4 score frag (rows 4r.., cols 4c..) and a
// 4x4 output frag (rows 4r.., hd-cols 4c..). Online softmax over NK tiles of 64.
// SMEM: Qs (natural) | KP (K transposed d-major, reused for P) | Vs (natural).
// ---------------------------------------------------------------------------
__global__ __launch_bounds__(256) void attn_kernel(
    const float* __restrict__ bias,   // [B,H,NQ,NK]
    float* __restrict__ ctx)          // [B,NQ,D]
{
    __shared__ float sQ[64 * 64];
    __shared__ float sKP[64 * 64];
    __shared__ float sV[64 * 64];

    int tid = threadIdx.x;
    int c = tid & 15, r = tid >> 4;
    int b = blockIdx.z, h = blockIdx.y, q0 = blockIdx.x * 64;

    const float* Qg = g_Q + ((size_t)b * NQ_) * D_ + h * HD_;
    const float* Kg = g_K + ((size_t)b * NK_) * D_ + h * HD_;
    const float* Vg = g_V + ((size_t)b * NK_) * D_ + h * HD_;
    const float* biasg = bias + (((size_t)b * H_ + h) * NQ_ + q0) * NK_;
    const float* mg = g_maskf + b * NK_;

    // Load Q tile (64 x 64)
    for (int x = tid; x < 64 * 16; x += 256) {
        int row = x >> 4, col = (x & 15) * 4;
        *(float4*)&sQ[row * 64 + col] =
            *(const float4*)&Qg[(size_t)(q0 + row) * D_ + col];
    }

    float m_i[4], l_i[4], acc[4][4];
    #pragma unroll
    for (int i = 0; i < 4; i++) {
        m_i[i] = -INFINITY; l_i[i] = 0.f;
        #pragma unroll
        for (int j = 0; j < 4; j++) acc[i][j] = 0.f;
    }

    for (int k0 = 0; k0 < NK_; k0 += 64) {
        __syncthreads();   // prev iteration done with sKP/sV
        // Load K (transposed -> sKP[d][j]) and V (natural)
        for (int x = tid; x < 64 * 16; x += 256) {
            int row = x >> 4, col = (x & 15) * 4;
            float4 kv = *(const float4*)&Kg[(size_t)(k0 + row) * D_ + col];
            sKP[(col + 0) * 64 + row] = kv.x;
            sKP[(col + 1) * 64 + row] = kv.y;
            sKP[(col + 2) * 64 + row] = kv.z;
            sKP[(col + 3) * 64 + row] = kv.w;
            *(float4*)&sV[row * 64 + col] =
                *(const float4*)&Vg[(size_t)(k0 + row) * D_ + col];
        }
        __syncthreads();

        // S = Q K^T (4x4 frag per thread)
        float dq[4][4];
        #pragma unroll
        for (int i = 0; i < 4; i++)
            #pragma unroll
            for (int j = 0; j < 4; j++) dq[i][j] = 0.f;

        #pragma unroll 16
        for (int kk = 0; kk < 64; kk++) {
            float a0 = sQ[(4 * r + 0) * 64 + kk];
            float a1 = sQ[(4 * r + 1) * 64 + kk];
            float a2 = sQ[(4 * r + 2) * 64 + kk];
            float a3 = sQ[(4 * r + 3) * 64 + kk];
            float4 bv = *(const float4*)&sKP[kk * 64 + 4 * c];
            dq[0][0] += a0 * bv.x; dq[0][1] += a0 * bv.y; dq[0][2] += a0 * bv.z; dq[0][3] += a0 * bv.w;
            dq[1][0] += a1 * bv.x; dq[1][1] += a1 * bv.y; dq[1][2] += a1 * bv.z; dq[1][3] += a1 * bv.w;
            dq[2][0] += a2 * bv.x; dq[2][1] += a2 * bv.y; dq[2][2] += a2 * bv.z; dq[2][3] += a2 * bv.w;
            dq[3][0] += a3 * bv.x; dq[3][1] += a3 * bv.y; dq[3][2] += a3 * bv.z; dq[3][3] += a3 * bv.w;
        }
        __syncthreads();   // all reads of sKP(K) done before P overwrites it

        // mask + bias + scale
        float mkv[4];
        *(float4*)&mkv[0] = *(const float4*)&mg[k0 + 4 * c];
        float s[4][4], rmax[4];
        #pragma unroll
        for (int i = 0; i < 4; i++) {
            float4 bb = *(const float4*)&biasg[(size_t)(4 * r + i) * NK_ + k0 + 4 * c];
            s[i][0] = (mkv[0] != 0.f) ? -INFINITY : dq[i][0] * SCALE_ + bb.x;
            s[i][1] = (mkv[1] != 0.f) ? -INFINITY : dq[i][1] * SCALE_ + bb.y;
            s[i][2] = (mkv[2] != 0.f) ? -INFINITY : dq[i][2] * SCALE_ + bb.z;
            s[i][3] = (mkv[3] != 0.f) ? -INFINITY : dq[i][3] * SCALE_ + bb.w;
            rmax[i] = fmaxf(fmaxf(s[i][0], s[i][1]), fmaxf(s[i][2], s[i][3]));
        }
        // row max across the 16 lanes of this row group
        #pragma unroll
        for (int off = 8; off; off >>= 1)
            #pragma unroll
            for (int i = 0; i < 4; i++)
                rmax[i] = fmaxf(rmax[i], __shfl_xor_sync(0xffffffffu, rmax[i], off, 16));

        float alpha[4], rsum[4];
        #pragma unroll
        for (int i = 0; i < 4; i++) {
            float mnew = fmaxf(m_i[i], rmax[i]);
            float p0, p1, p2, p3;
            if (mnew == -INFINITY) {       // fully-masked so far: contribute nothing
                alpha[i] = 1.f;
                p0 = p1 = p2 = p3 = 0.f;
            } else {
                alpha[i] = __expf(m_i[i] - mnew);   // exp(-inf)=0 on first tile
                p0 = __expf(s[i][0] - mnew);
                p1 = __expf(s[i][1] - mnew);
                p2 = __expf(s[i][2] - mnew);
                p3 = __expf(s[i][3] - mnew);
            }
            m_i[i] = mnew;
            rsum[i] = p0 + p1 + p2 + p3;
            float4 pv = make_float4(p0, p1, p2, p3);
            *(float4*)&sKP[(4 * r + i) * 64 + 4 * c] = pv;   // P into reused buffer
        }
        #pragma unroll
        for (int off = 8; off; off >>= 1)
            #pragma unroll
            for (int i = 0; i < 4; i++)
                rsum[i] += __shfl_xor_sync(0xffffffffu, rsum[i], off, 16);
        #pragma unroll
        for (int i = 0; i < 4; i++)
            l_i[i] = l_i[i] * alpha[i] + rsum[i];

        __syncthreads();   // P visible to all

        // O = alpha*O + P @ V
        #pragma unroll
        for (int i = 0; i < 4; i++)
            #pragma unroll
            for (int j = 0; j < 4; j++) acc[i][j] *= alpha[i];

        #pragma unroll 16
        for (int kk = 0; kk < 64; kk++) {
            float p0 = sKP[(4 * r + 0) * 64 + kk];
            float p1 = sKP[(4 * r + 1) * 64 + kk];
            float p2 = sKP[(4 * r + 2) * 64 + kk];
            float p3 = sKP[(4 * r + 3) * 64 + kk];
            float4 vv = *(const float4*)&sV[kk * 64 + 4 * c];
            acc[0][0] += p0 * vv.x; acc[0][1] += p0 * vv.y; acc[0][2] += p0 * vv.z; acc[0][3] += p0 * vv.w;
            acc[1][0] += p1 * vv.x; acc[1][1] += p1 * vv.y; acc[1][2] += p1 * vv.z; acc[1][3] += p1 * vv.w;
            acc[2][0] += p2 * vv.x; acc[2][1] += p2 * vv.y; acc[2][2] += p2 * vv.z; acc[2][3] += p2 * vv.w;
            acc[3][0] += p3 * vv.x; acc[3][1] += p3 * vv.y; acc[3][2] += p3 * vv.z; acc[3][3] += p3 * vv.w;
        }
    }

    // Normalize and store to ctx [B,NQ,D] (head-interleaved layout == reference transpose)
    #pragma unroll
    for (int i = 0; i < 4; i++) {
        float inv = 1.f / l_i[i];
        float4 o = make_float4(acc[i][0] * inv, acc[i][1] * inv,
                               acc[i][2] * inv, acc[i][3] * inv);
        *(float4*)&ctx[((size_t)(b * NQ_ + q0 + 4 * r + i)) * D_ + h * HD_ + 4 * c] = o;
    }
}

// ---------------------------------------------------------------------------
extern "C" void kernel_launch(void* const* d_in, const int* in_sizes, int n_in,
                              void* d_out, int out_size)
{
    const float* q  = (const float*)d_in[0];
    const float* k  = (const float*)d_in[1];
    const float* v  = (const float*)d_in[2];
    const float* ab = (const float*)d_in[3];
    const void*  mk = d_in[4];
    const float* Wq = (const float*)d_in[5];
    const float* bq = (const float*)d_in[6];
    const float* Wk = (const float*)d_in[7];
    const float* bk = (const float*)d_in[8];
    const float* Wv = (const float*)d_in[9];
    const float* bv = (const float*)d_in[10];
    const float* Wo = (const float*)d_in[11];
    const float* bo = (const float*)d_in[12];
    float* out = (float*)d_out;

    float *gq, *gk, *gv, *gctx;
    cudaGetSymbolAddress((void**)&gq,   g_Q);
    cudaGetSymbolAddress((void**)&gk,   g_K);
    cudaGetSymbolAddress((void**)&gv,   g_V);
    cudaGetSymbolAddress((void**)&gctx, g_ctx);

    detect_mask_kernel<<<1, 256>>>((const unsigned char*)mk);
    prep_mask_kernel<<<B_, 256>>>(mk);

    // Projections: [B*N, 1024] @ [1024,1024] + bias
    gemm_bias_kernel<<<dim3(8, (B_ * NQ_) / 128), 256>>>(q, Wq, bq, gq);
    gemm_bias_kernel<<<dim3(8, (B_ * NK_) / 128), 256>>>(k, Wk, bk, gk);
    gemm_bias_kernel<<<dim3(8, (B_ * NK_) / 128), 256>>>(v, Wv, bv, gv);

    // Attention
    attn_kernel<<<dim3(NQ_ / 64, H_, B_), 256>>>(ab, gctx);

    // Output projection
    gemm_bias_kernel<<<dim3(8, (B_ * NQ_) / 128), 256>>>(gctx, Wo, bo, out);
}

// round 2
// speedup vs baseline: 1.6193x; 1.6193x over previous
#include <cuda_runtime.h>
#include <math.h>
#include <stdint.h>

// Problem constants
#define B_     2
#define NQ_    1024
#define NK_    2048
#define D_     1024
#define H_     16
#define HD_    64
#define SCALE_ 0.125f   // 64^-0.5

// Scratch (static device globals: allocation-free per harness rules)
__device__ float g_Q[(size_t)B_ * NQ_ * D_];     // 8 MB
__device__ float g_K[(size_t)B_ * NK_ * D_];     // 16 MB
__device__ float g_V[(size_t)B_ * NK_ * D_];     // 16 MB
__device__ float g_ctx[(size_t)B_ * NQ_ * D_];   // 8 MB
__device__ float g_maskf[B_ * NK_];
__device__ int   g_mask_mode;                    // 0=u8, 1=i32, 2=f32

// ---------------------------------------------------------------------------
// tf32 helpers + mma wrapper (m16n8k8, row.col, f32 accum)
// ---------------------------------------------------------------------------
__device__ __forceinline__ uint32_t f2tf(float x) {
    uint32_t u; asm("cvt.rna.tf32.f32 %0, %1;" : "=r"(u) : "f"(x)); return u;
}
__device__ __forceinline__ float f2tff(float x) { return __uint_as_float(f2tf(x)); }

__device__ __forceinline__ void mma_tf32(float* d, const uint32_t* a, const uint32_t* b) {
    asm volatile(
        "mma.sync.aligned.m16n8k8.row.col.f32.tf32.tf32.f32 "
        "{%0,%1,%2,%3}, {%4,%5,%6,%7}, {%8,%9}, {%0,%1,%2,%3};"
        : "+f"(d[0]), "+f"(d[1]), "+f"(d[2]), "+f"(d[3])
        : "r"(a[0]), "r"(a[1]), "r"(a[2]), "r"(a[3]),
          "r"(b[0]), "r"(b[1]));
}

// ---------------------------------------------------------------------------
// Mask dtype detection (unchanged)
// ---------------------------------------------------------------------------
__global__ void detect_mask_kernel(const unsigned char* __restrict__ p) {
    __shared__ int s_nonbin, s_unal;
    int tid = threadIdx.x;
    if (tid == 0) { s_nonbin = 0; s_unal = 0; }
    __syncthreads();
    for (int i = tid; i < B_ * NK_; i += 256) {
        unsigned char v = p[i];
        if (v > 1) s_nonbin = 1;
        else if (v == 1 && (i & 3)) s_unal = 1;
    }
    __syncthreads();
    if (tid == 0) g_mask_mode = s_nonbin ? 2 : (s_unal ? 0 : 1);
}

__global__ void prep_mask_kernel(const void* __restrict__ mptr) {
    int b = blockIdx.x;
    int tid = threadIdx.x;          // 256 threads
    __shared__ int anyUnmasked;
    if (tid == 0) anyUnmasked = 0;
    __syncthreads();
    int mode = g_mask_mode;
    float vals[NK_ / 256];
    #pragma unroll
    for (int x = 0; x < NK_ / 256; x++) {
        int i = tid + x * 256;
        float m;
        if (mode == 0)      m = ((const unsigned char*)mptr)[b * NK_ + i] ? 1.f : 0.f;
        else if (mode == 1) m = ((const int*)mptr)[b * NK_ + i] ? 1.f : 0.f;
        else                m = (((const float*)mptr)[b * NK_ + i] != 0.f) ? 1.f : 0.f;
        vals[x] = m;
        if (m == 0.f) anyUnmasked = 1;
    }
    __syncthreads();
    #pragma unroll
    for (int x = 0; x < NK_ / 256; x++) {
        int i = tid + x * 256;
        float m = vals[x];
        if (i == 0 && !anyUnmasked) m = 0.f;  // safe mask
        g_maskf[b * NK_ + i] = m;
    }
}

// ---------------------------------------------------------------------------
// tf32 tensor-core GEMM + bias:  Y[M,1024] = X[M,1024] @ W[1024,1024] + bias
// CTA tile 128x128, BK=32, 8 warps (2x4), warp tile 64x32 (4x4 m16n8k8 frags).
// SMEM: As[k][m] stride 132 (transposed at store), Bs[k][n] stride 132.
// ---------------------------------------------------------------------------
__global__ __launch_bounds__(256) void gemm_tf32_kernel(
    const float* __restrict__ X, const float* __restrict__ W,
    const float* __restrict__ bias, float* __restrict__ Y)
{
    const int K = 1024, N = 1024;
    __shared__ float As[32][132];
    __shared__ float Bs[32][132];

    int tid  = threadIdx.x;
    int lane = tid & 31, warp = tid >> 5;
    int g = lane >> 2, t = lane & 3;
    int wm = (warp >> 2) * 64;        // warp M origin within tile (0 or 64)
    int wn = (warp & 3) * 32;         // warp N origin (0,32,64,96)
    int m0 = blockIdx.y * 128, n0 = blockIdx.x * 128;

    float acc[4][4][4];
    #pragma unroll
    for (int i = 0; i < 4; i++)
        #pragma unroll
        for (int j = 0; j < 4; j++)
            #pragma unroll
            for (int c = 0; c < 4; c++) acc[i][j][c] = 0.f;

    for (int k0 = 0; k0 < K; k0 += 32) {
        // Load A 128x32 (transpose into As[k][m], tf32-converted)
        #pragma unroll
        for (int i = 0; i < 4; i++) {
            int idx = tid + i * 256;               // 0..1023
            int m = idx >> 3, kq = (idx & 7) * 4;
            float4 v = *(const float4*)&X[(size_t)(m0 + m) * K + k0 + kq];
            As[kq + 0][m] = f2tff(v.x);
            As[kq + 1][m] = f2tff(v.y);
            As[kq + 2][m] = f2tff(v.z);
            As[kq + 3][m] = f2tff(v.w);
        }
        // Load B 32x128 (natural, tf32-converted)
        #pragma unroll
        for (int i = 0; i < 4; i++) {
            int idx = tid + i * 256;
            int kk = idx >> 5, nq = (idx & 31) * 4;
            float4 v = *(const float4*)&W[(size_t)(k0 + kk) * N + n0 + nq];
            v.x = f2tff(v.x); v.y = f2tff(v.y); v.z = f2tff(v.z); v.w = f2tff(v.w);
            *(float4*)&Bs[kk][nq] = v;
        }
        __syncthreads();

        #pragma unroll
        for (int kt = 0; kt < 4; kt++) {
            uint32_t a[4][4], bfr[4][2];
            #pragma unroll
            for (int mt = 0; mt < 4; mt++) {
                int mm = wm + mt * 16 + g;
                a[mt][0] = __float_as_uint(As[kt * 8 + t][mm]);
                a[mt][1] = __float_as_uint(As[kt * 8 + t][mm + 8]);
                a[mt][2] = __float_as_uint(As[kt * 8 + t + 4][mm]);
                a[mt][3] = __float_as_uint(As[kt * 8 + t + 4][mm + 8]);
            }
            #pragma unroll
            for (int nt = 0; nt < 4; nt++) {
                int nn = wn + nt * 8 + g;
                bfr[nt][0] = __float_as_uint(Bs[kt * 8 + t][nn]);
                bfr[nt][1] = __float_as_uint(Bs[kt * 8 + t + 4][nn]);
            }
            #pragma unroll
            for (int mt = 0; mt < 4; mt++)
                #pragma unroll
                for (int nt = 0; nt < 4; nt++)
                    mma_tf32(acc[mt][nt], a[mt], bfr[nt]);
        }
        __syncthreads();
    }

    // Epilogue: add bias, write float2 pairs
    #pragma unroll
    for (int mt = 0; mt < 4; mt++) {
        int row = m0 + wm + mt * 16 + g;
        #pragma unroll
        for (int nt = 0; nt < 4; nt++) {
            int col = n0 + wn + nt * 8 + 2 * t;
            float2 bb = *(const float2*)&bias[col];
            float2 o0, o1;
            o0.x = acc[mt][nt][0] + bb.x;
            o0.y = acc[mt][nt][1] + bb.y;
            o1.x = acc[mt][nt][2] + bb.x;
            o1.y = acc[mt][nt][3] + bb.y;
            *(float2*)&Y[(size_t)row * N + col]       = o0;
            *(float2*)&Y[(size_t)(row + 8) * N + col] = o1;
        }
    }
}

// ---------------------------------------------------------------------------
// tf32 tensor-core flash attention. One CTA = 128 q rows of one (b,h).
// 8 warps, warp owns rows [w*16, w*16+16). Online softmax per row inside a quad.
// SMEM (dynamic): sK[d][key] (64x65, transposed K), sV[key][d] (64x68),
//                 sP[q][*] (128x68, Q staging then P tiles).
// ---------------------------------------------------------------------------
#define STK 65
#define STV 68
#define STP 68
#define ATTN_SMEM ((64 * STK + 64 * STV + 128 * STP) * 4)

__global__ __launch_bounds__(256) void attn_tf32_kernel(
    const float* __restrict__ bias,   // [B,H,NQ,NK]
    float* __restrict__ ctx)          // [B,NQ,D]
{
    extern __shared__ float smem[];
    float* sK = smem;                  // [64][STK]
    float* sV = smem + 64 * STK;       // [64][STV]
    float* sP = sV + 64 * STV;         // [128][STP]

    int tid = threadIdx.x, lane = tid & 31, warp = tid >> 5;
    int g = lane >> 2, t = lane & 3;
    int b = blockIdx.z, h = blockIdx.y, q0 = blockIdx.x * 128;
    int wq = warp * 16;

    const float* Qg = g_Q + (size_t)(b * NQ_ + q0) * D_ + h * HD_;
    const float* Kg = g_K + (size_t)b * NK_ * D_ + h * HD_;
    const float* Vg = g_V + (size_t)b * NK_ * D_ + h * HD_;
    const float* biasg = bias + (((size_t)b * H_ + h) * NQ_ + q0) * NK_;
    const float* mg = g_maskf + b * NK_;

    // Stage Q (128x64) into sP, tf32-converted
    for (int i = tid; i < 128 * 16; i += 256) {
        int row = i >> 4, dq = (i & 15) * 4;
        float4 v = *(const float4*)&Qg[(size_t)row * D_ + dq];
        float* p = &sP[row * STP + dq];
        p[0] = f2tff(v.x); p[1] = f2tff(v.y); p[2] = f2tff(v.z); p[3] = f2tff(v.w);
    }
    __syncthreads();

    // Q fragments register-resident: 8 ktiles x 4 regs
    uint32_t qf[8][4];
    #pragma unroll
    for (int kt = 0; kt < 8; kt++) {
        qf[kt][0] = __float_as_uint(sP[(wq + g) * STP + kt * 8 + t]);
        qf[kt][1] = __float_as_uint(sP[(wq + g + 8) * STP + kt * 8 + t]);
        qf[kt][2] = __float_as_uint(sP[(wq + g) * STP + kt * 8 + t + 4]);
        qf[kt][3] = __float_as_uint(sP[(wq + g + 8) * STP + kt * 8 + t + 4]);
    }

    float oacc[8][4];
    #pragma unroll
    for (int nt = 0; nt < 8; nt++)
        #pragma unroll
        for (int c = 0; c < 4; c++) oacc[nt][c] = 0.f;
    float mr0 = -INFINITY, mr1 = -INFINITY, l0 = 0.f, l1 = 0.f;

    for (int k0 = 0; k0 < NK_; k0 += 64) {
        __syncthreads();   // prior iter's sK/sV reads complete
        // Load K transposed (sK[d][key]) and V natural (sV[key][d]), tf32
        for (int i = tid; i < 64 * 16; i += 256) {
            int key = i >> 4, dq = (i & 15) * 4;
            float4 kv = *(const float4*)&Kg[(size_t)(k0 + key) * D_ + dq];
            sK[(dq + 0) * STK + key] = f2tff(kv.x);
            sK[(dq + 1) * STK + key] = f2tff(kv.y);
            sK[(dq + 2) * STK + key] = f2tff(kv.z);
            sK[(dq + 3) * STK + key] = f2tff(kv.w);
            float4 vv = *(const float4*)&Vg[(size_t)(k0 + key) * D_ + dq];
            vv.x = f2tff(vv.x); vv.y = f2tff(vv.y); vv.z = f2tff(vv.z); vv.w = f2tff(vv.w);
            *(float4*)&sV[key * STV + dq] = vv;
        }
        __syncthreads();

        // S = Q @ K^T : sacc[nt] is 16x8 tile (rows g/g+8, cols nt*8+2t(+1))
        float sacc[8][4];
        #pragma unroll
        for (int nt = 0; nt < 8; nt++)
            #pragma unroll
            for (int c = 0; c < 4; c++) sacc[nt][c] = 0.f;

        #pragma unroll
        for (int kt = 0; kt < 8; kt++) {
            #pragma unroll
            for (int nt = 0; nt < 8; nt++) {
                uint32_t bfr[2];
                bfr[0] = __float_as_uint(sK[(kt * 8 + t) * STK + nt * 8 + g]);
                bfr[1] = __float_as_uint(sK[(kt * 8 + t + 4) * STK + nt * 8 + g]);
                mma_tf32(sacc[nt], qf[kt], bfr);
            }
        }

        // scale + bias + mask (in place), row maxima
        float rmax0 = -INFINITY, rmax1 = -INFINITY;
        #pragma unroll
        for (int nt = 0; nt < 8; nt++) {
            int kc = k0 + nt * 8 + 2 * t;
            float2 mk  = *(const float2*)&mg[kc];
            float2 b0v = *(const float2*)&biasg[(size_t)(wq + g) * NK_ + kc];
            float2 b1v = *(const float2*)&biasg[(size_t)(wq + g + 8) * NK_ + kc];
            sacc[nt][0] = (mk.x != 0.f) ? -INFINITY : sacc[nt][0] * SCALE_ + b0v.x;
            sacc[nt][1] = (mk.y != 0.f) ? -INFINITY : sacc[nt][1] * SCALE_ + b0v.y;
            sacc[nt][2] = (mk.x != 0.f) ? -INFINITY : sacc[nt][2] * SCALE_ + b1v.x;
            sacc[nt][3] = (mk.y != 0.f) ? -INFINITY : sacc[nt][3] * SCALE_ + b1v.y;
            rmax0 = fmaxf(rmax0, fmaxf(sacc[nt][0], sacc[nt][1]));
            rmax1 = fmaxf(rmax1, fmaxf(sacc[nt][2], sacc[nt][3]));
        }
        rmax0 = fmaxf(rmax0, __shfl_xor_sync(0xffffffffu, rmax0, 1));
        rmax0 = fmaxf(rmax0, __shfl_xor_sync(0xffffffffu, rmax0, 2));
        rmax1 = fmaxf(rmax1, __shfl_xor_sync(0xffffffffu, rmax1, 1));
        rmax1 = fmaxf(rmax1, __shfl_xor_sync(0xffffffffu, rmax1, 2));

        float mn0 = fmaxf(mr0, rmax0), mn1 = fmaxf(mr1, rmax1);
        bool dead0 = (mn0 == -INFINITY), dead1 = (mn1 == -INFINITY);
        float al0 = dead0 ? 1.f : __expf(mr0 - mn0);
        float al1 = dead1 ? 1.f : __expf(mr1 - mn1);
        float sum0 = 0.f, sum1 = 0.f;

        #pragma unroll
        for (int nt = 0; nt < 8; nt++) {
            float p00 = dead0 ? 0.f : __expf(sacc[nt][0] - mn0);
            float p01 = dead0 ? 0.f : __expf(sacc[nt][1] - mn0);
            float p10 = dead1 ? 0.f : __expf(sacc[nt][2] - mn1);
            float p11 = dead1 ? 0.f : __expf(sacc[nt][3] - mn1);
            sum0 += p00 + p01;
            sum1 += p10 + p11;
            float* pr0 = &sP[(wq + g) * STP + nt * 8 + 2 * t];
            float* pr1 = &sP[(wq + g + 8) * STP + nt * 8 + 2 * t];
            pr0[0] = f2tff(p00); pr0[1] = f2tff(p01);
            pr1[0] = f2tff(p10); pr1[1] = f2tff(p11);
        }
        sum0 += __shfl_xor_sync(0xffffffffu, sum0, 1);
        sum0 += __shfl_xor_sync(0xffffffffu, sum0, 2);
        sum1 += __shfl_xor_sync(0xffffffffu, sum1, 1);
        sum1 += __shfl_xor_sync(0xffffffffu, sum1, 2);

        mr0 = mn0; mr1 = mn1;
        l0 = l0 * al0 + sum0;
        l1 = l1 * al1 + sum1;
        #pragma unroll
        for (int nt = 0; nt < 8; nt++) {
            oacc[nt][0] *= al0; oacc[nt][1] *= al0;
            oacc[nt][2] *= al1; oacc[nt][3] *= al1;
        }
        __syncwarp();   // P stores visible within warp

        // O += P @ V
        #pragma unroll
        for (int kt = 0; kt < 8; kt++) {
            uint32_t pa[4];
            pa[0] = __float_as_uint(sP[(wq + g) * STP + kt * 8 + t]);
            pa[1] = __float_as_uint(sP[(wq + g + 8) * STP + kt * 8 + t]);
            pa[2] = __float_as_uint(sP[(wq + g) * STP + kt * 8 + t + 4]);
            pa[3] = __float_as_uint(sP[(wq + g + 8) * STP + kt * 8 + t + 4]);
            #pragma unroll
            for (int nt = 0; nt < 8; nt++) {
                uint32_t vb[2];
                vb[0] = __float_as_uint(sV[(kt * 8 + t) * STV + nt * 8 + g]);
                vb[1] = __float_as_uint(sV[(kt * 8 + t + 4) * STV + nt * 8 + g]);
                mma_tf32(oacc[nt], pa, vb);
            }
        }
    }

    // Normalize and store: ctx[b, q0+row, h*HD + d]
    float inv0 = 1.f / l0, inv1 = 1.f / l1;
    size_t row0 = (size_t)(b * NQ_ + q0 + wq + g) * D_ + h * HD_;
    size_t row1 = row0 + 8 * D_;
    #pragma unroll
    for (int nt = 0; nt < 8; nt++) {
        int col = nt * 8 + 2 * t;
        float2 o0 = make_float2(oacc[nt][0] * inv0, oacc[nt][1] * inv0);
        float2 o1 = make_float2(oacc[nt][2] * inv1, oacc[nt][3] * inv1);
        *(float2*)&ctx[row0 + col] = o0;
        *(float2*)&ctx[row1 + col] = o1;
    }
}

// ---------------------------------------------------------------------------
extern "C" void kernel_launch(void* const* d_in, const int* in_sizes, int n_in,
                              void* d_out, int out_size)
{
    const float* q  = (const float*)d_in[0];
    const float* k  = (const float*)d_in[1];
    const float* v  = (const float*)d_in[2];
    const float* ab = (const float*)d_in[3];
    const void*  mk = d_in[4];
    const float* Wq = (const float*)d_in[5];
    const float* bq = (const float*)d_in[6];
    const float* Wk = (const float*)d_in[7];
    const float* bk = (const float*)d_in[8];
    const float* Wv = (const float*)d_in[9];
    const float* bv = (const float*)d_in[10];
    const float* Wo = (const float*)d_in[11];
    const float* bo = (const float*)d_in[12];
    float* out = (float*)d_out;

    float *gq, *gk, *gv, *gctx;
    cudaGetSymbolAddress((void**)&gq,   g_Q);
    cudaGetSymbolAddress((void**)&gk,   g_K);
    cudaGetSymbolAddress((void**)&gv,   g_V);
    cudaGetSymbolAddress((void**)&gctx, g_ctx);

    static int smem_set = 0;
    if (!smem_set) {
        cudaFuncSetAttribute(attn_tf32_kernel,
                             cudaFuncAttributeMaxDynamicSharedMemorySize, ATTN_SMEM);
        smem_set = 1;
    }

    detect_mask_kernel<<<1, 256>>>((const unsigned char*)mk);
    prep_mask_kernel<<<B_, 256>>>(mk);

    // Projections: [B*N, 1024] @ [1024,1024] + bias
    gemm_tf32_kernel<<<dim3(8, (B_ * NQ_) / 128), 256>>>(q, Wq, bq, gq);
    gemm_tf32_kernel<<<dim3(8, (B_ * NK_) / 128), 256>>>(k, Wk, bk, gk);
    gemm_tf32_kernel<<<dim3(8, (B_ * NK_) / 128), 256>>>(v, Wv, bv, gv);

    // Attention
    attn_tf32_kernel<<<dim3(NQ_ / 128, H_, B_), 256, ATTN_SMEM>>>(ab, gctx);

    // Output projection
    gemm_tf32_kernel<<<dim3(8, (B_ * NQ_) / 128), 256>>>(gctx, Wo, bo, out);
}

// round 3
// speedup vs baseline: 2.2592x; 1.3952x over previous
#include <cuda_runtime.h>
#include <math.h>
#include <stdint.h>

#define B_     2
#define NQ_    1024
#define NK_    2048
#define D_     1024
#define H_     16
#define HD_    64
#define SCALE_ 0.125f

__device__ float g_Q[(size_t)B_ * NQ_ * D_];
__device__ float g_K[(size_t)B_ * NK_ * D_];
__device__ float g_V[(size_t)B_ * NK_ * D_];
__device__ float g_ctx[(size_t)B_ * NQ_ * D_];
__device__ float g_maskf[B_ * NK_];
__device__ int   g_mask_mode;

__device__ __forceinline__ uint32_t f2tf(float x) {
    uint32_t u; asm("cvt.rna.tf32.f32 %0, %1;" : "=r"(u) : "f"(x)); return u;
}
__device__ __forceinline__ float f2tff(float x) { return __uint_as_float(f2tf(x)); }

__device__ __forceinline__ void mma_tf32(float* d, const uint32_t* a, const uint32_t* b) {
    asm volatile(
        "mma.sync.aligned.m16n8k8.row.col.f32.tf32.tf32.f32 "
        "{%0,%1,%2,%3}, {%4,%5,%6,%7}, {%8,%9}, {%0,%1,%2,%3};"
        : "+f"(d[0]), "+f"(d[1]), "+f"(d[2]), "+f"(d[3])
        : "r"(a[0]), "r"(a[1]), "r"(a[2]), "r"(a[3]),
          "r"(b[0]), "r"(b[1]));
}

__device__ __forceinline__ void cp16(uint32_t dst, const void* src) {
    asm volatile("cp.async.cg.shared.global [%0], [%1], 16;" :: "r"(dst), "l"(src));
}
__device__ __forceinline__ void cp_commit() { asm volatile("cp.async.commit_group;"); }
template <int N> __device__ __forceinline__ void cp_wait() {
    asm volatile("cp.async.wait_group %0;" :: "n"(N));
}

__global__ void detect_mask_kernel(const unsigned char* __restrict__ p) {
    __shared__ int s_nonbin, s_unal;
    int tid = threadIdx.x;
    if (tid == 0) { s_nonbin = 0; s_unal = 0; }
    __syncthreads();
    for (int i = tid; i < B_ * NK_; i += 256) {
        unsigned char v = p[i];
        if (v > 1) s_nonbin = 1;
        else if (v == 1 && (i & 3)) s_unal = 1;
    }
    __syncthreads();
    if (tid == 0) g_mask_mode = s_nonbin ? 2 : (s_unal ? 0 : 1);
}

__global__ void prep_mask_kernel(const void* __restrict__ mptr) {
    int b = blockIdx.x;
    int tid = threadIdx.x;
    __shared__ int anyUnmasked;
    if (tid == 0) anyUnmasked = 0;
    __syncthreads();
    int mode = g_mask_mode;
    float vals[NK_ / 256];
    #pragma unroll
    for (int x = 0; x < NK_ / 256; x++) {
        int i = tid + x * 256;
        float m;
        if (mode == 0)      m = ((const unsigned char*)mptr)[b * NK_ + i] ? 1.f : 0.f;
        else if (mode == 1) m = ((const int*)mptr)[b * NK_ + i] ? 1.f : 0.f;
        else                m = (((const float*)mptr)[b * NK_ + i] != 0.f) ? 1.f : 0.f;
        vals[x] = m;
        if (m == 0.f) anyUnmasked = 1;
    }
    __syncthreads();
    #pragma unroll
    for (int x = 0; x < NK_ / 256; x++) {
        int i = tid + x * 256;
        float m = vals[x];
        if (i == 0 && !anyUnmasked) m = 0.f;
        g_maskf[b * NK_ + i] = m;
    }
}

#define GA_S 36
#define GB_S 136
#define GEMM_SMEM ((2 * 128 * GA_S + 2 * 32 * GB_S) * 4)

__device__ __forceinline__ void gemm_body(
    const float* __restrict__ X, const float* __restrict__ W,
    const float* __restrict__ bias, float* __restrict__ Y,
    int m0, int n0, float* sA, float* sB)
{
    const int K = 1024, N = 1024;
    int tid  = threadIdx.x;
    int lane = tid & 31, warp = tid >> 5;
    int g = lane >> 2, t = lane & 3;
    int wm = (warp >> 2) * 64;
    int wn = (warp & 3) * 32;

    uint32_t sA_u = (uint32_t)__cvta_generic_to_shared(sA);
    uint32_t sB_u = (uint32_t)__cvta_generic_to_shared(sB);

    float acc[4][4][4];
    #pragma unroll
    for (int i = 0; i < 4; i++)
        #pragma unroll
        for (int j = 0; j < 4; j++)
            #pragma unroll
            for (int c = 0; c < 4; c++) acc[i][j][c] = 0.f;

    auto issue = [&](int buf, int k0) {
        #pragma unroll
        for (int i = 0; i < 4; i++) {
            int c = tid + i * 256;
            int row = c >> 3, col = (c & 7) * 4;
            cp16(sA_u + (uint32_t)(((buf * 128 + row) * GA_S + col) * 4),
                 X + (size_t)(m0 + row) * K + k0 + col);
        }
        #pragma unroll
        for (int i = 0; i < 4; i++) {
            int c = tid + i * 256;
            int row = c >> 5, col = (c & 31) * 4;
            cp16(sB_u + (uint32_t)(((buf * 32 + row) * GB_S + col) * 4),
                 W + (size_t)(k0 + row) * N + n0 + col);
        }
    };

    issue(0, 0);
    cp_commit();

    #pragma unroll 1
    for (int it = 0; it < 32; it++) {
        int buf = it & 1;
        if (it > 0) __syncthreads();
        if (it < 31) {
            issue(buf ^ 1, (it + 1) * 32);
            cp_commit();
            cp_wait<1>();
        } else {
            cp_wait<0>();
        }
        __syncthreads();

        const float* A0 = sA + (size_t)buf * 128 * GA_S;
        const float* B0 = sB + (size_t)buf * 32 * GB_S;

        #pragma unroll
        for (int kt = 0; kt < 4; kt++) {
            uint32_t a[4][4], bfr[4][2];
            #pragma unroll
            for (int mt = 0; mt < 4; mt++) {
                const float* ap = &A0[(size_t)(wm + mt * 16 + g) * GA_S + kt * 8 + t];
                a[mt][0] = f2tf(ap[0]);
                a[mt][1] = f2tf(ap[8 * GA_S]);
                a[mt][2] = f2tf(ap[4]);
                a[mt][3] = f2tf(ap[8 * GA_S + 4]);
            }
            #pragma unroll
            for (int nt = 0; nt < 4; nt++) {
                const float* bp = &B0[(size_t)(kt * 8 + t) * GB_S + wn + nt * 8 + g];
                bfr[nt][0] = f2tf(bp[0]);
                bfr[nt][1] = f2tf(bp[4 * GB_S]);
            }
            #pragma unroll
            for (int mt = 0; mt < 4; mt++)
                #pragma unroll
                for (int nt = 0; nt < 4; nt++)
                    mma_tf32(acc[mt][nt], a[mt], bfr[nt]);
        }
    }

    #pragma unroll
    for (int mt = 0; mt < 4; mt++) {
        int row = m0 + wm + mt * 16 + g;
        #pragma unroll
        for (int nt = 0; nt < 4; nt++) {
            int col = n0 + wn + nt * 8 + 2 * t;
            float2 bb = *(const float2*)&bias[col];
            float2 o0, o1;
            o0.x = acc[mt][nt][0] + bb.x;
            o0.y = acc[mt][nt][1] + bb.y;
            o1.x = acc[mt][nt][2] + bb.x;
            o1.y = acc[mt][nt][3] + bb.y;
            *(float2*)&Y[(size_t)row * N + col]       = o0;
            *(float2*)&Y[(size_t)(row + 8) * N + col] = o1;
        }
    }
}

__global__ __launch_bounds__(256) void qkv_proj_kernel(
    const float* __restrict__ q, const float* __restrict__ k, const float* __restrict__ v,
    const float* __restrict__ Wq, const float* __restrict__ bq,
    const float* __restrict__ Wk, const float* __restrict__ bk,
    const float* __restrict__ Wv, const float* __restrict__ bv)
{
    extern __shared__ float sm[];
    int y = blockIdx.y;
    const float *X, *W, *bias; float* Y; int m0;
    if (y < 16)      { X = q; W = Wq; bias = bq; Y = g_Q; m0 = y * 128; }
    else if (y < 48) { X = k; W = Wk; bias = bk; Y = g_K; m0 = (y - 16) * 128; }
    else             { X = v; W = Wv; bias = bv; Y = g_V; m0 = (y - 48) * 128; }
    gemm_body(X, W, bias, Y, m0, blockIdx.x * 128, sm, sm + 2 * 128 * GA_S);
}

__global__ __launch_bounds__(256) void oproj_kernel(
    const float* __restrict__ Wo, const float* __restrict__ bo, float* __restrict__ out)
{
    extern __shared__ float sm[];
    gemm_body(g_ctx, Wo, bo, out, blockIdx.y * 128, blockIdx.x * 128,
              sm, sm + 2 * 128 * GA_S);
}

#define STK 68
#define STV 72
#define STP 68
#define ATTN_SMEM ((2 * 64 * STK + 2 * 64 * STV + 128 * STP) * 4)

__global__ __launch_bounds__(256) void attn_tf32_kernel(
    const float* __restrict__ bias, float* __restrict__ ctx)
{
    extern __shared__ float smem[];
    float* sK = smem;
    float* sV = smem + 2 * 64 * STK;
    float* sP = smem + 2 * 64 * STK + 2 * 64 * STV;

    int tid = threadIdx.x, lane = tid & 31, warp = tid >> 5;
    int g = lane >> 2, t = lane & 3;
    int b = blockIdx.z, h = blockIdx.y, q0 = blockIdx.x * 128;
    int wq = warp * 16;

    const float* Qg = g_Q + (size_t)(b * NQ_ + q0) * D_ + h * HD_;
    const float* Kg = g_K + (size_t)b * NK_ * D_ + h * HD_;
    const float* Vg = g_V + (size_t)b * NK_ * D_ + h * HD_;
    const float* biasg = bias + (((size_t)b * H_ + h) * NQ_ + q0) * NK_;
    const float* mg = g_maskf + b * NK_;

    uint32_t sK_u = (uint32_t)__cvta_generic_to_shared(sK);
    uint32_t sV_u = (uint32_t)__cvta_generic_to_shared(sV);

    auto issueKV = [&](int buf, int k0) {
        #pragma unroll
        for (int i = 0; i < 4; i++) {
            int c = tid + i * 256;
            int row = c >> 4, col = (c & 15) * 4;
            cp16(sK_u + (uint32_t)(((buf * 64 + row) * STK + col) * 4),
                 Kg + (size_t)(k0 + row) * D_ + col);
            cp16(sV_u + (uint32_t)(((buf * 64 + row) * STV + col) * 4),
                 Vg + (size_t)(k0 + row) * D_ + col);
        }
    };

    issueKV(0, 0);
    cp_commit();

    for (int i = tid; i < 128 * 16; i += 256) {
        int row = i >> 4, dq = (i & 15) * 4;
        float4 v = *(const float4*)&Qg[(size_t)row * D_ + dq];
        float* p = &sP[row * STP + dq];
        p[0] = f2tff(v.x); p[1] = f2tff(v.y); p[2] = f2tff(v.z); p[3] = f2tff(v.w);
    }
    __syncthreads();

    uint32_t qf[8][4];
    #pragma unroll
    for (int kt = 0; kt < 8; kt++) {
        qf[kt][0] = __float_as_uint(sP[(wq + g) * STP + kt * 8 + t]);
        qf[kt][1] = __float_as_uint(sP[(wq + g + 8) * STP + kt * 8 + t]);
        qf[kt][2] = __float_as_uint(sP[(wq + g) * STP + kt * 8 + t + 4]);
        qf[kt][3] = __float_as_uint(sP[(wq + g + 8) * STP + kt * 8 + t + 4]);
    }

    float oacc[8][4];
    #pragma unroll
    for (int nt = 0; nt < 8; nt++)
        #pragma unroll
        for (int c = 0; c < 4; c++) oacc[nt][c] = 0.f;
    float mr0 = -INFINITY, mr1 = -INFINITY, l0 = 0.f, l1 = 0.f;

    #pragma unroll 1
    for (int it = 0; it < NK_ / 64; it++) {
        int buf = it & 1, k0 = it * 64;
        if (it > 0) __syncthreads();
        if (it < NK_ / 64 - 1) {
            issueKV(buf ^ 1, k0 + 64);
            cp_commit();
            cp_wait<1>();
        } else {
            cp_wait<0>();
        }
        __syncthreads();

        const float* K0 = sK + (size_t)buf * 64 * STK;
        const float* V0 = sV + (size_t)buf * 64 * STV;

        float sacc[8][4];
        #pragma unroll
        for (int nt = 0; nt < 8; nt++)
            #pragma unroll
            for (int c = 0; c < 4; c++) sacc[nt][c] = 0.f;

        #pragma unroll
        for (int kt = 0; kt < 8; kt++) {
            #pragma unroll
            for (int nt = 0; nt < 8; nt++) {
                const float* kp = &K0[(size_t)(nt * 8 + g) * STK + kt * 8 + t];
                uint32_t bfr[2];
                bfr[0] = f2tf(kp[0]);
                bfr[1] = f2tf(kp[4]);
                mma_tf32(sacc[nt], qf[kt], bfr);
            }
        }

        float rmax0 = -INFINITY, rmax1 = -INFINITY;
        #pragma unroll
        for (int nt = 0; nt < 8; nt++) {
            int kc = k0 + nt * 8 + 2 * t;
            float2 mk  = *(const float2*)&mg[kc];
            float2 b0v = *(const float2*)&biasg[(size_t)(wq + g) * NK_ + kc];
            float2 b1v = *(const float2*)&biasg[(size_t)(wq + g + 8) * NK_ + kc];
            sacc[nt][0] = (mk.x != 0.f) ? -INFINITY : sacc[nt][0] * SCALE_ + b0v.x;
            sacc[nt][1] = (mk.y != 0.f) ? -INFINITY : sacc[nt][1] * SCALE_ + b0v.y;
            sacc[nt][2] = (mk.x != 0.f) ? -INFINITY : sacc[nt][2] * SCALE_ + b1v.x;
            sacc[nt][3] = (mk.y != 0.f) ? -INFINITY : sacc[nt][3] * SCALE_ + b1v.y;
            rmax0 = fmaxf(rmax0, fmaxf(sacc[nt][0], sacc[nt][1]));
            rmax1 = fmaxf(rmax1, fmaxf(sacc[nt][2], sacc[nt][3]));
        }
        rmax0 = fmaxf(rmax0, __shfl_xor_sync(0xffffffffu, rmax0, 1));
        rmax0 = fmaxf(rmax0, __shfl_xor_sync(0xffffffffu, rmax0, 2));
        rmax1 = fmaxf(rmax1, __shfl_xor_sync(0xffffffffu, rmax1, 1));
        rmax1 = fmaxf(rmax1, __shfl_xor_sync(0xffffffffu, rmax1, 2));

        float mn0 = fmaxf(mr0, rmax0), mn1 = fmaxf(mr1, rmax1);
        bool dead0 = (mn0 == -INFINITY), dead1 = (mn1 == -INFINITY);
        float al0 = dead0 ? 1.f : __expf(mr0 - mn0);
        float al1 = dead1 ? 1.f : __expf(mr1 - mn1);
        float sum0 = 0.f, sum1 = 0.f;

        #pragma unroll
        for (int nt = 0; nt < 8; nt++) {
            float p00 = dead0 ? 0.f : __expf(sacc[nt][0] - mn0);
            float p01 = dead0 ? 0.f : __expf(sacc[nt][1] - mn0);
            float p10 = dead1 ? 0.f : __expf(sacc[nt][2] - mn1);
            float p11 = dead1 ? 0.f : __expf(sacc[nt][3] - mn1);
            sum0 += p00 + p01;
            sum1 += p10 + p11;
            float2 w0 = make_float2(f2tff(p00), f2tff(p01));
            float2 w1 = make_float2(f2tff(p10), f2tff(p11));
            *(float2*)&sP[(wq + g) * STP + nt * 8 + 2 * t]     = w0;
            *(float2*)&sP[(wq + g + 8) * STP + nt * 8 + 2 * t] = w1;
        }
        sum0 += __shfl_xor_sync(0xffffffffu, sum0, 1);
        sum0 += __shfl_xor_sync(0xffffffffu, sum0, 2);
        sum1 += __shfl_xor_sync(0xffffffffu, sum1, 1);
        sum1 += __shfl_xor_sync(0xffffffffu, sum1, 2);

        mr0 = mn0; mr1 = mn1;
        l0 = l0 * al0 + sum0;
        l1 = l1 * al1 + sum1;
        #pragma unroll
        for (int nt = 0; nt < 8; nt++) {
            oacc[nt][0] *= al0; oacc[nt][1] *= al0;
            oacc[nt][2] *= al1; oacc[nt][3] *= al1;
        }
        __syncwarp();

        #pragma unroll
        for (int kt = 0; kt < 8; kt++) {
            uint32_t pa[4];
            pa[0] = __float_as_uint(sP[(wq + g) * STP + kt * 8 + t]);
            pa[1] = __float_as_uint(sP[(wq + g + 8) * STP + kt * 8 + t]);
            pa[2] = __float_as_uint(sP[(wq + g) * STP + kt * 8 + t + 4]);
            pa[3] = __float_as_uint(sP[(wq + g + 8) * STP + kt * 8 + t + 4]);
            #pragma unroll
            for (int nt = 0; nt < 8; nt++) {
                const float* vp = &V0[(size_t)(kt * 8 + t) * STV + nt * 8 + g];
                uint32_t vb[2];
                vb[0] = f2tf(vp[0]);
                vb[1] = f2tf(vp[4 * STV]);
                mma_tf32(oacc[nt], pa, vb);
            }
        }
    }

    float inv0 = 1.f / l0, inv1 = 1.f / l1;
    size_t row0 = (size_t)(b * NQ_ + q0 + wq + g) * D_ + h * HD_;
    size_t row1 = row0 + 8 * D_;
    #pragma unroll
    for (int nt = 0; nt < 8; nt++) {
        int col = nt * 8 + 2 * t;
        float2 o0 = make_float2(oacc[nt][0] * inv0, oacc[nt][1] * inv0);
        float2 o1 = make_float2(oacc[nt][2] * inv1, oacc[nt][3] * inv1);
        *(float2*)&ctx[row0 + col] = o0;
        *(float2*)&ctx[row1 + col] = o1;
    }
}

extern "C" void kernel_launch(void* const* d_in, const int* in_sizes, int n_in,
                              void* d_out, int out_size)
{
    const float* q  = (const float*)d_in[0];
    const float* k  = (const float*)d_in[1];
    const float* v  = (const float*)d_in[2];
    const float* ab = (const float*)d_in[3];
    const void*  mk = d_in[4];
    const float* Wq = (const float*)d_in[5];
    const float* bq = (const float*)d_in[6];
    const float* Wk = (const float*)d_in[7];
    const float* bk = (const float*)d_in[8];
    const float* Wv = (const float*)d_in[9];
    const float* bv = (const float*)d_in[10];
    const float* Wo = (const float*)d_in[11];
    const float* bo = (const float*)d_in[12];
    float* out = (float*)d_out;

    static int smem_set = 0;
    if (!smem_set) {
        cudaFuncSetAttribute(qkv_proj_kernel,
                             cudaFuncAttributeMaxDynamicSharedMemorySize, GEMM_SMEM);
        cudaFuncSetAttribute(oproj_kernel,
                             cudaFuncAttributeMaxDynamicSharedMemorySize, GEMM_SMEM);
        cudaFuncSetAttribute(attn_tf32_kernel,
                             cudaFuncAttributeMaxDynamicSharedMemorySize, ATTN_SMEM);
        smem_set = 1;
    }

    float* gctx;
    cudaGetSymbolAddress((void**)&gctx, g_ctx);

    detect_mask_kernel<<<1, 256>>>((const unsigned char*)mk);
    prep_mask_kernel<<<B_, 256>>>(mk);

    qkv_proj_kernel<<<dim3(8, 80), 256, GEMM_SMEM>>>(q, k, v, Wq, bq, Wk, bk, Wv, bv);

    attn_tf32_kernel<<<dim3(NQ_ / 128, H_, B_), 256, ATTN_SMEM>>>(ab, gctx);

    oproj_kernel<<<dim3(8, 16), 256, GEMM_SMEM>>>(Wo, bo, out);
}

// round 4
// speedup vs baseline: 3.1941x; 1.4138x over previous
#include <cuda_runtime.h>
#include <math.h>
#include <stdint.h>

#define B_     2
#define NQ_    1024
#define NK_    2048
#define D_     1024
#define H_     16
#define HD_    64
#define SCALE_ 0.125f

__device__ float g_Q[(size_t)B_ * NQ_ * D_];
__device__ float g_K[(size_t)B_ * NK_ * D_];
__device__ float g_V[(size_t)B_ * NK_ * D_];
__device__ float g_ctx[(size_t)B_ * NQ_ * D_];
__device__ float g_maskf[B_ * NK_];
__device__ int   g_mask_mode;

__device__ __forceinline__ uint32_t f2tf(float x) {
    uint32_t u; asm("cvt.rna.tf32.f32 %0, %1;" : "=r"(u) : "f"(x)); return u;
}
__device__ __forceinline__ float f2tff(float x) { return __uint_as_float(f2tf(x)); }

__device__ __forceinline__ void mma_tf32(float* d, const uint32_t* a, const uint32_t* b) {
    asm volatile(
        "mma.sync.aligned.m16n8k8.row.col.f32.tf32.tf32.f32 "
        "{%0,%1,%2,%3}, {%4,%5,%6,%7}, {%8,%9}, {%0,%1,%2,%3};"
        : "+f"(d[0]), "+f"(d[1]), "+f"(d[2]), "+f"(d[3])
        : "r"(a[0]), "r"(a[1]), "r"(a[2]), "r"(a[3]),
          "r"(b[0]), "r"(b[1]));
}

__device__ __forceinline__ void cp16(uint32_t dst, const void* src) {
    asm volatile("cp.async.cg.shared.global [%0], [%1], 16;" :: "r"(dst), "l"(src));
}
__device__ __forceinline__ void cp_commit() { asm volatile("cp.async.commit_group;"); }
template <int N> __device__ __forceinline__ void cp_wait() {
    asm volatile("cp.async.wait_group %0;" :: "n"(N));
}

__global__ void detect_mask_kernel(const unsigned char* __restrict__ p) {
    __shared__ int s_nonbin, s_unal;
    int tid = threadIdx.x;
    if (tid == 0) { s_nonbin = 0; s_unal = 0; }
    __syncthreads();
    for (int i = tid; i < B_ * NK_; i += 256) {
        unsigned char v = p[i];
        if (v > 1) s_nonbin = 1;
        else if (v == 1 && (i & 3)) s_unal = 1;
    }
    __syncthreads();
    if (tid == 0) g_mask_mode = s_nonbin ? 2 : (s_unal ? 0 : 1);
}

__global__ void prep_mask_kernel(const void* __restrict__ mptr) {
    int b = blockIdx.x;
    int tid = threadIdx.x;
    __shared__ int anyUnmasked;
    if (tid == 0) anyUnmasked = 0;
    __syncthreads();
    int mode = g_mask_mode;
    float vals[NK_ / 256];
    #pragma unroll
    for (int x = 0; x < NK_ / 256; x++) {
        int i = tid + x * 256;
        float m;
        if (mode == 0)      m = ((const unsigned char*)mptr)[b * NK_ + i] ? 1.f : 0.f;
        else if (mode == 1) m = ((const int*)mptr)[b * NK_ + i] ? 1.f : 0.f;
        else                m = (((const float*)mptr)[b * NK_ + i] != 0.f) ? 1.f : 0.f;
        vals[x] = m;
        if (m == 0.f) anyUnmasked = 1;
    }
    __syncthreads();
    #pragma unroll
    for (int x = 0; x < NK_ / 256; x++) {
        int i = tid + x * 256;
        float m = vals[x];
        if (i == 0 && !anyUnmasked) m = 0.f;
        g_maskf[b * NK_ + i] = m;
    }
}

#define GA_S 36
#define GB_S 136
#define GEMM_SMEM ((2 * 128 * GA_S + 2 * 32 * GB_S) * 4)

__device__ __forceinline__ void gemm_body(
    const float* __restrict__ X, const float* __restrict__ W,
    const float* __restrict__ bias, float* __restrict__ Y,
    int m0, int n0, float* sA, float* sB)
{
    const int K = 1024, N = 1024;
    int tid  = threadIdx.x;
    int lane = tid & 31, warp = tid >> 5;
    int g = lane >> 2, t = lane & 3;
    int wm = (warp >> 2) * 64;
    int wn = (warp & 3) * 32;

    uint32_t sA_u = (uint32_t)__cvta_generic_to_shared(sA);
    uint32_t sB_u = (uint32_t)__cvta_generic_to_shared(sB);

    float acc[4][4][4];
    #pragma unroll
    for (int i = 0; i < 4; i++)
        #pragma unroll
        for (int j = 0; j < 4; j++)
            #pragma unroll
            for (int c = 0; c < 4; c++) acc[i][j][c] = 0.f;

    auto issue = [&](int buf, int k0) {
        #pragma unroll
        for (int i = 0; i < 4; i++) {
            int c = tid + i * 256;
            int row = c >> 3, col = (c & 7) * 4;
            cp16(sA_u + (uint32_t)(((buf * 128 + row) * GA_S + col) * 4),
                 X + (size_t)(m0 + row) * K + k0 + col);
        }
        #pragma unroll
        for (int i = 0; i < 4; i++) {
            int c = tid + i * 256;
            int row = c >> 5, col = (c & 31) * 4;
            cp16(sB_u + (uint32_t)(((buf * 32 + row) * GB_S + col) * 4),
                 W + (size_t)(k0 + row) * N + n0 + col);
        }
    };

    issue(0, 0);
    cp_commit();

    #pragma unroll 1
    for (int it = 0; it < 32; it++) {
        int buf = it & 1;
        if (it > 0) __syncthreads();
        if (it < 31) {
            issue(buf ^ 1, (it + 1) * 32);
            cp_commit();
            cp_wait<1>();
        } else {
            cp_wait<0>();
        }
        __syncthreads();

        const float* A0 = sA + (size_t)buf * 128 * GA_S;
        const float* B0 = sB + (size_t)buf * 32 * GB_S;

        #pragma unroll
        for (int kt = 0; kt < 4; kt++) {
            uint32_t a[4][4], bfr[4][2];
            #pragma unroll
            for (int mt = 0; mt < 4; mt++) {
                const float* ap = &A0[(size_t)(wm + mt * 16 + g) * GA_S + kt * 8 + t];
                a[mt][0] = f2tf(ap[0]);
                a[mt][1] = f2tf(ap[8 * GA_S]);
                a[mt][2] = f2tf(ap[4]);
                a[mt][3] = f2tf(ap[8 * GA_S + 4]);
            }
            #pragma unroll
            for (int nt = 0; nt < 4; nt++) {
                const float* bp = &B0[(size_t)(kt * 8 + t) * GB_S + wn + nt * 8 + g];
                bfr[nt][0] = f2tf(bp[0]);
                bfr[nt][1] = f2tf(bp[4 * GB_S]);
            }
            #pragma unroll
            for (int mt = 0; mt < 4; mt++)
                #pragma unroll
                for (int nt = 0; nt < 4; nt++)
                    mma_tf32(acc[mt][nt], a[mt], bfr[nt]);
        }
    }

    #pragma unroll
    for (int mt = 0; mt < 4; mt++) {
        int row = m0 + wm + mt * 16 + g;
        #pragma unroll
        for (int nt = 0; nt < 4; nt++) {
            int col = n0 + wn + nt * 8 + 2 * t;
            float2 bb = *(const float2*)&bias[col];
            float2 o0, o1;
            o0.x = acc[mt][nt][0] + bb.x;
            o0.y = acc[mt][nt][1] + bb.y;
            o1.x = acc[mt][nt][2] + bb.x;
            o1.y = acc[mt][nt][3] + bb.y;
            *(float2*)&Y[(size_t)row * N + col]       = o0;
            *(float2*)&Y[(size_t)(row + 8) * N + col] = o1;
        }
    }
}

__global__ __launch_bounds__(256, 2) void qkv_proj_kernel(
    const float* __restrict__ q, const float* __restrict__ k, const float* __restrict__ v,
    const float* __restrict__ Wq, const float* __restrict__ bq,
    const float* __restrict__ Wk, const float* __restrict__ bk,
    const float* __restrict__ Wv, const float* __restrict__ bv)
{
    extern __shared__ float sm[];
    int y = blockIdx.y;
    const float *X, *W, *bias; float* Y; int m0;
    if (y < 16)      { X = q; W = Wq; bias = bq; Y = g_Q; m0 = y * 128; }
    else if (y < 48) { X = k; W = Wk; bias = bk; Y = g_K; m0 = (y - 16) * 128; }
    else             { X = v; W = Wv; bias = bv; Y = g_V; m0 = (y - 48) * 128; }
    gemm_body(X, W, bias, Y, m0, blockIdx.x * 128, sm, sm + 2 * 128 * GA_S);
}

__global__ __launch_bounds__(256, 2) void oproj_kernel(
    const float* __restrict__ Wo, const float* __restrict__ bo, float* __restrict__ out)
{
    extern __shared__ float sm[];
    gemm_body(g_ctx, Wo, bo, out, blockIdx.y * 128, blockIdx.x * 128,
              sm, sm + 2 * 128 * GA_S);
}

#define STK 68
#define STV 72
#define STP 68
#define ATTN_SMEM ((2 * 64 * STK + 2 * 64 * STV + 128 * STP) * 4)

__global__ __launch_bounds__(256, 2) void attn_tf32_kernel(
    const float* __restrict__ bias, float* __restrict__ ctx)
{
    extern __shared__ float smem[];
    float* sK = smem;
    float* sV = smem + 2 * 64 * STK;
    float* sP = smem + 2 * 64 * STK + 2 * 64 * STV;

    int tid = threadIdx.x, lane = tid & 31, warp = tid >> 5;
    int g = lane >> 2, t = lane & 3;
    int b = blockIdx.z, h = blockIdx.y, q0 = blockIdx.x * 128;
    int wq = warp * 16;

    const float* Qg = g_Q + (size_t)(b * NQ_ + q0) * D_ + h * HD_;
    const float* Kg = g_K + (size_t)b * NK_ * D_ + h * HD_;
    const float* Vg = g_V + (size_t)b * NK_ * D_ + h * HD_;
    const float* biasg = bias + (((size_t)b * H_ + h) * NQ_ + q0) * NK_;
    const float* mg = g_maskf + b * NK_;

    uint32_t sK_u = (uint32_t)__cvta_generic_to_shared(sK);
    uint32_t sV_u = (uint32_t)__cvta_generic_to_shared(sV);

    auto issueKV = [&](int buf, int k0) {
        #pragma unroll
        for (int i = 0; i < 4; i++) {
            int c = tid + i * 256;
            int row = c >> 4, col = (c & 15) * 4;
            cp16(sK_u + (uint32_t)(((buf * 64 + row) * STK + col) * 4),
                 Kg + (size_t)(k0 + row) * D_ + col);
            cp16(sV_u + (uint32_t)(((buf * 64 + row) * STV + col) * 4),
                 Vg + (size_t)(k0 + row) * D_ + col);
        }
    };

    issueKV(0, 0);
    cp_commit();

    for (int i = tid; i < 128 * 16; i += 256) {
        int row = i >> 4, dq = (i & 15) * 4;
        float4 v = *(const float4*)&Qg[(size_t)row * D_ + dq];
        float* p = &sP[row * STP + dq];
        p[0] = f2tff(v.x); p[1] = f2tff(v.y); p[2] = f2tff(v.z); p[3] = f2tff(v.w);
    }
    __syncthreads();

    uint32_t qf[8][4];
    #pragma unroll
    for (int kt = 0; kt < 8; kt++) {
        qf[kt][0] = __float_as_uint(sP[(wq + g) * STP + kt * 8 + t]);
        qf[kt][1] = __float_as_uint(sP[(wq + g + 8) * STP + kt * 8 + t]);
        qf[kt][2] = __float_as_uint(sP[(wq + g) * STP + kt * 8 + t + 4]);
        qf[kt][3] = __float_as_uint(sP[(wq + g + 8) * STP + kt * 8 + t + 4]);
    }

    float oacc[8][4];
    #pragma unroll
    for (int nt = 0; nt < 8; nt++)
        #pragma unroll
        for (int c = 0; c < 4; c++) oacc[nt][c] = 0.f;
    float mr0 = -INFINITY, mr1 = -INFINITY, l0 = 0.f, l1 = 0.f;

    #pragma unroll 1
    for (int it = 0; it < NK_ / 64; it++) {
        int buf = it & 1, k0 = it * 64;
        if (it > 0) __syncthreads();
        if (it < NK_ / 64 - 1) {
            issueKV(buf ^ 1, k0 + 64);
            cp_commit();
            cp_wait<1>();
        } else {
            cp_wait<0>();
        }
        __syncthreads();

        const float* K0 = sK + (size_t)buf * 64 * STK;
        const float* V0 = sV + (size_t)buf * 64 * STV;

        float sacc[8][4];
        #pragma unroll
        for (int nt = 0; nt < 8; nt++)
            #pragma unroll
            for (int c = 0; c < 4; c++) sacc[nt][c] = 0.f;

        #pragma unroll
        for (int kt = 0; kt < 8; kt++) {
            #pragma unroll
            for (int nt = 0; nt < 8; nt++) {
                const float* kp = &K0[(size_t)(nt * 8 + g) * STK + kt * 8 + t];
                uint32_t bfr[2];
                bfr[0] = f2tf(kp[0]);
                bfr[1] = f2tf(kp[4]);
                mma_tf32(sacc[nt], qf[kt], bfr);
            }
        }

        float rmax0 = -INFINITY, rmax1 = -INFINITY;
        #pragma unroll
        for (int nt = 0; nt < 8; nt++) {
            int kc = k0 + nt * 8 + 2 * t;
            float2 mk  = *(const float2*)&mg[kc];
            float2 b0v = *(const float2*)&biasg[(size_t)(wq + g) * NK_ + kc];
            float2 b1v = *(const float2*)&biasg[(size_t)(wq + g + 8) * NK_ + kc];
            sacc[nt][0] = (mk.x != 0.f) ? -INFINITY : sacc[nt][0] * SCALE_ + b0v.x;
            sacc[nt][1] = (mk.y != 0.f) ? -INFINITY : sacc[nt][1] * SCALE_ + b0v.y;
            sacc[nt][2] = (mk.x != 0.f) ? -INFINITY : sacc[nt][2] * SCALE_ + b1v.x;
            sacc[nt][3] = (mk.y != 0.f) ? -INFINITY : sacc[nt][3] * SCALE_ + b1v.y;
            rmax0 = fmaxf(rmax0, fmaxf(sacc[nt][0], sacc[nt][1]));
            rmax1 = fmaxf(rmax1, fmaxf(sacc[nt][2], sacc[nt][3]));
        }
        rmax0 = fmaxf(rmax0, __shfl_xor_sync(0xffffffffu, rmax0, 1));
        rmax0 = fmaxf(rmax0, __shfl_xor_sync(0xffffffffu, rmax0, 2));
        rmax1 = fmaxf(rmax1, __shfl_xor_sync(0xffffffffu, rmax1, 1));
        rmax1 = fmaxf(rmax1, __shfl_xor_sync(0xffffffffu, rmax1, 2));

        float mn0 = fmaxf(mr0, rmax0), mn1 = fmaxf(mr1, rmax1);
        bool dead0 = (mn0 == -INFINITY), dead1 = (mn1 == -INFINITY);
        float al0 = dead0 ? 1.f : __expf(mr0 - mn0);
        float al1 = dead1 ? 1.f : __expf(mr1 - mn1);
        float sum0 = 0.f, sum1 = 0.f;

        #pragma unroll
        for (int nt = 0; nt < 8; nt++) {
            float p00 = dead0 ? 0.f : __expf(sacc[nt][0] - mn0);
            float p01 = dead0 ? 0.f : __expf(sacc[nt][1] - mn0);
            float p10 = dead1 ? 0.f : __expf(sacc[nt][2] - mn1);
            float p11 = dead1 ? 0.f : __expf(sacc[nt][3] - mn1);
            sum0 += p00 + p01;
            sum1 += p10 + p11;
            float2 w0 = make_float2(f2tff(p00), f2tff(p01));
            float2 w1 = make_float2(f2tff(p10), f2tff(p11));
            *(float2*)&sP[(wq + g) * STP + nt * 8 + 2 * t]     = w0;
            *(float2*)&sP[(wq + g + 8) * STP + nt * 8 + 2 * t] = w1;
        }
        sum0 += __shfl_xor_sync(0xffffffffu, sum0, 1);
        sum0 += __shfl_xor_sync(0xffffffffu, sum0, 2);
        sum1 += __shfl_xor_sync(0xffffffffu, sum1, 1);
        sum1 += __shfl_xor_sync(0xffffffffu, sum1, 2);

        mr0 = mn0; mr1 = mn1;
        l0 = l0 * al0 + sum0;
        l1 = l1 * al1 + sum1;
        #pragma unroll
        for (int nt = 0; nt < 8; nt++) {
            oacc[nt][0] *= al0; oacc[nt][1] *= al0;
            oacc[nt][2] *= al1; oacc[nt][3] *= al1;
        }
        __syncwarp();

        #pragma unroll
        for (int kt = 0; kt < 8; kt++) {
            uint32_t pa[4];
            pa[0] = __float_as_uint(sP[(wq + g) * STP + kt * 8 + t]);
            pa[1] = __float_as_uint(sP[(wq + g + 8) * STP + kt * 8 + t]);
            pa[2] = __float_as_uint(sP[(wq + g) * STP + kt * 8 + t + 4]);
            pa[3] = __float_as_uint(sP[(wq + g + 8) * STP + kt * 8 + t + 4]);
            #pragma unroll
            for (int nt = 0; nt < 8; nt++) {
                const float* vp = &V0[(size_t)(kt * 8 + t) * STV + nt * 8 + g];
                uint32_t vb[2];
                vb[0] = f2tf(vp[0]);
                vb[1] = f2tf(vp[4 * STV]);
                mma_tf32(oacc[nt], pa, vb);
            }
        }
    }

    float inv0 = 1.f / l0, inv1 = 1.f / l1;
    size_t row0 = (size_t)(b * NQ_ + q0 + wq + g) * D_ + h * HD_;
    size_t row1 = row0 + 8 * D_;
    #pragma unroll
    for (int nt = 0; nt < 8; nt++) {
        int col = nt * 8 + 2 * t;
        float2 o0 = make_float2(oacc[nt][0] * inv0, oacc[nt][1] * inv0);
        float2 o1 = make_float2(oacc[nt][2] * inv1, oacc[nt][3] * inv1);
        *(float2*)&ctx[row0 + col] = o0;
        *(float2*)&ctx[row1 + col] = o1;
    }
}

extern "C" void kernel_launch(void* const* d_in, const int* in_sizes, int n_in,
                              void* d_out, int out_size)
{
    const float* q  = (const float*)d_in[0];
    const float* k  = (const float*)d_in[1];
    const float* v  = (const float*)d_in[2];
    const float* ab = (const float*)d_in[3];
    const void*  mk = d_in[4];
    const float* Wq = (const float*)d_in[5];
    const float* bq = (const float*)d_in[6];
    const float* Wk = (const float*)d_in[7];
    const float* bk = (const float*)d_in[8];
    const float* Wv = (const float*)d_in[9];
    const float* bv = (const float*)d_in[10];
    const float* Wo = (const float*)d_in[11];
    const float* bo = (const float*)d_in[12];
    float* out = (float*)d_out;

    static int smem_set = 0;
    if (!smem_set) {
        cudaFuncSetAttribute(qkv_proj_kernel,
                             cudaFuncAttributeMaxDynamicSharedMemorySize, GEMM_SMEM);
        cudaFuncSetAttribute(oproj_kernel,
                             cudaFuncAttributeMaxDynamicSharedMemorySize, GEMM_SMEM);
        cudaFuncSetAttribute(attn_tf32_kernel,
                             cudaFuncAttributeMaxDynamicSharedMemorySize, ATTN_SMEM);
        smem_set = 1;
    }

    float* gctx;
    cudaGetSymbolAddress((void**)&gctx, g_ctx);

    detect_mask_kernel<<<1, 256>>>((const unsigned char*)mk);
    prep_mask_kernel<<<B_, 256>>>(mk);

    qkv_proj_kernel<<<dim3(8, 80), 256, GEMM_SMEM>>>(q, k, v, Wq, bq, Wk, bk, Wv, bv);

    attn_tf32_kernel<<<dim3(NQ_ / 128, H_, B_), 256, ATTN_SMEM>>>(ab, gctx);

    oproj_kernel<<<dim3(8, 16), 256, GEMM_SMEM>>>(Wo, bo, out);
}

// round 5
// speedup vs baseline: 3.3233x; 1.0405x over previous
#include <cuda_runtime.h>
#include <math.h>
#include <stdint.h>

#define B_     2
#define NQ_    1024
#define NK_    2048
#define D_     1024
#define H_     16
#define HD_    64
#define SCALE_ 0.125f

__device__ float g_Q[(size_t)B_ * NQ_ * D_];   // stored pre-scaled + tf32-rounded
__device__ float g_K[(size_t)B_ * NK_ * D_];   // stored tf32-rounded
__device__ float g_V[(size_t)B_ * NK_ * D_];   // stored tf32-rounded
__device__ float g_ctx[(size_t)B_ * NQ_ * D_];
__device__ float g_maskf[B_ * NK_];
__device__ int   g_mask_mode;

__device__ __forceinline__ uint32_t f2tf(float x) {
    uint32_t u; asm("cvt.rna.tf32.f32 %0, %1;" : "=r"(u) : "f"(x)); return u;
}
__device__ __forceinline__ float f2tff(float x) { return __uint_as_float(f2tf(x)); }

__device__ __forceinline__ void mma_tf32(float* d, const uint32_t* a, const uint32_t* b) {
    asm volatile(
        "mma.sync.aligned.m16n8k8.row.col.f32.tf32.tf32.f32 "
        "{%0,%1,%2,%3}, {%4,%5,%6,%7}, {%8,%9}, {%0,%1,%2,%3};"
        : "+f"(d[0]), "+f"(d[1]), "+f"(d[2]), "+f"(d[3])
        : "r"(a[0]), "r"(a[1]), "r"(a[2]), "r"(a[3]),
          "r"(b[0]), "r"(b[1]));
}

__device__ __forceinline__ void cp16(uint32_t dst, const void* src) {
    asm volatile("cp.async.cg.shared.global [%0], [%1], 16;" :: "r"(dst), "l"(src));
}
__device__ __forceinline__ void cp_commit() { asm volatile("cp.async.commit_group;"); }
template <int N> __device__ __forceinline__ void cp_wait() {
    asm volatile("cp.async.wait_group %0;" :: "n"(N));
}

__global__ void detect_mask_kernel(const unsigned char* __restrict__ p) {
    __shared__ int s_nonbin, s_unal;
    int tid = threadIdx.x;
    if (tid == 0) { s_nonbin = 0; s_unal = 0; }
    __syncthreads();
    for (int i = tid; i < B_ * NK_; i += 256) {
        unsigned char v = p[i];
        if (v > 1) s_nonbin = 1;
        else if (v == 1 && (i & 3)) s_unal = 1;
    }
    __syncthreads();
    if (tid == 0) g_mask_mode = s_nonbin ? 2 : (s_unal ? 0 : 1);
}

__global__ void prep_mask_kernel(const void* __restrict__ mptr) {
    int b = blockIdx.x;
    int tid = threadIdx.x;
    __shared__ int anyUnmasked;
    if (tid == 0) anyUnmasked = 0;
    __syncthreads();
    int mode = g_mask_mode;
    float vals[NK_ / 256];
    #pragma unroll
    for (int x = 0; x < NK_ / 256; x++) {
        int i = tid + x * 256;
        float m;
        if (mode == 0)      m = ((const unsigned char*)mptr)[b * NK_ + i] ? 1.f : 0.f;
        else if (mode == 1) m = ((const int*)mptr)[b * NK_ + i] ? 1.f : 0.f;
        else                m = (((const float*)mptr)[b * NK_ + i] != 0.f) ? 1.f : 0.f;
        vals[x] = m;
        if (m == 0.f) anyUnmasked = 1;
    }
    __syncthreads();
    #pragma unroll
    for (int x = 0; x < NK_ / 256; x++) {
        int i = tid + x * 256;
        float m = vals[x];
        if (i == 0 && !anyUnmasked) m = 0.f;
        g_maskf[b * NK_ + i] = m;
    }
}

#define GA_S 36
#define GB_S 136
#define GEMM_SMEM ((2 * 128 * GA_S + 2 * 32 * GB_S) * 4)

// MODE 0: raw fp32 store.  MODE 1: store tf32-rounded (acc+bias)*outScale.
template <int MODE>
__device__ __forceinline__ void gemm_body(
    const float* __restrict__ X, const float* __restrict__ W,
    const float* __restrict__ bias, float* __restrict__ Y,
    int m0, int n0, float outScale, float* sA, float* sB)
{
    const int K = 1024, N = 1024;
    int tid  = threadIdx.x;
    int lane = tid & 31, warp = tid >> 5;
    int g = lane >> 2, t = lane & 3;
    int wm = (warp >> 2) * 64;
    int wn = (warp & 3) * 32;

    uint32_t sA_u = (uint32_t)__cvta_generic_to_shared(sA);
    uint32_t sB_u = (uint32_t)__cvta_generic_to_shared(sB);

    float acc[4][4][4];
    #pragma unroll
    for (int i = 0; i < 4; i++)
        #pragma unroll
        for (int j = 0; j < 4; j++)
            #pragma unroll
            for (int c = 0; c < 4; c++) acc[i][j][c] = 0.f;

    auto issue = [&](int buf, int k0) {
        #pragma unroll
        for (int i = 0; i < 4; i++) {
            int c = tid + i * 256;
            int row = c >> 3, col = (c & 7) * 4;
            cp16(sA_u + (uint32_t)(((buf * 128 + row) * GA_S + col) * 4),
                 X + (size_t)(m0 + row) * K + k0 + col);
        }
        #pragma unroll
        for (int i = 0; i < 4; i++) {
            int c = tid + i * 256;
            int row = c >> 5, col = (c & 31) * 4;
            cp16(sB_u + (uint32_t)(((buf * 32 + row) * GB_S + col) * 4),
                 W + (size_t)(k0 + row) * N + n0 + col);
        }
    };

    issue(0, 0);
    cp_commit();

    #pragma unroll 1
    for (int it = 0; it < 32; it++) {
        int buf = it & 1;
        if (it > 0) __syncthreads();
        if (it < 31) {
            issue(buf ^ 1, (it + 1) * 32);
            cp_commit();
            cp_wait<1>();
        } else {
            cp_wait<0>();
        }
        __syncthreads();

        const float* A0 = sA + (size_t)buf * 128 * GA_S;
        const float* B0 = sB + (size_t)buf * 32 * GB_S;

        #pragma unroll
        for (int kt = 0; kt < 4; kt++) {
            uint32_t a[4][4], bfr[4][2];
            #pragma unroll
            for (int mt = 0; mt < 4; mt++) {
                const float* ap = &A0[(size_t)(wm + mt * 16 + g) * GA_S + kt * 8 + t];
                a[mt][0] = f2tf(ap[0]);
                a[mt][1] = f2tf(ap[8 * GA_S]);
                a[mt][2] = f2tf(ap[4]);
                a[mt][3] = f2tf(ap[8 * GA_S + 4]);
            }
            #pragma unroll
            for (int nt = 0; nt < 4; nt++) {
                const float* bp = &B0[(size_t)(kt * 8 + t) * GB_S + wn + nt * 8 + g];
                bfr[nt][0] = f2tf(bp[0]);
                bfr[nt][1] = f2tf(bp[4 * GB_S]);
            }
            #pragma unroll
            for (int mt = 0; mt < 4; mt++)
                #pragma unroll
                for (int nt = 0; nt < 4; nt++)
                    mma_tf32(acc[mt][nt], a[mt], bfr[nt]);
        }
    }

    #pragma unroll
    for (int mt = 0; mt < 4; mt++) {
        int row = m0 + wm + mt * 16 + g;
        #pragma unroll
        for (int nt = 0; nt < 4; nt++) {
            int col = n0 + wn + nt * 8 + 2 * t;
            float2 bb = *(const float2*)&bias[col];
            float2 o0, o1;
            if (MODE == 1) {
                o0.x = f2tff((acc[mt][nt][0] + bb.x) * outScale);
                o0.y = f2tff((acc[mt][nt][1] + bb.y) * outScale);
                o1.x = f2tff((acc[mt][nt][2] + bb.x) * outScale);
                o1.y = f2tff((acc[mt][nt][3] + bb.y) * outScale);
            } else {
                o0.x = acc[mt][nt][0] + bb.x;
                o0.y = acc[mt][nt][1] + bb.y;
                o1.x = acc[mt][nt][2] + bb.x;
                o1.y = acc[mt][nt][3] + bb.y;
            }
            *(float2*)&Y[(size_t)row * N + col]       = o0;
            *(float2*)&Y[(size_t)(row + 8) * N + col] = o1;
        }
    }
}

__global__ __launch_bounds__(256, 2) void qkv_proj_kernel(
    const float* __restrict__ q, const float* __restrict__ k, const float* __restrict__ v,
    const float* __restrict__ Wq, const float* __restrict__ bq,
    const float* __restrict__ Wk, const float* __restrict__ bk,
    const float* __restrict__ Wv, const float* __restrict__ bv)
{
    extern __shared__ float sm[];
    int y = blockIdx.y;
    const float *X, *W, *bias; float* Y; int m0; float sc;
    if (y < 16)      { X = q; W = Wq; bias = bq; Y = g_Q; m0 = y * 128;        sc = SCALE_; }
    else if (y < 48) { X = k; W = Wk; bias = bk; Y = g_K; m0 = (y - 16) * 128; sc = 1.0f;   }
    else             { X = v; W = Wv; bias = bv; Y = g_V; m0 = (y - 48) * 128; sc = 1.0f;   }
    gemm_body<1>(X, W, bias, Y, m0, blockIdx.x * 128, sc, sm, sm + 2 * 128 * GA_S);
}

__global__ __launch_bounds__(256, 2) void oproj_kernel(
    const float* __restrict__ Wo, const float* __restrict__ bo, float* __restrict__ out)
{
    extern __shared__ float sm[];
    gemm_body<0>(g_ctx, Wo, bo, out, blockIdx.y * 128, blockIdx.x * 128, 1.0f,
                 sm, sm + 2 * 128 * GA_S);
}

#define STK 68
#define STV 72
#define STP 68
#define ATTN_SMEM ((2 * 64 * STK + 2 * 64 * STV + 128 * STP) * 4)

__global__ __launch_bounds__(256, 2) void attn_tf32_kernel(
    const float* __restrict__ bias, float* __restrict__ ctx)
{
    extern __shared__ float smem[];
    float* sK = smem;
    float* sV = smem + 2 * 64 * STK;
    float* sP = smem + 2 * 64 * STK + 2 * 64 * STV;

    int tid = threadIdx.x, lane = tid & 31, warp = tid >> 5;
    int g = lane >> 2, t = lane & 3;
    int b = blockIdx.z, h = blockIdx.y, q0 = blockIdx.x * 128;
    int wq = warp * 16;

    const float* Qg = g_Q + (size_t)(b * NQ_ + q0) * D_ + h * HD_;
    const float* Kg = g_K + (size_t)b * NK_ * D_ + h * HD_;
    const float* Vg = g_V + (size_t)b * NK_ * D_ + h * HD_;
    const float* biasg = bias + (((size_t)b * H_ + h) * NQ_ + q0) * NK_;
    const float* mg = g_maskf + b * NK_;

    uint32_t sK_u = (uint32_t)__cvta_generic_to_shared(sK);
    uint32_t sV_u = (uint32_t)__cvta_generic_to_shared(sV);

    auto issueKV = [&](int buf, int k0) {
        #pragma unroll
        for (int i = 0; i < 4; i++) {
            int c = tid + i * 256;
            int row = c >> 4, col = (c & 15) * 4;
            cp16(sK_u + (uint32_t)(((buf * 64 + row) * STK + col) * 4),
                 Kg + (size_t)(k0 + row) * D_ + col);
            cp16(sV_u + (uint32_t)(((buf * 64 + row) * STV + col) * 4),
                 Vg + (size_t)(k0 + row) * D_ + col);
        }
    };

    issueKV(0, 0);
    cp_commit();

    // Stage Q (already tf32-rounded and pre-scaled by projection) — pure copy
    for (int i = tid; i < 128 * 16; i += 256) {
        int row = i >> 4, dq = (i & 15) * 4;
        *(float4*)&sP[row * STP + dq] = *(const float4*)&Qg[(size_t)row * D_ + dq];
    }
    __syncthreads();

    uint32_t qf[8][4];
    #pragma unroll
    for (int kt = 0; kt < 8; kt++) {
        qf[kt][0] = __float_as_uint(sP[(wq + g) * STP + kt * 8 + t]);
        qf[kt][1] = __float_as_uint(sP[(wq + g + 8) * STP + kt * 8 + t]);
        qf[kt][2] = __float_as_uint(sP[(wq + g) * STP + kt * 8 + t + 4]);
        qf[kt][3] = __float_as_uint(sP[(wq + g + 8) * STP + kt * 8 + t + 4]);
    }

    float oacc[8][4];
    #pragma unroll
    for (int nt = 0; nt < 8; nt++)
        #pragma unroll
        for (int c = 0; c < 4; c++) oacc[nt][c] = 0.f;
    float mr0 = -INFINITY, mr1 = -INFINITY, l0 = 0.f, l1 = 0.f;

    #pragma unroll 1
    for (int it = 0; it < NK_ / 64; it++) {
        int buf = it & 1, k0 = it * 64;
        if (it > 0) __syncthreads();
        if (it < NK_ / 64 - 1) {
            issueKV(buf ^ 1, k0 + 64);
            cp_commit();
            cp_wait<1>();
        } else {
            cp_wait<0>();
        }
        __syncthreads();

        const float* K0 = sK + (size_t)buf * 64 * STK;
        const float* V0 = sV + (size_t)buf * 64 * STV;

        float sacc[8][4];
        #pragma unroll
        for (int nt = 0; nt < 8; nt++)
            #pragma unroll
            for (int c = 0; c < 4; c++) sacc[nt][c] = 0.f;

        #pragma unroll
        for (int kt = 0; kt < 8; kt++) {
            #pragma unroll
            for (int nt = 0; nt < 8; nt++) {
                const float* kp = &K0[(size_t)(nt * 8 + g) * STK + kt * 8 + t];
                uint32_t bfr[2];
                bfr[0] = __float_as_uint(kp[0]);     // already tf32-rounded
                bfr[1] = __float_as_uint(kp[4]);
                mma_tf32(sacc[nt], qf[kt], bfr);
            }
        }

        // bias + mask (Q pre-scaled: no *SCALE here), row maxima
        float rmax0 = -INFINITY, rmax1 = -INFINITY;
        #pragma unroll
        for (int nt = 0; nt < 8; nt++) {
            int kc = k0 + nt * 8 + 2 * t;
            float2 mk  = *(const float2*)&mg[kc];
            float2 b0v = *(const float2*)&biasg[(size_t)(wq + g) * NK_ + kc];
            float2 b1v = *(const float2*)&biasg[(size_t)(wq + g + 8) * NK_ + kc];
            sacc[nt][0] = (mk.x != 0.f) ? -INFINITY : sacc[nt][0] + b0v.x;
            sacc[nt][1] = (mk.y != 0.f) ? -INFINITY : sacc[nt][1] + b0v.y;
            sacc[nt][2] = (mk.x != 0.f) ? -INFINITY : sacc[nt][2] + b1v.x;
            sacc[nt][3] = (mk.y != 0.f) ? -INFINITY : sacc[nt][3] + b1v.y;
            rmax0 = fmaxf(rmax0, fmaxf(sacc[nt][0], sacc[nt][1]));
            rmax1 = fmaxf(rmax1, fmaxf(sacc[nt][2], sacc[nt][3]));
        }
        rmax0 = fmaxf(rmax0, __shfl_xor_sync(0xffffffffu, rmax0, 1));
        rmax0 = fmaxf(rmax0, __shfl_xor_sync(0xffffffffu, rmax0, 2));
        rmax1 = fmaxf(rmax1, __shfl_xor_sync(0xffffffffu, rmax1, 1));
        rmax1 = fmaxf(rmax1, __shfl_xor_sync(0xffffffffu, rmax1, 2));

        float mn0 = fmaxf(mr0, rmax0), mn1 = fmaxf(mr1, rmax1);
        bool dead0 = (mn0 == -INFINITY), dead1 = (mn1 == -INFINITY);
        float al0 = dead0 ? 1.f : __expf(mr0 - mn0);
        float al1 = dead1 ? 1.f : __expf(mr1 - mn1);
        float sum0 = 0.f, sum1 = 0.f;

        #pragma unroll
        for (int nt = 0; nt < 8; nt++) {
            float p00 = dead0 ? 0.f : __expf(sacc[nt][0] - mn0);
            float p01 = dead0 ? 0.f : __expf(sacc[nt][1] - mn0);
            float p10 = dead1 ? 0.f : __expf(sacc[nt][2] - mn1);
            float p11 = dead1 ? 0.f : __expf(sacc[nt][3] - mn1);
            sum0 += p00 + p01;
            sum1 += p10 + p11;
            float2 w0 = make_float2(f2tff(p00), f2tff(p01));
            float2 w1 = make_float2(f2tff(p10), f2tff(p11));
            *(float2*)&sP[(wq + g) * STP + nt * 8 + 2 * t]     = w0;
            *(float2*)&sP[(wq + g + 8) * STP + nt * 8 + 2 * t] = w1;
        }
        sum0 += __shfl_xor_sync(0xffffffffu, sum0, 1);
        sum0 += __shfl_xor_sync(0xffffffffu, sum0, 2);
        sum1 += __shfl_xor_sync(0xffffffffu, sum1, 1);
        sum1 += __shfl_xor_sync(0xffffffffu, sum1, 2);

        mr0 = mn0; mr1 = mn1;
        l0 = l0 * al0 + sum0;
        l1 = l1 * al1 + sum1;
        #pragma unroll
        for (int nt = 0; nt < 8; nt++) {
            oacc[nt][0] *= al0; oacc[nt][1] *= al0;
            oacc[nt][2] *= al1; oacc[nt][3] *= al1;
        }
        __syncwarp();

        #pragma unroll
        for (int kt = 0; kt < 8; kt++) {
            uint32_t pa[4];
            pa[0] = __float_as_uint(sP[(wq + g) * STP + kt * 8 + t]);
            pa[1] = __float_as_uint(sP[(wq + g + 8) * STP + kt * 8 + t]);
            pa[2] = __float_as_uint(sP[(wq + g) * STP + kt * 8 + t + 4]);
            pa[3] = __float_as_uint(sP[(wq + g + 8) * STP + kt * 8 + t + 4]);
            #pragma unroll
            for (int nt = 0; nt < 8; nt++) {
                const float* vp = &V0[(size_t)(kt * 8 + t) * STV + nt * 8 + g];
                uint32_t vb[2];
                vb[0] = __float_as_uint(vp[0]);      // already tf32-rounded
                vb[1] = __float_as_uint(vp[4 * STV]);
                mma_tf32(oacc[nt], pa, vb);
            }
        }
    }

    float inv0 = 1.f / l0, inv1 = 1.f / l1;
    size_t row0 = (size_t)(b * NQ_ + q0 + wq + g) * D_ + h * HD_;
    size_t row1 = row0 + 8 * D_;
    #pragma unroll
    for (int nt = 0; nt < 8; nt++) {
        int col = nt * 8 + 2 * t;
        float2 o0 = make_float2(oacc[nt][0] * inv0, oacc[nt][1] * inv0);
        float2 o1 = make_float2(oacc[nt][2] * inv1, oacc[nt][3] * inv1);
        *(float2*)&ctx[row0 + col] = o0;
        *(float2*)&ctx[row1 + col] = o1;
    }
}

extern "C" void kernel_launch(void* const* d_in, const int* in_sizes, int n_in,
                              void* d_out, int out_size)
{
    const float* q  = (const float*)d_in[0];
    const float* k  = (const float*)d_in[1];
    const float* v  = (const float*)d_in[2];
    const float* ab = (const float*)d_in[3];
    const void*  mk = d_in[4];
    const float* Wq = (const float*)d_in[5];
    const float* bq = (const float*)d_in[6];
    const float* Wk = (const float*)d_in[7];
    const float* bk = (const float*)d_in[8];
    const float* Wv = (const float*)d_in[9];
    const float* bv = (const float*)d_in[10];
    const float* Wo = (const float*)d_in[11];
    const float* bo = (const float*)d_in[12];
    float* out = (float*)d_out;

    static int smem_set = 0;
    if (!smem_set) {
        cudaFuncSetAttribute(qkv_proj_kernel,
                             cudaFuncAttributeMaxDynamicSharedMemorySize, GEMM_SMEM);
        cudaFuncSetAttribute(oproj_kernel,
                             cudaFuncAttributeMaxDynamicSharedMemorySize, GEMM_SMEM);
        cudaFuncSetAttribute(attn_tf32_kernel,
                             cudaFuncAttributeMaxDynamicSharedMemorySize, ATTN_SMEM);
        smem_set = 1;
    }

    float* gctx;
    cudaGetSymbolAddress((void**)&gctx, g_ctx);

    detect_mask_kernel<<<1, 256>>>((const unsigned char*)mk);
    prep_mask_kernel<<<B_, 256>>>(mk);

    qkv_proj_kernel<<<dim3(8, 80), 256, GEMM_SMEM>>>(q, k, v, Wq, bq, Wk, bk, Wv, bv);

    attn_tf32_kernel<<<dim3(NQ_ / 128, H_, B_), 256, ATTN_SMEM>>>(ab, gctx);

    oproj_kernel<<<dim3(8, 16), 256, GEMM_SMEM>>>(Wo, bo, out);
}

// round 6
// speedup vs baseline: 3.5440x; 1.0664x over previous
#include <cuda_runtime.h>
#include <math.h>
#include <stdint.h>

#define B_     2
#define NQ_    1024
#define NK_    2048
#define D_     1024
#define H_     16
#define HD_    64
#define SCALE_ 0.125f

__device__ float g_Q[(size_t)B_ * NQ_ * D_];    // pre-scaled + tf32-rounded
__device__ float g_K[(size_t)B_ * NK_ * D_];    // tf32-rounded
__device__ float g_V[(size_t)B_ * NK_ * D_];    // tf32-rounded
__device__ float g_Vt[(size_t)B_ * H_ * HD_ * NK_];  // V transposed per (b,h): [d][key]
__device__ float g_ctx[(size_t)B_ * NQ_ * D_];
__device__ float g_maskf[B_ * NK_];
__device__ int   g_mask_mode;

__device__ __forceinline__ uint32_t f2tf(float x) {
    uint32_t u; asm("cvt.rna.tf32.f32 %0, %1;" : "=r"(u) : "f"(x)); return u;
}
__device__ __forceinline__ float f2tff(float x) { return __uint_as_float(f2tf(x)); }

__device__ __forceinline__ void mma_tf32(float* d, const uint32_t* a, const uint32_t* b) {
    asm volatile(
        "mma.sync.aligned.m16n8k8.row.col.f32.tf32.tf32.f32 "
        "{%0,%1,%2,%3}, {%4,%5,%6,%7}, {%8,%9}, {%0,%1,%2,%3};"
        : "+f"(d[0]), "+f"(d[1]), "+f"(d[2]), "+f"(d[3])
        : "r"(a[0]), "r"(a[1]), "r"(a[2]), "r"(a[3]),
          "r"(b[0]), "r"(b[1]));
}

__device__ __forceinline__ void ldsm4(uint32_t* r, uint32_t addr) {
    asm volatile("ldmatrix.sync.aligned.m8n8.x4.shared.b16 {%0,%1,%2,%3}, [%4];"
                 : "=r"(r[0]), "=r"(r[1]), "=r"(r[2]), "=r"(r[3]) : "r"(addr));
}

__device__ __forceinline__ void cp16(uint32_t dst, const void* src) {
    asm volatile("cp.async.cg.shared.global [%0], [%1], 16;" :: "r"(dst), "l"(src));
}
__device__ __forceinline__ void cp_commit() { asm volatile("cp.async.commit_group;"); }
template <int N> __device__ __forceinline__ void cp_wait() {
    asm volatile("cp.async.wait_group %0;" :: "n"(N));
}

__global__ void detect_mask_kernel(const unsigned char* __restrict__ p) {
    __shared__ int s_nonbin, s_unal;
    int tid = threadIdx.x;
    if (tid == 0) { s_nonbin = 0; s_unal = 0; }
    __syncthreads();
    for (int i = tid; i < B_ * NK_; i += 256) {
        unsigned char v = p[i];
        if (v > 1) s_nonbin = 1;
        else if (v == 1 && (i & 3)) s_unal = 1;
    }
    __syncthreads();
    if (tid == 0) g_mask_mode = s_nonbin ? 2 : (s_unal ? 0 : 1);
}

__global__ void prep_mask_kernel(const void* __restrict__ mptr) {
    int b = blockIdx.x;
    int tid = threadIdx.x;
    __shared__ int anyUnmasked;
    if (tid == 0) anyUnmasked = 0;
    __syncthreads();
    int mode = g_mask_mode;
    float vals[NK_ / 256];
    #pragma unroll
    for (int x = 0; x < NK_ / 256; x++) {
        int i = tid + x * 256;
        float m;
        if (mode == 0)      m = ((const unsigned char*)mptr)[b * NK_ + i] ? 1.f : 0.f;
        else if (mode == 1) m = ((const int*)mptr)[b * NK_ + i] ? 1.f : 0.f;
        else                m = (((const float*)mptr)[b * NK_ + i] != 0.f) ? 1.f : 0.f;
        vals[x] = m;
        if (m == 0.f) anyUnmasked = 1;
    }
    __syncthreads();
    #pragma unroll
    for (int x = 0; x < NK_ / 256; x++) {
        int i = tid + x * 256;
        float m = vals[x];
        if (i == 0 && !anyUnmasked) m = 0.f;
        g_maskf[b * NK_ + i] = m;
    }
}

// V transpose per (b,h): g_V[b*NK+key][h*HD+d] -> g_Vt[(b*H+h)*HD+d][key]
__global__ __launch_bounds__(256) void vtrans_kernel() {
    __shared__ float tile[32][33];
    int bh = blockIdx.z, b = bh >> 4, h = bh & 15;
    int k0 = blockIdx.x * 32, d0 = blockIdx.y * 32;
    int tx = threadIdx.x, ty = threadIdx.y;
    #pragma unroll
    for (int i = 0; i < 4; i++)
        tile[ty + i * 8][tx] =
            g_V[(size_t)(b * NK_ + k0 + ty + i * 8) * D_ + h * HD_ + d0 + tx];
    __syncthreads();
    #pragma unroll
    for (int i = 0; i < 4; i++)
        g_Vt[(size_t)(bh * HD_ + d0 + ty + i * 8) * NK_ + k0 + tx] =
            tile[tx][ty + i * 8];
}

#define GA_S 36
#define GB_S 136
#define GEMM_SMEM ((2 * 128 * GA_S + 2 * 32 * GB_S) * 4)

// MODE 0: raw fp32 store.  MODE 1: store tf32-rounded (acc+bias)*outScale.
template <int MODE>
__device__ __forceinline__ void gemm_body(
    const float* __restrict__ X, const float* __restrict__ W,
    const float* __restrict__ bias, float* __restrict__ Y,
    int m0, int n0, float outScale, float* sA, float* sB)
{
    const int K = 1024, N = 1024;
    int tid  = threadIdx.x;
    int lane = tid & 31, warp = tid >> 5;
    int g = lane >> 2, t = lane & 3;
    int wm = (warp >> 2) * 64;
    int wn = (warp & 3) * 32;

    uint32_t sA_u = (uint32_t)__cvta_generic_to_shared(sA);
    uint32_t sB_u = (uint32_t)__cvta_generic_to_shared(sB);

    // ldmatrix A-frag lane geometry
    int arow = (lane & 15);              // row within 16-row tile pair
    int acol = (lane >> 2) & 4;          // +4 floats if lane>=16

    float acc[4][4][4];
    #pragma unroll
    for (int i = 0; i < 4; i++)
        #pragma unroll
        for (int j = 0; j < 4; j++)
            #pragma unroll
            for (int c = 0; c < 4; c++) acc[i][j][c] = 0.f;

    auto issue = [&](int buf, int k0) {
        #pragma unroll
        for (int i = 0; i < 4; i++) {
            int c = tid + i * 256;
            int row = c >> 3, col = (c & 7) * 4;
            cp16(sA_u + (uint32_t)(((buf * 128 + row) * GA_S + col) * 4),
                 X + (size_t)(m0 + row) * K + k0 + col);
        }
        #pragma unroll
        for (int i = 0; i < 4; i++) {
            int c = tid + i * 256;
            int row = c >> 5, col = (c & 31) * 4;
            cp16(sB_u + (uint32_t)(((buf * 32 + row) * GB_S + col) * 4),
                 W + (size_t)(k0 + row) * N + n0 + col);
        }
    };

    issue(0, 0);
    cp_commit();

    #pragma unroll 1
    for (int it = 0; it < 32; it++) {
        int buf = it & 1;
        if (it > 0) __syncthreads();
        if (it < 31) {
            issue(buf ^ 1, (it + 1) * 32);
            cp_commit();
            cp_wait<1>();
        } else {
            cp_wait<0>();
        }
        __syncthreads();

        uint32_t A0_u = sA_u + (uint32_t)(buf * 128 * GA_S * 4);
        const float* B0 = sB + (size_t)buf * 32 * GB_S;

        #pragma unroll
        for (int kt = 0; kt < 4; kt++) {
            uint32_t a[4][4], bfr[4][2];
            #pragma unroll
            for (int mt = 0; mt < 4; mt++) {
                ldsm4(a[mt], A0_u +
                      (uint32_t)(((wm + mt * 16 + arow) * GA_S + kt * 8 + acol) * 4));
                a[mt][0] = f2tf(__uint_as_float(a[mt][0]));
                a[mt][1] = f2tf(__uint_as_float(a[mt][1]));
                a[mt][2] = f2tf(__uint_as_float(a[mt][2]));
                a[mt][3] = f2tf(__uint_as_float(a[mt][3]));
            }
            #pragma unroll
            for (int nt = 0; nt < 4; nt++) {
                const float* bp = &B0[(size_t)(kt * 8 + t) * GB_S + wn + nt * 8 + g];
                bfr[nt][0] = f2tf(bp[0]);
                bfr[nt][1] = f2tf(bp[4 * GB_S]);
            }
            #pragma unroll
            for (int mt = 0; mt < 4; mt++)
                #pragma unroll
                for (int nt = 0; nt < 4; nt++)
                    mma_tf32(acc[mt][nt], a[mt], bfr[nt]);
        }
    }

    #pragma unroll
    for (int mt = 0; mt < 4; mt++) {
        int row = m0 + wm + mt * 16 + g;
        #pragma unroll
        for (int nt = 0; nt < 4; nt++) {
            int col = n0 + wn + nt * 8 + 2 * t;
            float2 bb = *(const float2*)&bias[col];
            float2 o0, o1;
            if (MODE == 1) {
                o0.x = f2tff((acc[mt][nt][0] + bb.x) * outScale);
                o0.y = f2tff((acc[mt][nt][1] + bb.y) * outScale);
                o1.x = f2tff((acc[mt][nt][2] + bb.x) * outScale);
                o1.y = f2tff((acc[mt][nt][3] + bb.y) * outScale);
            } else {
                o0.x = acc[mt][nt][0] + bb.x;
                o0.y = acc[mt][nt][1] + bb.y;
                o1.x = acc[mt][nt][2] + bb.x;
                o1.y = acc[mt][nt][3] + bb.y;
            }
            *(float2*)&Y[(size_t)row * N + col]       = o0;
            *(float2*)&Y[(size_t)(row + 8) * N + col] = o1;
        }
    }
}

__global__ __launch_bounds__(256, 2) void qkv_proj_kernel(
    const float* __restrict__ q, const float* __restrict__ k, const float* __restrict__ v,
    const float* __restrict__ Wq, const float* __restrict__ bq,
    const float* __restrict__ Wk, const float* __restrict__ bk,
    const float* __restrict__ Wv, const float* __restrict__ bv)
{
    extern __shared__ float sm[];
    int y = blockIdx.y;
    const float *X, *W, *bias; float* Y; int m0; float sc;
    if (y < 16)      { X = q; W = Wq; bias = bq; Y = g_Q; m0 = y * 128;        sc = SCALE_; }
    else if (y < 48) { X = k; W = Wk; bias = bk; Y = g_K; m0 = (y - 16) * 128; sc = 1.0f;   }
    else             { X = v; W = Wv; bias = bv; Y = g_V; m0 = (y - 48) * 128; sc = 1.0f;   }
    gemm_body<1>(X, W, bias, Y, m0, blockIdx.x * 128, sc, sm, sm + 2 * 128 * GA_S);
}

__global__ __launch_bounds__(256, 2) void oproj_kernel(
    const float* __restrict__ Wo, const float* __restrict__ bo, float* __restrict__ out)
{
    extern __shared__ float sm[];
    gemm_body<0>(g_ctx, Wo, bo, out, blockIdx.y * 128, blockIdx.x * 128, 1.0f,
                 sm, sm + 2 * 128 * GA_S);
}

#define STK 68
#define SVT 68
#define STP 68
#define ATTN_SMEM ((2 * 64 * STK + 2 * 64 * SVT + 128 * STP) * 4)

__global__ __launch_bounds__(256, 2) void attn_tf32_kernel(
    const float* __restrict__ bias, float* __restrict__ ctx)
{
    extern __shared__ float smem[];
    float* sK  = smem;                               // [2][64][STK]  keys x d
    float* sVt = smem + 2 * 64 * STK;                // [2][64][SVT]  d x keys
    float* sP  = smem + 2 * 64 * STK + 2 * 64 * SVT; // [128][STP]    Q then P

    int tid = threadIdx.x, lane = tid & 31, warp = tid >> 5;
    int g = lane >> 2, t = lane & 3;
    int b = blockIdx.z, h = blockIdx.y, q0 = blockIdx.x * 128;
    int wq = warp * 16;

    const float* Qg  = g_Q + (size_t)(b * NQ_ + q0) * D_ + h * HD_;
    const float* Kg  = g_K + (size_t)b * NK_ * D_ + h * HD_;
    const float* Vtg = g_Vt + (size_t)(b * H_ + h) * HD_ * NK_;
    const float* biasg = bias + (((size_t)b * H_ + h) * NQ_ + q0) * NK_;
    const float* mg = g_maskf + b * NK_;

    uint32_t sK_u  = (uint32_t)__cvta_generic_to_shared(sK);
    uint32_t sVt_u = (uint32_t)__cvta_generic_to_shared(sVt);
    uint32_t sP_u  = (uint32_t)__cvta_generic_to_shared(sP);

    // ldmatrix lane geometry
    int arow = wq + (lane & 15);            // A-frag row (q)
    int acol = (lane >> 2) & 4;             // A-frag col offset (+4 floats if lane>=16)
    int brow = (lane & 7) + ((lane & 16) >> 1);  // B-frag row within 16-row pair
    int bcol = (lane & 8) >> 1;                  // B-frag col offset (+4 if lane&8)

    auto issueKV = [&](int buf, int k0) {
        #pragma unroll
        for (int i = 0; i < 4; i++) {
            int c = tid + i * 256;
            int row = c >> 4, col = (c & 15) * 4;
            cp16(sK_u + (uint32_t)(((buf * 64 + row) * STK + col) * 4),
                 Kg + (size_t)(k0 + row) * D_ + col);
            cp16(sVt_u + (uint32_t)(((buf * 64 + row) * SVT + col) * 4),
                 Vtg + (size_t)row * NK_ + k0 + col);
        }
    };

    issueKV(0, 0);
    cp_commit();

    // Stage Q (already tf32-rounded + pre-scaled) — pure copy
    for (int i = tid; i < 128 * 16; i += 256) {
        int row = i >> 4, dq = (i & 15) * 4;
        *(float4*)&sP[row * STP + dq] = *(const float4*)&Qg[(size_t)row * D_ + dq];
    }
    __syncthreads();

    // Q fragments register-resident via ldmatrix
    uint32_t qf[8][4];
    #pragma unroll
    for (int kt = 0; kt < 8; kt++)
        ldsm4(qf[kt], sP_u + (uint32_t)((arow * STP + kt * 8 + acol) * 4));

    float oacc[8][4];
    #pragma unroll
    for (int nt = 0; nt < 8; nt++)
        #pragma unroll
        for (int c = 0; c < 4; c++) oacc[nt][c] = 0.f;
    float mr0 = -INFINITY, mr1 = -INFINITY, l0 = 0.f, l1 = 0.f;

    #pragma unroll 1
    for (int it = 0; it < NK_ / 64; it++) {
        int buf = it & 1, k0 = it * 64;
        if (it > 0) __syncthreads();
        if (it < NK_ / 64 - 1) {
            issueKV(buf ^ 1, k0 + 64);
            cp_commit();
            cp_wait<1>();
        } else {
            cp_wait<0>();
        }
        __syncthreads();

        uint32_t K0_u = sK_u  + (uint32_t)(buf * 64 * STK * 4);
        uint32_t V0_u = sVt_u + (uint32_t)(buf * 64 * SVT * 4);

        float sacc[8][4];
        #pragma unroll
        for (int nt = 0; nt < 8; nt++)
            #pragma unroll
            for (int c = 0; c < 4; c++) sacc[nt][c] = 0.f;

        // S = Q @ K^T — K B-frags via ldmatrix (rows = keys, natural layout)
        #pragma unroll
        for (int kt = 0; kt < 8; kt++) {
            uint32_t kb[4][4];
            #pragma unroll
            for (int n2 = 0; n2 < 4; n2++)
                ldsm4(kb[n2], K0_u +
                      (uint32_t)(((n2 * 16 + brow) * STK + kt * 8 + bcol) * 4));
            #pragma unroll
            for (int nt = 0; nt < 8; nt++)
                mma_tf32(sacc[nt], qf[kt], &kb[nt >> 1][(nt & 1) * 2]);
        }

        // bias + mask, row maxima
        float rmax0 = -INFINITY, rmax1 = -INFINITY;
        #pragma unroll
        for (int nt = 0; nt < 8; nt++) {
            int kc = k0 + nt * 8 + 2 * t;
            float2 mk  = *(const float2*)&mg[kc];
            float2 b0v = *(const float2*)&biasg[(size_t)(wq + g) * NK_ + kc];
            float2 b1v = *(const float2*)&biasg[(size_t)(wq + g + 8) * NK_ + kc];
            sacc[nt][0] = (mk.x != 0.f) ? -INFINITY : sacc[nt][0] + b0v.x;
            sacc[nt][1] = (mk.y != 0.f) ? -INFINITY : sacc[nt][1] + b0v.y;
            sacc[nt][2] = (mk.x != 0.f) ? -INFINITY : sacc[nt][2] + b1v.x;
            sacc[nt][3] = (mk.y != 0.f) ? -INFINITY : sacc[nt][3] + b1v.y;
            rmax0 = fmaxf(rmax0, fmaxf(sacc[nt][0], sacc[nt][1]));
            rmax1 = fmaxf(rmax1, fmaxf(sacc[nt][2], sacc[nt][3]));
        }
        rmax0 = fmaxf(rmax0, __shfl_xor_sync(0xffffffffu, rmax0, 1));
        rmax0 = fmaxf(rmax0, __shfl_xor_sync(0xffffffffu, rmax0, 2));
        rmax1 = fmaxf(rmax1, __shfl_xor_sync(0xffffffffu, rmax1, 1));
        rmax1 = fmaxf(rmax1, __shfl_xor_sync(0xffffffffu, rmax1, 2));

        float mn0 = fmaxf(mr0, rmax0), mn1 = fmaxf(mr1, rmax1);
        bool dead0 = (mn0 == -INFINITY), dead1 = (mn1 == -INFINITY);
        float al0 = dead0 ? 1.f : __expf(mr0 - mn0);
        float al1 = dead1 ? 1.f : __expf(mr1 - mn1);
        float sum0 = 0.f, sum1 = 0.f;

        #pragma unroll
        for (int nt = 0; nt < 8; nt++) {
            float p00 = dead0 ? 0.f : __expf(sacc[nt][0] - mn0);
            float p01 = dead0 ? 0.f : __expf(sacc[nt][1] - mn0);
            float p10 = dead1 ? 0.f : __expf(sacc[nt][2] - mn1);
            float p11 = dead1 ? 0.f : __expf(sacc[nt][3] - mn1);
            sum0 += p00 + p01;
            sum1 += p10 + p11;
            float2 w0 = make_float2(f2tff(p00), f2tff(p01));
            float2 w1 = make_float2(f2tff(p10), f2tff(p11));
            *(float2*)&sP[(wq + g) * STP + nt * 8 + 2 * t]     = w0;
            *(float2*)&sP[(wq + g + 8) * STP + nt * 8 + 2 * t] = w1;
        }
        sum0 += __shfl_xor_sync(0xffffffffu, sum0, 1);
        sum0 += __shfl_xor_sync(0xffffffffu, sum0, 2);
        sum1 += __shfl_xor_sync(0xffffffffu, sum1, 1);
        sum1 += __shfl_xor_sync(0xffffffffu, sum1, 2);

        mr0 = mn0; mr1 = mn1;
        l0 = l0 * al0 + sum0;
        l1 = l1 * al1 + sum1;
        #pragma unroll
        for (int nt = 0; nt < 8; nt++) {
            oacc[nt][0] *= al0; oacc[nt][1] *= al0;
            oacc[nt][2] *= al1; oacc[nt][3] *= al1;
        }
        __syncwarp();   // P stores visible to this warp's ldmatrix

        // O += P @ V — P A-frags and Vt B-frags via ldmatrix
        #pragma unroll
        for (int kt = 0; kt < 8; kt++) {
            uint32_t pa[4];
            ldsm4(pa, sP_u + (uint32_t)((arow * STP + kt * 8 + acol) * 4));
            uint32_t vb[4][4];
            #pragma unroll
            for (int n2 = 0; n2 < 4; n2++)
                ldsm4(vb[n2], V0_u +
                      (uint32_t)(((n2 * 16 + brow) * SVT + kt * 8 + bcol) * 4));
            #pragma unroll
            for (int nt = 0; nt < 8; nt++)
                mma_tf32(oacc[nt], pa, &vb[nt >> 1][(nt & 1) * 2]);
        }
    }

    float inv0 = 1.f / l0, inv1 = 1.f / l1;
    size_t row0 = (size_t)(b * NQ_ + q0 + wq + g) * D_ + h * HD_;
    size_t row1 = row0 + 8 * D_;
    #pragma unroll
    for (int nt = 0; nt < 8; nt++) {
        int col = nt * 8 + 2 * t;
        float2 o0 = make_float2(oacc[nt][0] * inv0, oacc[nt][1] * inv0);
        float2 o1 = make_float2(oacc[nt][2] * inv1, oacc[nt][3] * inv1);
        *(float2*)&ctx[row0 + col] = o0;
        *(float2*)&ctx[row1 + col] = o1;
    }
}

extern "C" void kernel_launch(void* const* d_in, const int* in_sizes, int n_in,
                              void* d_out, int out_size)
{
    const float* q  = (const float*)d_in[0];
    const float* k  = (const float*)d_in[1];
    const float* v  = (const float*)d_in[2];
    const float* ab = (const float*)d_in[3];
    const void*  mk = d_in[4];
    const float* Wq = (const float*)d_in[5];
    const float* bq = (const float*)d_in[6];
    const float* Wk = (const float*)d_in[7];
    const float* bk = (const float*)d_in[8];
    const float* Wv = (const float*)d_in[9];
    const float* bv = (const float*)d_in[10];
    const float* Wo = (const float*)d_in[11];
    const float* bo = (const float*)d_in[12];
    float* out = (float*)d_out;

    static int smem_set = 0;
    if (!smem_set) {
        cudaFuncSetAttribute(qkv_proj_kernel,
                             cudaFuncAttributeMaxDynamicSharedMemorySize, GEMM_SMEM);
        cudaFuncSetAttribute(oproj_kernel,
                             cudaFuncAttributeMaxDynamicSharedMemorySize, GEMM_SMEM);
        cudaFuncSetAttribute(attn_tf32_kernel,
                             cudaFuncAttributeMaxDynamicSharedMemorySize, ATTN_SMEM);
        smem_set = 1;
    }

    float* gctx;
    cudaGetSymbolAddress((void**)&gctx, g_ctx);

    detect_mask_kernel<<<1, 256>>>((const unsigned char*)mk);
    prep_mask_kernel<<<B_, 256>>>(mk);

    qkv_proj_kernel<<<dim3(8, 80), 256, GEMM_SMEM>>>(q, k, v, Wq, bq, Wk, bk, Wv, bv);

    vtrans_kernel<<<dim3(NK_ / 32, HD_ / 32, B_ * H_), dim3(32, 8)>>>();

    attn_tf32_kernel<<<dim3(NQ_ / 128, H_, B_), 256, ATTN_SMEM>>>(ab, gctx);

    oproj_kernel<<<dim3(8, 16), 256, GEMM_SMEM>>>(Wo, bo, out);
}

// round 7
// speedup vs baseline: 3.5914x; 1.0134x over previous
#include <cuda_runtime.h>
#include <math.h>
#include <stdint.h>

#define B_     2
#define NQ_    1024
#define NK_    2048
#define D_     1024
#define H_     16
#define HD_    64
#define SCALE_ 0.125f

__device__ float g_Q[(size_t)B_ * NQ_ * D_];    // pre-scaled + tf32-rounded
__device__ float g_K[(size_t)B_ * NK_ * D_];    // tf32-rounded
__device__ float g_V[(size_t)B_ * NK_ * D_];    // tf32-rounded
__device__ float g_Vt[(size_t)B_ * H_ * HD_ * NK_];  // V transposed per (b,h): [d][key]
__device__ float g_ctx[(size_t)B_ * NQ_ * D_];  // tf32-rounded (attn epilogue)
__device__ float g_Wr[(size_t)4 * D_ * D_];     // tf32-rounded Wq|Wk|Wv|Wo
__device__ float g_maskf[B_ * NK_];
__device__ int   g_mask_mode;

__device__ __forceinline__ uint32_t f2tf(float x) {
    uint32_t u; asm("cvt.rna.tf32.f32 %0, %1;" : "=r"(u) : "f"(x)); return u;
}
__device__ __forceinline__ float f2tff(float x) { return __uint_as_float(f2tf(x)); }

__device__ __forceinline__ void mma_tf32(float* d, const uint32_t* a, const uint32_t* b) {
    asm volatile(
        "mma.sync.aligned.m16n8k8.row.col.f32.tf32.tf32.f32 "
        "{%0,%1,%2,%3}, {%4,%5,%6,%7}, {%8,%9}, {%0,%1,%2,%3};"
        : "+f"(d[0]), "+f"(d[1]), "+f"(d[2]), "+f"(d[3])
        : "r"(a[0]), "r"(a[1]), "r"(a[2]), "r"(a[3]),
          "r"(b[0]), "r"(b[1]));
}

__device__ __forceinline__ void ldsm4(uint32_t* r, uint32_t addr) {
    asm volatile("ldmatrix.sync.aligned.m8n8.x4.shared.b16 {%0,%1,%2,%3}, [%4];"
                 : "=r"(r[0]), "=r"(r[1]), "=r"(r[2]), "=r"(r[3]) : "r"(addr));
}

__device__ __forceinline__ void cp16(uint32_t dst, const void* src) {
    asm volatile("cp.async.cg.shared.global [%0], [%1], 16;" :: "r"(dst), "l"(src));
}
__device__ __forceinline__ void cp_commit() { asm volatile("cp.async.commit_group;"); }
template <int N> __device__ __forceinline__ void cp_wait() {
    asm volatile("cp.async.wait_group %0;" :: "n"(N));
}

__global__ void detect_mask_kernel(const unsigned char* __restrict__ p) {
    __shared__ int s_nonbin, s_unal;
    int tid = threadIdx.x;
    if (tid == 0) { s_nonbin = 0; s_unal = 0; }
    __syncthreads();
    for (int i = tid; i < B_ * NK_; i += 256) {
        unsigned char v = p[i];
        if (v > 1) s_nonbin = 1;
        else if (v == 1 && (i & 3)) s_unal = 1;
    }
    __syncthreads();
    if (tid == 0) g_mask_mode = s_nonbin ? 2 : (s_unal ? 0 : 1);
}

__global__ void prep_mask_kernel(const void* __restrict__ mptr) {
    int b = blockIdx.x;
    int tid = threadIdx.x;
    __shared__ int anyUnmasked;
    if (tid == 0) anyUnmasked = 0;
    __syncthreads();
    int mode = g_mask_mode;
    float vals[NK_ / 256];
    #pragma unroll
    for (int x = 0; x < NK_ / 256; x++) {
        int i = tid + x * 256;
        float m;
        if (mode == 0)      m = ((const unsigned char*)mptr)[b * NK_ + i] ? 1.f : 0.f;
        else if (mode == 1) m = ((const int*)mptr)[b * NK_ + i] ? 1.f : 0.f;
        else                m = (((const float*)mptr)[b * NK_ + i] != 0.f) ? 1.f : 0.f;
        vals[x] = m;
        if (m == 0.f) anyUnmasked = 1;
    }
    __syncthreads();
    #pragma unroll
    for (int x = 0; x < NK_ / 256; x++) {
        int i = tid + x * 256;
        float m = vals[x];
        if (i == 0 && !anyUnmasked) m = 0.f;
        g_maskf[b * NK_ + i] = m;
    }
}

// Round 4 weight matrices to tf32 once (values identical to per-load rounding).
__global__ __launch_bounds__(256) void round_w_kernel(
    const float* __restrict__ w0, const float* __restrict__ w1,
    const float* __restrict__ w2, const float* __restrict__ w3)
{
    int which = blockIdx.y;
    const float* s = (which == 0) ? w0 : (which == 1) ? w1 : (which == 2) ? w2 : w3;
    float* d = g_Wr + (size_t)which * D_ * D_;
    for (int i = blockIdx.x * blockDim.x + threadIdx.x;
         i < (D_ * D_) / 4; i += gridDim.x * blockDim.x) {
        float4 v = ((const float4*)s)[i];
        v.x = f2tff(v.x); v.y = f2tff(v.y); v.z = f2tff(v.z); v.w = f2tff(v.w);
        ((float4*)d)[i] = v;
    }
}

// V transpose per (b,h): g_V[b*NK+key][h*HD+d] -> g_Vt[(b*H+h)*HD+d][key]
__global__ __launch_bounds__(256) void vtrans_kernel() {
    __shared__ float tile[32][33];
    int bh = blockIdx.z, b = bh >> 4, h = bh & 15;
    int k0 = blockIdx.x * 32, d0 = blockIdx.y * 32;
    int tx = threadIdx.x, ty = threadIdx.y;
    #pragma unroll
    for (int i = 0; i < 4; i++)
        tile[ty + i * 8][tx] =
            g_V[(size_t)(b * NK_ + k0 + ty + i * 8) * D_ + h * HD_ + d0 + tx];
    __syncthreads();
    #pragma unroll
    for (int i = 0; i < 4; i++)
        g_Vt[(size_t)(bh * HD_ + d0 + ty + i * 8) * NK_ + k0 + tx] =
            tile[tx][ty + i * 8];
}

#define GA_S 36
#define GB_S 136
#define GSTG 3
#define GEMM_SMEM ((GSTG * 128 * GA_S + GSTG * 32 * GB_S) * 4)

// MODE 0: raw fp32 store.  MODE 1: store tf32-rounded (acc+bias)*outScale.
// ACVT 1: A needs tf32 rounding after ldmatrix; 0: A already rounded.
// B (weights) always pre-rounded.
template <int MODE, int ACVT>
__device__ __forceinline__ void gemm_body(
    const float* __restrict__ X, const float* __restrict__ W,
    const float* __restrict__ bias, float* __restrict__ Y,
    int m0, int n0, float outScale, float* sA, float* sB)
{
    const int K = 1024, N = 1024;
    int tid  = threadIdx.x;
    int lane = tid & 31, warp = tid >> 5;
    int g = lane >> 2, t = lane & 3;
    int wm = (warp >> 2) * 64;
    int wn = (warp & 3) * 32;

    uint32_t sA_u = (uint32_t)__cvta_generic_to_shared(sA);
    uint32_t sB_u = (uint32_t)__cvta_generic_to_shared(sB);

    int arow = (lane & 15);
    int acol = (lane >> 2) & 4;

    float acc[4][4][4];
    #pragma unroll
    for (int i = 0; i < 4; i++)
        #pragma unroll
        for (int j = 0; j < 4; j++)
            #pragma unroll
            for (int c = 0; c < 4; c++) acc[i][j][c] = 0.f;

    auto issue = [&](int buf, int k0) {
        #pragma unroll
        for (int i = 0; i < 4; i++) {
            int c = tid + i * 256;
            int row = c >> 3, col = (c & 7) * 4;
            cp16(sA_u + (uint32_t)(((buf * 128 + row) * GA_S + col) * 4),
                 X + (size_t)(m0 + row) * K + k0 + col);
        }
        #pragma unroll
        for (int i = 0; i < 4; i++) {
            int c = tid + i * 256;
            int row = c >> 5, col = (c & 31) * 4;
            cp16(sB_u + (uint32_t)(((buf * 32 + row) * GB_S + col) * 4),
                 W + (size_t)(k0 + row) * N + n0 + col);
        }
    };

    issue(0, 0);  cp_commit();
    issue(1, 32); cp_commit();

    #pragma unroll 1
    for (int it = 0; it < 32; it++) {
        int buf = it % GSTG;
        if (it < 31) cp_wait<1>(); else cp_wait<0>();
        __syncthreads();           // tile `it` ready; all warps done with tile it-1
        if (it + 2 < 32) {         // prefetch distance 2 into the just-freed slot
            issue((it + 2) % GSTG, (it + 2) * 32);
            cp_commit();
        }

        uint32_t A0_u = sA_u + (uint32_t)(buf * 128 * GA_S * 4);
        const float* B0 = sB + (size_t)buf * 32 * GB_S;

        #pragma unroll
        for (int kt = 0; kt < 4; kt++) {
            uint32_t a[4][4], bfr[4][2];
            #pragma unroll
            for (int mt = 0; mt < 4; mt++) {
                ldsm4(a[mt], A0_u +
                      (uint32_t)(((wm + mt * 16 + arow) * GA_S + kt * 8 + acol) * 4));
                if (ACVT) {
                    a[mt][0] = f2tf(__uint_as_float(a[mt][0]));
                    a[mt][1] = f2tf(__uint_as_float(a[mt][1]));
                    a[mt][2] = f2tf(__uint_as_float(a[mt][2]));
                    a[mt][3] = f2tf(__uint_as_float(a[mt][3]));
                }
            }
            #pragma unroll
            for (int nt = 0; nt < 4; nt++) {
                const float* bp = &B0[(size_t)(kt * 8 + t) * GB_S + wn + nt * 8 + g];
                bfr[nt][0] = __float_as_uint(bp[0]);        // pre-rounded weights
                bfr[nt][1] = __float_as_uint(bp[4 * GB_S]);
            }
            #pragma unroll
            for (int mt = 0; mt < 4; mt++)
                #pragma unroll
                for (int nt = 0; nt < 4; nt++)
                    mma_tf32(acc[mt][nt], a[mt], bfr[nt]);
        }
    }

    #pragma unroll
    for (int mt = 0; mt < 4; mt++) {
        int row = m0 + wm + mt * 16 + g;
        #pragma unroll
        for (int nt = 0; nt < 4; nt++) {
            int col = n0 + wn + nt * 8 + 2 * t;
            float2 bb = *(const float2*)&bias[col];
            float2 o0, o1;
            if (MODE == 1) {
                o0.x = f2tff((acc[mt][nt][0] + bb.x) * outScale);
                o0.y = f2tff((acc[mt][nt][1] + bb.y) * outScale);
                o1.x = f2tff((acc[mt][nt][2] + bb.x) * outScale);
                o1.y = f2tff((acc[mt][nt][3] + bb.y) * outScale);
            } else {
                o0.x = acc[mt][nt][0] + bb.x;
                o0.y = acc[mt][nt][1] + bb.y;
                o1.x = acc[mt][nt][2] + bb.x;
                o1.y = acc[mt][nt][3] + bb.y;
            }
            *(float2*)&Y[(size_t)row * N + col]       = o0;
            *(float2*)&Y[(size_t)(row + 8) * N + col] = o1;
        }
    }
}

__global__ __launch_bounds__(256, 2) void qkv_proj_kernel(
    const float* __restrict__ q, const float* __restrict__ k, const float* __restrict__ v,
    const float* __restrict__ bq, const float* __restrict__ bk,
    const float* __restrict__ bv)
{
    extern __shared__ float sm[];
    int y = blockIdx.y;
    const float *X, *W, *bias; float* Y; int m0; float sc;
    if (y < 16)      { X = q; W = g_Wr;              bias = bq; Y = g_Q; m0 = y * 128;        sc = SCALE_; }
    else if (y < 48) { X = k; W = g_Wr + 1 * D_ * D_; bias = bk; Y = g_K; m0 = (y - 16) * 128; sc = 1.0f;   }
    else             { X = v; W = g_Wr + 2 * D_ * D_; bias = bv; Y = g_V; m0 = (y - 48) * 128; sc = 1.0f;   }
    gemm_body<1, 1>(X, W, bias, Y, m0, blockIdx.x * 128, sc, sm, sm + GSTG * 128 * GA_S);
}

__global__ __launch_bounds__(256, 2) void oproj_kernel(
    const float* __restrict__ bo, float* __restrict__ out)
{
    extern __shared__ float sm[];
    gemm_body<0, 0>(g_ctx, g_Wr + 3 * D_ * D_, bo, out,
                    blockIdx.y * 128, blockIdx.x * 128, 1.0f,
                    sm, sm + GSTG * 128 * GA_S);
}

#define STK 68
#define SVT 68
#define STP 68
#define ATTN_SMEM ((2 * 64 * STK + 2 * 64 * SVT + 128 * STP) * 4)

__global__ __launch_bounds__(256, 2) void attn_tf32_kernel(
    const float* __restrict__ bias, float* __restrict__ ctx)
{
    extern __shared__ float smem[];
    float* sK  = smem;                               // [2][64][STK]  keys x d
    float* sVt = smem + 2 * 64 * STK;                // [2][64][SVT]  d x keys
    float* sP  = smem + 2 * 64 * STK + 2 * 64 * SVT; // [128][STP]    Q then P

    int tid = threadIdx.x, lane = tid & 31, warp = tid >> 5;
    int g = lane >> 2, t = lane & 3;
    int b = blockIdx.z, h = blockIdx.y, q0 = blockIdx.x * 128;
    int wq = warp * 16;

    const float* Qg  = g_Q + (size_t)(b * NQ_ + q0) * D_ + h * HD_;
    const float* Kg  = g_K + (size_t)b * NK_ * D_ + h * HD_;
    const float* Vtg = g_Vt + (size_t)(b * H_ + h) * HD_ * NK_;
    const float* biasg = bias + (((size_t)b * H_ + h) * NQ_ + q0) * NK_;
    const float* mg = g_maskf + b * NK_;

    uint32_t sK_u  = (uint32_t)__cvta_generic_to_shared(sK);
    uint32_t sVt_u = (uint32_t)__cvta_generic_to_shared(sVt);
    uint32_t sP_u  = (uint32_t)__cvta_generic_to_shared(sP);

    int arow = wq + (lane & 15);
    int acol = (lane >> 2) & 4;
    int brow = (lane & 7) + ((lane & 16) >> 1);
    int bcol = (lane & 8) >> 1;

    auto issueKV = [&](int buf, int k0) {
        #pragma unroll
        for (int i = 0; i < 4; i++) {
            int c = tid + i * 256;
            int row = c >> 4, col = (c & 15) * 4;
            cp16(sK_u + (uint32_t)(((buf * 64 + row) * STK + col) * 4),
                 Kg + (size_t)(k0 + row) * D_ + col);
            cp16(sVt_u + (uint32_t)(((buf * 64 + row) * SVT + col) * 4),
                 Vtg + (size_t)row * NK_ + k0 + col);
        }
    };

    issueKV(0, 0);
    cp_commit();

    for (int i = tid; i < 128 * 16; i += 256) {
        int row = i >> 4, dq = (i & 15) * 4;
        *(float4*)&sP[row * STP + dq] = *(const float4*)&Qg[(size_t)row * D_ + dq];
    }
    __syncthreads();

    uint32_t qf[8][4];
    #pragma unroll
    for (int kt = 0; kt < 8; kt++)
        ldsm4(qf[kt], sP_u + (uint32_t)((arow * STP + kt * 8 + acol) * 4));

    float oacc[8][4];
    #pragma unroll
    for (int nt = 0; nt < 8; nt++)
        #pragma unroll
        for (int c = 0; c < 4; c++) oacc[nt][c] = 0.f;
    float mr0 = -INFINITY, mr1 = -INFINITY, l0 = 0.f, l1 = 0.f;

    #pragma unroll 1
    for (int it = 0; it < NK_ / 64; it++) {
        int buf = it & 1, k0 = it * 64;
        cp_wait<0>();
        __syncthreads();           // tile `it` ready; all warps done with it-1
        if (it < NK_ / 64 - 1) {   // prefetch into the just-freed slot
            issueKV(buf ^ 1, k0 + 64);
            cp_commit();
        }

        uint32_t K0_u = sK_u  + (uint32_t)(buf * 64 * STK * 4);
        uint32_t V0_u = sVt_u + (uint32_t)(buf * 64 * SVT * 4);

        float sacc[8][4];
        #pragma unroll
        for (int nt = 0; nt < 8; nt++)
            #pragma unroll
            for (int c = 0; c < 4; c++) sacc[nt][c] = 0.f;

        #pragma unroll
        for (int kt = 0; kt < 8; kt++) {
            uint32_t kb[4][4];
            #pragma unroll
            for (int n2 = 0; n2 < 4; n2++)
                ldsm4(kb[n2], K0_u +
                      (uint32_t)(((n2 * 16 + brow) * STK + kt * 8 + bcol) * 4));
            #pragma unroll
            for (int nt = 0; nt < 8; nt++)
                mma_tf32(sacc[nt], qf[kt], &kb[nt >> 1][(nt & 1) * 2]);
        }

        float rmax0 = -INFINITY, rmax1 = -INFINITY;
        #pragma unroll
        for (int nt = 0; nt < 8; nt++) {
            int kc = k0 + nt * 8 + 2 * t;
            float2 mk  = *(const float2*)&mg[kc];
            float2 b0v = *(const float2*)&biasg[(size_t)(wq + g) * NK_ + kc];
            float2 b1v = *(const float2*)&biasg[(size_t)(wq + g + 8) * NK_ + kc];
            sacc[nt][0] = (mk.x != 0.f) ? -INFINITY : sacc[nt][0] + b0v.x;
            sacc[nt][1] = (mk.y != 0.f) ? -INFINITY : sacc[nt][1] + b0v.y;
            sacc[nt][2] = (mk.x != 0.f) ? -INFINITY : sacc[nt][2] + b1v.x;
            sacc[nt][3] = (mk.y != 0.f) ? -INFINITY : sacc[nt][3] + b1v.y;
            rmax0 = fmaxf(rmax0, fmaxf(sacc[nt][0], sacc[nt][1]));
            rmax1 = fmaxf(rmax1, fmaxf(sacc[nt][2], sacc[nt][3]));
        }
        rmax0 = fmaxf(rmax0, __shfl_xor_sync(0xffffffffu, rmax0, 1));
        rmax0 = fmaxf(rmax0, __shfl_xor_sync(0xffffffffu, rmax0, 2));
        rmax1 = fmaxf(rmax1, __shfl_xor_sync(0xffffffffu, rmax1, 1));
        rmax1 = fmaxf(rmax1, __shfl_xor_sync(0xffffffffu, rmax1, 2));

        float mn0 = fmaxf(mr0, rmax0), mn1 = fmaxf(mr1, rmax1);
        bool dead0 = (mn0 == -INFINITY), dead1 = (mn1 == -INFINITY);
        float al0 = dead0 ? 1.f : __expf(mr0 - mn0);
        float al1 = dead1 ? 1.f : __expf(mr1 - mn1);
        float sum0 = 0.f, sum1 = 0.f;

        #pragma unroll
        for (int nt = 0; nt < 8; nt++) {
            float p00 = dead0 ? 0.f : __expf(sacc[nt][0] - mn0);
            float p01 = dead0 ? 0.f : __expf(sacc[nt][1] - mn0);
            float p10 = dead1 ? 0.f : __expf(sacc[nt][2] - mn1);
            float p11 = dead1 ? 0.f : __expf(sacc[nt][3] - mn1);
            sum0 += p00 + p01;
            sum1 += p10 + p11;
            float2 w0 = make_float2(f2tff(p00), f2tff(p01));
            float2 w1 = make_float2(f2tff(p10), f2tff(p11));
            *(float2*)&sP[(wq + g) * STP + nt * 8 + 2 * t]     = w0;
            *(float2*)&sP[(wq + g + 8) * STP + nt * 8 + 2 * t] = w1;
        }
        sum0 += __shfl_xor_sync(0xffffffffu, sum0, 1);
        sum0 += __shfl_xor_sync(0xffffffffu, sum0, 2);
        sum1 += __shfl_xor_sync(0xffffffffu, sum1, 1);
        sum1 += __shfl_xor_sync(0xffffffffu, sum1, 2);

        mr0 = mn0; mr1 = mn1;
        l0 = l0 * al0 + sum0;
        l1 = l1 * al1 + sum1;
        #pragma unroll
        for (int nt = 0; nt < 8; nt++) {
            oacc[nt][0] *= al0; oacc[nt][1] *= al0;
            oacc[nt][2] *= al1; oacc[nt][3] *= al1;
        }
        __syncwarp();   // P rows are warp-private; warp-level visibility suffices

        #pragma unroll
        for (int kt = 0; kt < 8; kt++) {
            uint32_t pa[4];
            ldsm4(pa, sP_u + (uint32_t)((arow * STP + kt * 8 + acol) * 4));
            uint32_t vb[4][4];
            #pragma unroll
            for (int n2 = 0; n2 < 4; n2++)
                ldsm4(vb[n2], V0_u +
                      (uint32_t)(((n2 * 16 + brow) * SVT + kt * 8 + bcol) * 4));
            #pragma unroll
            for (int nt = 0; nt < 8; nt++)
                mma_tf32(oacc[nt], pa, &vb[nt >> 1][(nt & 1) * 2]);
        }
    }

    // Normalize + tf32-round (feeds oproj A directly) and store
    float inv0 = 1.f / l0, inv1 = 1.f / l1;
    size_t row0 = (size_t)(b * NQ_ + q0 + wq + g) * D_ + h * HD_;
    size_t row1 = row0 + 8 * D_;
    #pragma unroll
    for (int nt = 0; nt < 8; nt++) {
        int col = nt * 8 + 2 * t;
        float2 o0 = make_float2(f2tff(oacc[nt][0] * inv0), f2tff(oacc[nt][1] * inv0));
        float2 o1 = make_float2(f2tff(oacc[nt][2] * inv1), f2tff(oacc[nt][3] * inv1));
        *(float2*)&ctx[row0 + col] = o0;
        *(float2*)&ctx[row1 + col] = o1;
    }
}

extern "C" void kernel_launch(void* const* d_in, const int* in_sizes, int n_in,
                              void* d_out, int out_size)
{
    const float* q  = (const float*)d_in[0];
    const float* k  = (const float*)d_in[1];
    const float* v  = (const float*)d_in[2];
    const float* ab = (const float*)d_in[3];
    const void*  mk = d_in[4];
    const float* Wq = (const float*)d_in[5];
    const float* bq = (const float*)d_in[6];
    const float* Wk = (const float*)d_in[7];
    const float* bk = (const float*)d_in[8];
    const float* Wv = (const float*)d_in[9];
    const float* bv = (const float*)d_in[10];
    const float* Wo = (const float*)d_in[11];
    const float* bo = (const float*)d_in[12];
    float* out = (float*)d_out;

    static int smem_set = 0;
    if (!smem_set) {
        cudaFuncSetAttribute(qkv_proj_kernel,
                             cudaFuncAttributeMaxDynamicSharedMemorySize, GEMM_SMEM);
        cudaFuncSetAttribute(oproj_kernel,
                             cudaFuncAttributeMaxDynamicSharedMemorySize, GEMM_SMEM);
        cudaFuncSetAttribute(attn_tf32_kernel,
                             cudaFuncAttributeMaxDynamicSharedMemorySize, ATTN_SMEM);
        smem_set = 1;
    }

    float* gctx;
    cudaGetSymbolAddress((void**)&gctx, g_ctx);

    detect_mask_kernel<<<1, 256>>>((const unsigned char*)mk);
    prep_mask_kernel<<<B_, 256>>>(mk);
    round_w_kernel<<<dim3(128, 4), 256>>>(Wq, Wk, Wv, Wo);

    qkv_proj_kernel<<<dim3(8, 80), 256, GEMM_SMEM>>>(q, k, v, bq, bk, bv);

    vtrans_kernel<<<dim3(NK_ / 32, HD_ / 32, B_ * H_), dim3(32, 8)>>>();

    attn_tf32_kernel<<<dim3(NQ_ / 128, H_, B_), 256, ATTN_SMEM>>>(ab, gctx);

    oproj_kernel<<<dim3(8, 16), 256, GEMM_SMEM>>>(bo, out);
}

// round 8
// speedup vs baseline: 3.6527x; 1.0171x over previous
#include <cuda_runtime.h>
#include <math.h>
#include <stdint.h>

#define B_     2
#define NQ_    1024
#define NK_    2048
#define D_     1024
#define H_     16
#define HD_    64
#define SCALE_ 0.125f

__device__ float g_Q[(size_t)B_ * NQ_ * D_];    // pre-scaled + tf32-rounded
__device__ float g_K[(size_t)B_ * NK_ * D_];    // tf32-rounded
__device__ float g_V[(size_t)B_ * NK_ * D_];    // tf32-rounded
__device__ float g_Vt[(size_t)B_ * H_ * HD_ * NK_];  // V transposed per (b,h): [d][key]
__device__ float g_ctx[(size_t)B_ * NQ_ * D_];  // tf32-rounded (attn epilogue)
__device__ float g_Wr[(size_t)4 * D_ * D_];     // tf32-rounded Wq|Wk|Wv|Wo
__device__ float g_Xr[(size_t)10240 * D_];      // tf32-rounded inputs q|k|v
__device__ float g_maskf[B_ * NK_];
__device__ int   g_mask_mode;

__device__ __forceinline__ uint32_t f2tf(float x) {
    uint32_t u; asm("cvt.rna.tf32.f32 %0, %1;" : "=r"(u) : "f"(x)); return u;
}
__device__ __forceinline__ float f2tff(float x) { return __uint_as_float(f2tf(x)); }

__device__ __forceinline__ void mma_tf32(float* d, const uint32_t* a, const uint32_t* b) {
    asm volatile(
        "mma.sync.aligned.m16n8k8.row.col.f32.tf32.tf32.f32 "
        "{%0,%1,%2,%3}, {%4,%5,%6,%7}, {%8,%9}, {%0,%1,%2,%3};"
        : "+f"(d[0]), "+f"(d[1]), "+f"(d[2]), "+f"(d[3])
        : "r"(a[0]), "r"(a[1]), "r"(a[2]), "r"(a[3]),
          "r"(b[0]), "r"(b[1]));
}

__device__ __forceinline__ void ldsm4(uint32_t* r, uint32_t addr) {
    asm volatile("ldmatrix.sync.aligned.m8n8.x4.shared.b16 {%0,%1,%2,%3}, [%4];"
                 : "=r"(r[0]), "=r"(r[1]), "=r"(r[2]), "=r"(r[3]) : "r"(addr));
}

__device__ __forceinline__ void cp16(uint32_t dst, const void* src) {
    asm volatile("cp.async.cg.shared.global [%0], [%1], 16;" :: "r"(dst), "l"(src));
}
__device__ __forceinline__ void cp_commit() { asm volatile("cp.async.commit_group;"); }
template <int N> __device__ __forceinline__ void cp_wait() {
    asm volatile("cp.async.wait_group %0;" :: "n"(N));
}

__global__ void detect_mask_kernel(const unsigned char* __restrict__ p) {
    __shared__ int s_nonbin, s_unal;
    int tid = threadIdx.x;
    if (tid == 0) { s_nonbin = 0; s_unal = 0; }
    __syncthreads();
    for (int i = tid; i < B_ * NK_; i += 256) {
        unsigned char v = p[i];
        if (v > 1) s_nonbin = 1;
        else if (v == 1 && (i & 3)) s_unal = 1;
    }
    __syncthreads();
    if (tid == 0) g_mask_mode = s_nonbin ? 2 : (s_unal ? 0 : 1);
}

__global__ void prep_mask_kernel(const void* __restrict__ mptr) {
    int b = blockIdx.x;
    int tid = threadIdx.x;
    __shared__ int anyUnmasked;
    if (tid == 0) anyUnmasked = 0;
    __syncthreads();
    int mode = g_mask_mode;
    float vals[NK_ / 256];
    #pragma unroll
    for (int x = 0; x < NK_ / 256; x++) {
        int i = tid + x * 256;
        float m;
        if (mode == 0)      m = ((const unsigned char*)mptr)[b * NK_ + i] ? 1.f : 0.f;
        else if (mode == 1) m = ((const int*)mptr)[b * NK_ + i] ? 1.f : 0.f;
        else                m = (((const float*)mptr)[b * NK_ + i] != 0.f) ? 1.f : 0.f;
        vals[x] = m;
        if (m == 0.f) anyUnmasked = 1;
    }
    __syncthreads();
    #pragma unroll
    for (int x = 0; x < NK_ / 256; x++) {
        int i = tid + x * 256;
        float m = vals[x];
        if (i == 0 && !anyUnmasked) m = 0.f;
        g_maskf[b * NK_ + i] = m;
    }
}

// Round weight matrices to tf32 once (values identical to per-load rounding).
__global__ __launch_bounds__(256) void round_w_kernel(
    const float* __restrict__ w0, const float* __restrict__ w1,
    const float* __restrict__ w2, const float* __restrict__ w3)
{
    int which = blockIdx.y;
    const float* s = (which == 0) ? w0 : (which == 1) ? w1 : (which == 2) ? w2 : w3;
    float* d = g_Wr + (size_t)which * D_ * D_;
    for (int i = blockIdx.x * blockDim.x + threadIdx.x;
         i < (D_ * D_) / 4; i += gridDim.x * blockDim.x) {
        float4 v = ((const float4*)s)[i];
        v.x = f2tff(v.x); v.y = f2tff(v.y); v.z = f2tff(v.z); v.w = f2tff(v.w);
        ((float4*)d)[i] = v;
    }
}

// Round raw q/k/v inputs to tf32 once (so GEMM A-side needs no cvt).
__global__ __launch_bounds__(256) void round_x_kernel(
    const float* __restrict__ q, const float* __restrict__ k, const float* __restrict__ v)
{
    int which = blockIdx.y;
    const float* s; float* d; int n;
    if (which == 0)      { s = q; d = g_Xr;                     n = B_ * NQ_ * D_; }
    else if (which == 1) { s = k; d = g_Xr + (size_t)2048 * D_; n = B_ * NK_ * D_; }
    else                 { s = v; d = g_Xr + (size_t)6144 * D_; n = B_ * NK_ * D_; }
    for (int i = blockIdx.x * blockDim.x + threadIdx.x;
         i < n / 4; i += gridDim.x * blockDim.x) {
        float4 x = ((const float4*)s)[i];
        x.x = f2tff(x.x); x.y = f2tff(x.y); x.z = f2tff(x.z); x.w = f2tff(x.w);
        ((float4*)d)[i] = x;
    }
}

// V transpose per (b,h): g_V[b*NK+key][h*HD+d] -> g_Vt[(b*H+h)*HD+d][key]
__global__ __launch_bounds__(256) void vtrans_kernel() {
    __shared__ float tile[32][33];
    int bh = blockIdx.z, b = bh >> 4, h = bh & 15;
    int k0 = blockIdx.x * 32, d0 = blockIdx.y * 32;
    int tx = threadIdx.x, ty = threadIdx.y;
    #pragma unroll
    for (int i = 0; i < 4; i++)
        tile[ty + i * 8][tx] =
            g_V[(size_t)(b * NK_ + k0 + ty + i * 8) * D_ + h * HD_ + d0 + tx];
    __syncthreads();
    #pragma unroll
    for (int i = 0; i < 4; i++)
        g_Vt[(size_t)(bh * HD_ + d0 + ty + i * 8) * NK_ + k0 + tx] =
            tile[tx][ty + i * 8];
}

#define GA_S 36
#define GB_S 136
#define GSTG 3
#define GEMM_SMEM128 ((GSTG * 128 * GA_S + GSTG * 32 * GB_S) * 4)
#define GEMM_SMEM64  ((GSTG * 64  * GA_S + GSTG * 32 * GB_S) * 4)

// MODE 0: raw fp32 store.  MODE 1: store tf32-rounded (acc+bias)*outScale.
// All operands (X, W) are pre-rounded tf32: no cvt in the mainloop.
// MROWS: CTA tile M (128 or 64).
template <int MODE, int MROWS>
__device__ __forceinline__ void gemm_body(
    const float* __restrict__ X, const float* __restrict__ W,
    const float* __restrict__ bias, float* __restrict__ Y,
    int m0, int n0, float outScale, float* sA, float* sB)
{
    const int K = 1024, N = 1024;
    const int MT = MROWS / 32;          // 16-row tiles per warp
    int tid  = threadIdx.x;
    int lane = tid & 31, warp = tid >> 5;
    int g = lane >> 2, t = lane & 3;
    int wm = (warp >> 2) * (MROWS / 2);
    int wn = (warp & 3) * 32;

    uint32_t sA_u = (uint32_t)__cvta_generic_to_shared(sA);
    uint32_t sB_u = (uint32_t)__cvta_generic_to_shared(sB);

    int arow = (lane & 15);
    int acol = (lane >> 2) & 4;
    uint32_t a_base = (uint32_t)(((wm + arow) * GA_S + acol) * 4);

    float acc[MT][4][4];
    #pragma unroll
    for (int i = 0; i < MT; i++)
        #pragma unroll
        for (int j = 0; j < 4; j++)
            #pragma unroll
            for (int c = 0; c < 4; c++) acc[i][j][c] = 0.f;

    auto issue = [&](int buf, int k0) {
        #pragma unroll
        for (int i = 0; i < MT; i++) {
            int c = tid + i * 256;
            int row = c >> 3, col = (c & 7) * 4;
            cp16(sA_u + (uint32_t)(((buf * MROWS + row) * GA_S + col) * 4),
                 X + (size_t)(m0 + row) * K + k0 + col);
        }
        #pragma unroll
        for (int i = 0; i < 4; i++) {
            int c = tid + i * 256;
            int row = c >> 5, col = (c & 31) * 4;
            cp16(sB_u + (uint32_t)(((buf * 32 + row) * GB_S + col) * 4),
                 W + (size_t)(k0 + row) * N + n0 + col);
        }
    };

    issue(0, 0);  cp_commit();
    issue(1, 32); cp_commit();

    #pragma unroll 1
    for (int it = 0; it < 32; it++) {
        int buf = it % GSTG;
        if (it < 31) cp_wait<1>(); else cp_wait<0>();
        __syncthreads();
        if (it + 2 < 32) {
            issue((it + 2) % GSTG, (it + 2) * 32);
            cp_commit();
        }

        uint32_t A0_u = sA_u + (uint32_t)(buf * MROWS * GA_S * 4) + a_base;
        const float* B0 = sB + (size_t)buf * 32 * GB_S;

        #pragma unroll
        for (int kt = 0; kt < 4; kt++) {
            uint32_t a[MT][4], bfr[4][2];
            #pragma unroll
            for (int mt = 0; mt < MT; mt++)
                ldsm4(a[mt], A0_u + (uint32_t)((mt * 16 * GA_S + kt * 8) * 4));
            #pragma unroll
            for (int nt = 0; nt < 4; nt++) {
                const float* bp = &B0[(size_t)(kt * 8 + t) * GB_S + wn + nt * 8 + g];
                bfr[nt][0] = __float_as_uint(bp[0]);
                bfr[nt][1] = __float_as_uint(bp[4 * GB_S]);
            }
            #pragma unroll
            for (int mt = 0; mt < MT; mt++)
                #pragma unroll
                for (int nt = 0; nt < 4; nt++)
                    mma_tf32(acc[mt][nt], a[mt], bfr[nt]);
        }
    }

    #pragma unroll
    for (int mt = 0; mt < MT; mt++) {
        int row = m0 + wm + mt * 16 + g;
        #pragma unroll
        for (int nt = 0; nt < 4; nt++) {
            int col = n0 + wn + nt * 8 + 2 * t;
            float2 bb = *(const float2*)&bias[col];
            float2 o0, o1;
            if (MODE == 1) {
                o0.x = f2tff((acc[mt][nt][0] + bb.x) * outScale);
                o0.y = f2tff((acc[mt][nt][1] + bb.y) * outScale);
                o1.x = f2tff((acc[mt][nt][2] + bb.x) * outScale);
                o1.y = f2tff((acc[mt][nt][3] + bb.y) * outScale);
            } else {
                o0.x = acc[mt][nt][0] + bb.x;
                o0.y = acc[mt][nt][1] + bb.y;
                o1.x = acc[mt][nt][2] + bb.x;
                o1.y = acc[mt][nt][3] + bb.y;
            }
            *(float2*)&Y[(size_t)row * N + col]       = o0;
            *(float2*)&Y[(size_t)(row + 8) * N + col] = o1;
        }
    }
}

__global__ __launch_bounds__(256, 2) void qkv_proj_kernel(
    const float* __restrict__ bq, const float* __restrict__ bk,
    const float* __restrict__ bv)
{
    extern __shared__ float sm[];
    int y = blockIdx.y;
    const float *X, *W, *bias; float* Y; int m0; float sc;
    if (y < 16)      { X = g_Xr;                     W = g_Wr;               bias = bq; Y = g_Q; m0 = y * 128;        sc = SCALE_; }
    else if (y < 48) { X = g_Xr + (size_t)2048 * D_; W = g_Wr + 1 * D_ * D_; bias = bk; Y = g_K; m0 = (y - 16) * 128; sc = 1.0f;   }
    else             { X = g_Xr + (size_t)6144 * D_; W = g_Wr + 2 * D_ * D_; bias = bv; Y = g_V; m0 = (y - 48) * 128; sc = 1.0f;   }
    gemm_body<1, 128>(X, W, bias, Y, m0, blockIdx.x * 128, sc, sm, sm + GSTG * 128 * GA_S);
}

__global__ __launch_bounds__(256, 2) void oproj_kernel(
    const float* __restrict__ bo, float* __restrict__ out)
{
    extern __shared__ float sm[];
    gemm_body<0, 64>(g_ctx, g_Wr + 3 * D_ * D_, bo, out,
                     blockIdx.y * 64, blockIdx.x * 128, 1.0f,
                     sm, sm + GSTG * 64 * GA_S);
}

#define STK 68
#define SVT 68
#define STP 68
#define ATTN_SMEM ((2 * 64 * STK + 2 * 64 * SVT + 128 * STP) * 4)

__global__ __launch_bounds__(256, 2) void attn_tf32_kernel(
    const float* __restrict__ bias, float* __restrict__ ctx)
{
    extern __shared__ float smem[];
    float* sK  = smem;                               // [2][64][STK]  keys x d
    float* sVt = smem + 2 * 64 * STK;                // [2][64][SVT]  d x keys
    float* sP  = smem + 2 * 64 * STK + 2 * 64 * SVT; // [128][STP]    Q then P

    int tid = threadIdx.x, lane = tid & 31, warp = tid >> 5;
    int g = lane >> 2, t = lane & 3;
    int b = blockIdx.z, h = blockIdx.y, q0 = blockIdx.x * 128;
    int wq = warp * 16;

    const float* Qg  = g_Q + (size_t)(b * NQ_ + q0) * D_ + h * HD_;
    const float* Kg  = g_K + (size_t)b * NK_ * D_ + h * HD_;
    const float* Vtg = g_Vt + (size_t)(b * H_ + h) * HD_ * NK_;
    const float* biasg = bias + (((size_t)b * H_ + h) * NQ_ + q0) * NK_;
    const float* mg = g_maskf + b * NK_;

    uint32_t sK_u  = (uint32_t)__cvta_generic_to_shared(sK);
    uint32_t sVt_u = (uint32_t)__cvta_generic_to_shared(sVt);
    uint32_t sP_u  = (uint32_t)__cvta_generic_to_shared(sP);

    int arow = wq + (lane & 15);
    int acol = (lane >> 2) & 4;
    int brow = (lane & 7) + ((lane & 16) >> 1);
    int bcol = (lane & 8) >> 1;

    auto issueKV = [&](int buf, int k0) {
        #pragma unroll
        for (int i = 0; i < 4; i++) {
            int c = tid + i * 256;
            int row = c >> 4, col = (c & 15) * 4;
            cp16(sK_u + (uint32_t)(((buf * 64 + row) * STK + col) * 4),
                 Kg + (size_t)(k0 + row) * D_ + col);
            cp16(sVt_u + (uint32_t)(((buf * 64 + row) * SVT + col) * 4),
                 Vtg + (size_t)row * NK_ + k0 + col);
        }
    };

    issueKV(0, 0);
    cp_commit();

    for (int i = tid; i < 128 * 16; i += 256) {
        int row = i >> 4, dq = (i & 15) * 4;
        *(float4*)&sP[row * STP + dq] = *(const float4*)&Qg[(size_t)row * D_ + dq];
    }
    __syncthreads();

    uint32_t qf[8][4];
    #pragma unroll
    for (int kt = 0; kt < 8; kt++)
        ldsm4(qf[kt], sP_u + (uint32_t)((arow * STP + kt * 8 + acol) * 4));

    float oacc[8][4];
    #pragma unroll
    for (int nt = 0; nt < 8; nt++)
        #pragma unroll
        for (int c = 0; c < 4; c++) oacc[nt][c] = 0.f;
    float mr0 = -INFINITY, mr1 = -INFINITY, l0 = 0.f, l1 = 0.f;

    #pragma unroll 1
    for (int it = 0; it < NK_ / 64; it++) {
        int buf = it & 1, k0 = it * 64;

        // Pre-load bias straight into the S accumulators BEFORE the barrier —
        // the cp.async wait + syncthreads hides the LDG latency, and the MMA
        // accumulates Q·K on top (bias + sum vs sum + bias: benign reassoc).
        float sacc[8][4];
        #pragma unroll
        for (int nt = 0; nt < 8; nt++) {
            int kc = k0 + nt * 8 + 2 * t;
            float2 b0v = *(const float2*)&biasg[(size_t)(wq + g) * NK_ + kc];
            float2 b1v = *(const float2*)&biasg[(size_t)(wq + g + 8) * NK_ + kc];
            sacc[nt][0] = b0v.x; sacc[nt][1] = b0v.y;
            sacc[nt][2] = b1v.x; sacc[nt][3] = b1v.y;
        }

        cp_wait<0>();
        __syncthreads();
        if (it < NK_ / 64 - 1) {
            issueKV(buf ^ 1, k0 + 64);
            cp_commit();
        }

        uint32_t K0_u = sK_u  + (uint32_t)(buf * 64 * STK * 4);
        uint32_t V0_u = sVt_u + (uint32_t)(buf * 64 * SVT * 4);

        #pragma unroll
        for (int kt = 0; kt < 8; kt++) {
            uint32_t kb[4][4];
            #pragma unroll
            for (int n2 = 0; n2 < 4; n2++)
                ldsm4(kb[n2], K0_u +
                      (uint32_t)(((n2 * 16 + brow) * STK + kt * 8 + bcol) * 4));
            #pragma unroll
            for (int nt = 0; nt < 8; nt++)
                mma_tf32(sacc[nt], qf[kt], &kb[nt >> 1][(nt & 1) * 2]);
        }

        // mask + row maxima (bias already folded in)
        float rmax0 = -INFINITY, rmax1 = -INFINITY;
        #pragma unroll
        for (int nt = 0; nt < 8; nt++) {
            int kc = k0 + nt * 8 + 2 * t;
            float2 mk = *(const float2*)&mg[kc];
            if (mk.x != 0.f) { sacc[nt][0] = -INFINITY; sacc[nt][2] = -INFINITY; }
            if (mk.y != 0.f) { sacc[nt][1] = -INFINITY; sacc[nt][3] = -INFINITY; }
            rmax0 = fmaxf(rmax0, fmaxf(sacc[nt][0], sacc[nt][1]));
            rmax1 = fmaxf(rmax1, fmaxf(sacc[nt][2], sacc[nt][3]));
        }
        rmax0 = fmaxf(rmax0, __shfl_xor_sync(0xffffffffu, rmax0, 1));
        rmax0 = fmaxf(rmax0, __shfl_xor_sync(0xffffffffu, rmax0, 2));
        rmax1 = fmaxf(rmax1, __shfl_xor_sync(0xffffffffu, rmax1, 1));
        rmax1 = fmaxf(rmax1, __shfl_xor_sync(0xffffffffu, rmax1, 2));

        float mn0 = fmaxf(mr0, rmax0), mn1 = fmaxf(mr1, rmax1);
        bool dead0 = (mn0 == -INFINITY), dead1 = (mn1 == -INFINITY);
        float al0 = dead0 ? 1.f : __expf(mr0 - mn0);
        float al1 = dead1 ? 1.f : __expf(mr1 - mn1);
        float sum0 = 0.f, sum1 = 0.f;

        #pragma unroll
        for (int nt = 0; nt < 8; nt++) {
            float p00 = dead0 ? 0.f : __expf(sacc[nt][0] - mn0);
            float p01 = dead0 ? 0.f : __expf(sacc[nt][1] - mn0);
            float p10 = dead1 ? 0.f : __expf(sacc[nt][2] - mn1);
            float p11 = dead1 ? 0.f : __expf(sacc[nt][3] - mn1);
            sum0 += p00 + p01;
            sum1 += p10 + p11;
            float2 w0 = make_float2(f2tff(p00), f2tff(p01));
            float2 w1 = make_float2(f2tff(p10), f2tff(p11));
            *(float2*)&sP[(wq + g) * STP + nt * 8 + 2 * t]     = w0;
            *(float2*)&sP[(wq + g + 8) * STP + nt * 8 + 2 * t] = w1;
        }
        sum0 += __shfl_xor_sync(0xffffffffu, sum0, 1);
        sum0 += __shfl_xor_sync(0xffffffffu, sum0, 2);
        sum1 += __shfl_xor_sync(0xffffffffu, sum1, 1);
        sum1 += __shfl_xor_sync(0xffffffffu, sum1, 2);

        mr0 = mn0; mr1 = mn1;
        l0 = l0 * al0 + sum0;
        l1 = l1 * al1 + sum1;
        #pragma unroll
        for (int nt = 0; nt < 8; nt++) {
            oacc[nt][0] *= al0; oacc[nt][1] *= al0;
            oacc[nt][2] *= al1; oacc[nt][3] *= al1;
        }
        __syncwarp();   // P rows are warp-private; warp-level visibility suffices

        #pragma unroll
        for (int kt = 0; kt < 8; kt++) {
            uint32_t pa[4];
            ldsm4(pa, sP_u + (uint32_t)((arow * STP + kt * 8 + acol) * 4));
            uint32_t vb[4][4];
            #pragma unroll
            for (int n2 = 0; n2 < 4; n2++)
                ldsm4(vb[n2], V0_u +
                      (uint32_t)(((n2 * 16 + brow) * SVT + kt * 8 + bcol) * 4));
            #pragma unroll
            for (int nt = 0; nt < 8; nt++)
                mma_tf32(oacc[nt], pa, &vb[nt >> 1][(nt & 1) * 2]);
        }
    }

    float inv0 = 1.f / l0, inv1 = 1.f / l1;
    size_t row0 = (size_t)(b * NQ_ + q0 + wq + g) * D_ + h * HD_;
    size_t row1 = row0 + 8 * D_;
    #pragma unroll
    for (int nt = 0; nt < 8; nt++) {
        int col = nt * 8 + 2 * t;
        float2 o0 = make_float2(f2tff(oacc[nt][0] * inv0), f2tff(oacc[nt][1] * inv0));
        float2 o1 = make_float2(f2tff(oacc[nt][2] * inv1), f2tff(oacc[nt][3] * inv1));
        *(float2*)&ctx[row0 + col] = o0;
        *(float2*)&ctx[row1 + col] = o1;
    }
}

extern "C" void kernel_launch(void* const* d_in, const int* in_sizes, int n_in,
                              void* d_out, int out_size)
{
    const float* q  = (const float*)d_in[0];
    const float* k  = (const float*)d_in[1];
    const float* v  = (const float*)d_in[2];
    const float* ab = (const float*)d_in[3];
    const void*  mk = d_in[4];
    const float* Wq = (const float*)d_in[5];
    const float* bq = (const float*)d_in[6];
    const float* Wk = (const float*)d_in[7];
    const float* bk = (const float*)d_in[8];
    const float* Wv = (const float*)d_in[9];
    const float* bv = (const float*)d_in[10];
    const float* Wo = (const float*)d_in[11];
    const float* bo = (const float*)d_in[12];
    float* out = (float*)d_out;

    static int smem_set = 0;
    if (!smem_set) {
        cudaFuncSetAttribute(qkv_proj_kernel,
                             cudaFuncAttributeMaxDynamicSharedMemorySize, GEMM_SMEM128);
        cudaFuncSetAttribute(oproj_kernel,
                             cudaFuncAttributeMaxDynamicSharedMemorySize, GEMM_SMEM64);
        cudaFuncSetAttribute(attn_tf32_kernel,
                             cudaFuncAttributeMaxDynamicSharedMemorySize, ATTN_SMEM);
        smem_set = 1;
    }

    float* gctx;
    cudaGetSymbolAddress((void**)&gctx, g_ctx);

    detect_mask_kernel<<<1, 256>>>((const unsigned char*)mk);
    prep_mask_kernel<<<B_, 256>>>(mk);
    round_w_kernel<<<dim3(128, 4), 256>>>(Wq, Wk, Wv, Wo);
    round_x_kernel<<<dim3(256, 3), 256>>>(q, k, v);

    qkv_proj_kernel<<<dim3(8, 80), 256, GEMM_SMEM128>>>(bq, bk, bv);

    vtrans_kernel<<<dim3(NK_ / 32, HD_ / 32, B_ * H_), dim3(32, 8)>>>();

    attn_tf32_kernel<<<dim3(NQ_ / 128, H_, B_), 256, ATTN_SMEM>>>(ab, gctx);

    oproj_kernel<<<dim3(8, 32), 256, GEMM_SMEM64>>>(bo, out);
}

// round 9
// speedup vs baseline: 3.6894x; 1.0100x over previous
#include <cuda_runtime.h>
#include <math.h>
#include <stdint.h>

#define B_     2
#define NQ_    1024
#define NK_    2048
#define D_     1024
#define H_     16
#define HD_    64
#define SCALE_ 0.125f

__device__ float g_Q[(size_t)B_ * NQ_ * D_];    // pre-scaled + tf32-rounded
__device__ float g_K[(size_t)B_ * NK_ * D_];    // tf32-rounded
__device__ float g_V[(size_t)B_ * NK_ * D_];    // tf32-rounded
__device__ float g_Vt[(size_t)B_ * H_ * HD_ * NK_];  // V transposed per (b,h): [d][key]
__device__ float g_ctx[(size_t)B_ * NQ_ * D_];  // tf32-rounded (attn epilogue)
__device__ float g_Wt[(size_t)4 * D_ * D_];     // tf32-rounded TRANSPOSED Wq|Wk|Wv|Wo
__device__ float g_Xr[(size_t)10240 * D_];      // tf32-rounded inputs q|k|v
__device__ float g_maskf[B_ * NK_];
__device__ int   g_mask_mode;

__device__ __forceinline__ uint32_t f2tf(float x) {
    uint32_t u; asm("cvt.rna.tf32.f32 %0, %1;" : "=r"(u) : "f"(x)); return u;
}
__device__ __forceinline__ float f2tff(float x) { return __uint_as_float(f2tf(x)); }

__device__ __forceinline__ void mma_tf32(float* d, const uint32_t* a, const uint32_t* b) {
    asm volatile(
        "mma.sync.aligned.m16n8k8.row.col.f32.tf32.tf32.f32 "
        "{%0,%1,%2,%3}, {%4,%5,%6,%7}, {%8,%9}, {%0,%1,%2,%3};"
        : "+f"(d[0]), "+f"(d[1]), "+f"(d[2]), "+f"(d[3])
        : "r"(a[0]), "r"(a[1]), "r"(a[2]), "r"(a[3]),
          "r"(b[0]), "r"(b[1]));
}

__device__ __forceinline__ void ldsm4(uint32_t* r, uint32_t addr) {
    asm volatile("ldmatrix.sync.aligned.m8n8.x4.shared.b16 {%0,%1,%2,%3}, [%4];"
                 : "=r"(r[0]), "=r"(r[1]), "=r"(r[2]), "=r"(r[3]) : "r"(addr));
}

__device__ __forceinline__ void cp16(uint32_t dst, const void* src) {
    asm volatile("cp.async.cg.shared.global [%0], [%1], 16;" :: "r"(dst), "l"(src));
}
__device__ __forceinline__ void cp_commit() { asm volatile("cp.async.commit_group;"); }
template <int N> __device__ __forceinline__ void cp_wait() {
    asm volatile("cp.async.wait_group %0;" :: "n"(N));
}

__global__ void detect_mask_kernel(const unsigned char* __restrict__ p) {
    __shared__ int s_nonbin, s_unal;
    int tid = threadIdx.x;
    if (tid == 0) { s_nonbin = 0; s_unal = 0; }
    __syncthreads();
    for (int i = tid; i < B_ * NK_; i += 256) {
        unsigned char v = p[i];
        if (v > 1) s_nonbin = 1;
        else if (v == 1 && (i & 3)) s_unal = 1;
    }
    __syncthreads();
    if (tid == 0) g_mask_mode = s_nonbin ? 2 : (s_unal ? 0 : 1);
}

__global__ void prep_mask_kernel(const void* __restrict__ mptr) {
    int b = blockIdx.x;
    int tid = threadIdx.x;
    __shared__ int anyUnmasked;
    if (tid == 0) anyUnmasked = 0;
    __syncthreads();
    int mode = g_mask_mode;
    float vals[NK_ / 256];
    #pragma unroll
    for (int x = 0; x < NK_ / 256; x++) {
        int i = tid + x * 256;
        float m;
        if (mode == 0)      m = ((const unsigned char*)mptr)[b * NK_ + i] ? 1.f : 0.f;
        else if (mode == 1) m = ((const int*)mptr)[b * NK_ + i] ? 1.f : 0.f;
        else                m = (((const float*)mptr)[b * NK_ + i] != 0.f) ? 1.f : 0.f;
        vals[x] = m;
        if (m == 0.f) anyUnmasked = 1;
    }
    __syncthreads();
    #pragma unroll
    for (int x = 0; x < NK_ / 256; x++) {
        int i = tid + x * 256;
        float m = vals[x];
        if (i == 0 && !anyUnmasked) m = 0.f;
        g_maskf[b * NK_ + i] = m;
    }
}

// Transpose + tf32-round weights: W[k][n] -> Wt[n][k] (values identical to
// per-load rounding; transpose enables ldmatrix B-fragment loads).
__global__ __launch_bounds__(256) void wtrans_kernel(
    const float* __restrict__ w0, const float* __restrict__ w1,
    const float* __restrict__ w2, const float* __restrict__ w3)
{
    __shared__ float tile[32][33];
    int which = blockIdx.z;
    const float* s = (which == 0) ? w0 : (which == 1) ? w1 : (which == 2) ? w2 : w3;
    float* d = g_Wt + (size_t)which * D_ * D_;
    int k0 = blockIdx.x * 32, n0 = blockIdx.y * 32;
    int tx = threadIdx.x & 31, ty = threadIdx.x >> 5;
    #pragma unroll
    for (int i = 0; i < 4; i++)
        tile[ty + i * 8][tx] = f2tff(s[(size_t)(k0 + ty + i * 8) * D_ + n0 + tx]);
    __syncthreads();
    #pragma unroll
    for (int i = 0; i < 4; i++)
        d[(size_t)(n0 + ty + i * 8) * D_ + k0 + tx] = tile[tx][ty + i * 8];
}

// Round raw q/k/v inputs to tf32 once (so GEMM A-side needs no cvt).
__global__ __launch_bounds__(256) void round_x_kernel(
    const float* __restrict__ q, const float* __restrict__ k, const float* __restrict__ v)
{
    int which = blockIdx.y;
    const float* s; float* d; int n;
    if (which == 0)      { s = q; d = g_Xr;                     n = B_ * NQ_ * D_; }
    else if (which == 1) { s = k; d = g_Xr + (size_t)2048 * D_; n = B_ * NK_ * D_; }
    else                 { s = v; d = g_Xr + (size_t)6144 * D_; n = B_ * NK_ * D_; }
    for (int i = blockIdx.x * blockDim.x + threadIdx.x;
         i < n / 4; i += gridDim.x * blockDim.x) {
        float4 x = ((const float4*)s)[i];
        x.x = f2tff(x.x); x.y = f2tff(x.y); x.z = f2tff(x.z); x.w = f2tff(x.w);
        ((float4*)d)[i] = x;
    }
}

// V transpose per (b,h): g_V[b*NK+key][h*HD+d] -> g_Vt[(b*H+h)*HD+d][key]
__global__ __launch_bounds__(256) void vtrans_kernel() {
    __shared__ float tile[32][33];
    int bh = blockIdx.z, b = bh >> 4, h = bh & 15;
    int k0 = blockIdx.x * 32, d0 = blockIdx.y * 32;
    int tx = threadIdx.x, ty = threadIdx.y;
    #pragma unroll
    for (int i = 0; i < 4; i++)
        tile[ty + i * 8][tx] =
            g_V[(size_t)(b * NK_ + k0 + ty + i * 8) * D_ + h * HD_ + d0 + tx];
    __syncthreads();
    #pragma unroll
    for (int i = 0; i < 4; i++)
        g_Vt[(size_t)(bh * HD_ + d0 + ty + i * 8) * NK_ + k0 + tx] =
            tile[tx][ty + i * 8];
}

#define GS   36
#define GSTG 3
#define GEMM_SMEM128 ((GSTG * 128 * GS + GSTG * 128 * GS) * 4)
#define GEMM_SMEM64  ((GSTG * 64  * GS + GSTG * 128 * GS) * 4)

// MODE 0: raw fp32 store.  MODE 1: store tf32-rounded (acc+bias)*outScale.
// X pre-rounded [m][k]; Wt pre-rounded TRANSPOSED [n][k]. A and B frags both
// via ldmatrix from symmetric [rows][GS] smem tiles — zero cvt, zero scalar LDS.
template <int MODE, int MROWS>
__device__ __forceinline__ void gemm_body(
    const float* __restrict__ X, const float* __restrict__ Wt,
    const float* __restrict__ bias, float* __restrict__ Y,
    int m0, int n0, float outScale, float* sA, float* sB)
{
    const int K = 1024, N = 1024;
    const int MT = MROWS / 32;
    int tid  = threadIdx.x;
    int lane = tid & 31, warp = tid >> 5;
    int g = lane >> 2, t = lane & 3;
    int wm = (warp >> 2) * (MROWS / 2);
    int wn = (warp & 3) * 32;

    uint32_t sA_u = (uint32_t)__cvta_generic_to_shared(sA);
    uint32_t sB_u = (uint32_t)__cvta_generic_to_shared(sB);

    int arow = (lane & 15);
    int acol = (lane >> 2) & 4;
    uint32_t a_base = (uint32_t)(((wm + arow) * GS + acol) * 4);
    int brow = (lane & 7) + ((lane & 16) >> 1);
    int bcol = (lane & 8) >> 1;
    uint32_t b_base = (uint32_t)(((wn + brow) * GS + bcol) * 4);

    float acc[MT][4][4];
    #pragma unroll
    for (int i = 0; i < MT; i++)
        #pragma unroll
        for (int j = 0; j < 4; j++)
            #pragma unroll
            for (int c = 0; c < 4; c++) acc[i][j][c] = 0.f;

    auto issue = [&](int buf, int k0) {
        #pragma unroll
        for (int i = 0; i < MT; i++) {
            int c = tid + i * 256;
            int row = c >> 3, col = (c & 7) * 4;
            cp16(sA_u + (uint32_t)(((buf * MROWS + row) * GS + col) * 4),
                 X + (size_t)(m0 + row) * K + k0 + col);
        }
        #pragma unroll
        for (int i = 0; i < 4; i++) {
            int c = tid + i * 256;
            int row = c >> 3, col = (c & 7) * 4;
            cp16(sB_u + (uint32_t)(((buf * 128 + row) * GS + col) * 4),
                 Wt + (size_t)(n0 + row) * K + k0 + col);
        }
    };

    issue(0, 0);  cp_commit();
    issue(1, 32); cp_commit();

    #pragma unroll 1
    for (int it = 0; it < 32; it++) {
        int buf = it % GSTG;
        if (it < 31) cp_wait<1>(); else cp_wait<0>();
        __syncthreads();
        if (it + 2 < 32) {
            issue((it + 2) % GSTG, (it + 2) * 32);
            cp_commit();
        }

        uint32_t A0_u = sA_u + (uint32_t)(buf * MROWS * GS * 4) + a_base;
        uint32_t B0_u = sB_u + (uint32_t)(buf * 128 * GS * 4) + b_base;

        #pragma unroll
        for (int kt = 0; kt < 4; kt++) {
            uint32_t a[MT][4], kb[2][4];
            #pragma unroll
            for (int mt = 0; mt < MT; mt++)
                ldsm4(a[mt], A0_u + (uint32_t)((mt * 16 * GS + kt * 8) * 4));
            #pragma unroll
            for (int n2 = 0; n2 < 2; n2++)
                ldsm4(kb[n2], B0_u + (uint32_t)((n2 * 16 * GS + kt * 8) * 4));
            #pragma unroll
            for (int mt = 0; mt < MT; mt++)
                #pragma unroll
                for (int nt = 0; nt < 4; nt++)
                    mma_tf32(acc[mt][nt], a[mt], &kb[nt >> 1][(nt & 1) * 2]);
        }
    }

    #pragma unroll
    for (int mt = 0; mt < MT; mt++) {
        int row = m0 + wm + mt * 16 + g;
        #pragma unroll
        for (int nt = 0; nt < 4; nt++) {
            int col = n0 + wn + nt * 8 + 2 * t;
            float2 bb = *(const float2*)&bias[col];
            float2 o0, o1;
            if (MODE == 1) {
                o0.x = f2tff((acc[mt][nt][0] + bb.x) * outScale);
                o0.y = f2tff((acc[mt][nt][1] + bb.y) * outScale);
                o1.x = f2tff((acc[mt][nt][2] + bb.x) * outScale);
                o1.y = f2tff((acc[mt][nt][3] + bb.y) * outScale);
            } else {
                o0.x = acc[mt][nt][0] + bb.x;
                o0.y = acc[mt][nt][1] + bb.y;
                o1.x = acc[mt][nt][2] + bb.x;
                o1.y = acc[mt][nt][3] + bb.y;
            }
            *(float2*)&Y[(size_t)row * N + col]       = o0;
            *(float2*)&Y[(size_t)(row + 8) * N + col] = o1;
        }
    }
}

__global__ __launch_bounds__(256, 2) void qkv_proj_kernel(
    const float* __restrict__ bq, const float* __restrict__ bk,
    const float* __restrict__ bv)
{
    extern __shared__ float sm[];
    int y = blockIdx.y;
    const float *X, *W, *bias; float* Y; int m0; float sc;
    if (y < 16)      { X = g_Xr;                     W = g_Wt;               bias = bq; Y = g_Q; m0 = y * 128;        sc = SCALE_; }
    else if (y < 48) { X = g_Xr + (size_t)2048 * D_; W = g_Wt + 1 * D_ * D_; bias = bk; Y = g_K; m0 = (y - 16) * 128; sc = 1.0f;   }
    else             { X = g_Xr + (size_t)6144 * D_; W = g_Wt + 2 * D_ * D_; bias = bv; Y = g_V; m0 = (y - 48) * 128; sc = 1.0f;   }
    gemm_body<1, 128>(X, W, bias, Y, m0, blockIdx.x * 128, sc, sm, sm + GSTG * 128 * GS);
}

__global__ __launch_bounds__(256, 2) void oproj_kernel(
    const float* __restrict__ bo, float* __restrict__ out)
{
    extern __shared__ float sm[];
    gemm_body<0, 64>(g_ctx, g_Wt + 3 * D_ * D_, bo, out,
                     blockIdx.y * 64, blockIdx.x * 128, 1.0f,
                     sm, sm + GSTG * 64 * GS);
}

#define STK 68
#define SVT 68
#define STP 68
#define ATTN_SMEM ((2 * 64 * STK + 2 * 64 * SVT + 128 * STP) * 4)

__global__ __launch_bounds__(256, 2) void attn_tf32_kernel(
    const float* __restrict__ bias, float* __restrict__ ctx)
{
    extern __shared__ float smem[];
    float* sK  = smem;
    float* sVt = smem + 2 * 64 * STK;
    float* sP  = smem + 2 * 64 * STK + 2 * 64 * SVT;

    int tid = threadIdx.x, lane = tid & 31, warp = tid >> 5;
    int g = lane >> 2, t = lane & 3;
    int b = blockIdx.z, h = blockIdx.y, q0 = blockIdx.x * 128;
    int wq = warp * 16;

    const float* Qg  = g_Q + (size_t)(b * NQ_ + q0) * D_ + h * HD_;
    const float* Kg  = g_K + (size_t)b * NK_ * D_ + h * HD_;
    const float* Vtg = g_Vt + (size_t)(b * H_ + h) * HD_ * NK_;
    const float* biasg = bias + (((size_t)b * H_ + h) * NQ_ + q0) * NK_;
    const float* mg = g_maskf + b * NK_;

    uint32_t sK_u  = (uint32_t)__cvta_generic_to_shared(sK);
    uint32_t sVt_u = (uint32_t)__cvta_generic_to_shared(sVt);
    uint32_t sP_u  = (uint32_t)__cvta_generic_to_shared(sP);

    int arow = wq + (lane & 15);
    int acol = (lane >> 2) & 4;
    int brow = (lane & 7) + ((lane & 16) >> 1);
    int bcol = (lane & 8) >> 1;

    auto issueKV = [&](int buf, int k0) {
        #pragma unroll
        for (int i = 0; i < 4; i++) {
            int c = tid + i * 256;
            int row = c >> 4, col = (c & 15) * 4;
            cp16(sK_u + (uint32_t)(((buf * 64 + row) * STK + col) * 4),
                 Kg + (size_t)(k0 + row) * D_ + col);
            cp16(sVt_u + (uint32_t)(((buf * 64 + row) * SVT + col) * 4),
                 Vtg + (size_t)row * NK_ + k0 + col);
        }
    };

    issueKV(0, 0);
    cp_commit();

    for (int i = tid; i < 128 * 16; i += 256) {
        int row = i >> 4, dq = (i & 15) * 4;
        *(float4*)&sP[row * STP + dq] = *(const float4*)&Qg[(size_t)row * D_ + dq];
    }
    __syncthreads();

    uint32_t qf[8][4];
    #pragma unroll
    for (int kt = 0; kt < 8; kt++)
        ldsm4(qf[kt], sP_u + (uint32_t)((arow * STP + kt * 8 + acol) * 4));

    float oacc[8][4];
    #pragma unroll
    for (int nt = 0; nt < 8; nt++)
        #pragma unroll
        for (int c = 0; c < 4; c++) oacc[nt][c] = 0.f;
    float mr0 = -INFINITY, mr1 = -INFINITY, l0 = 0.f, l1 = 0.f;

    #pragma unroll 1
    for (int it = 0; it < NK_ / 64; it++) {
        int buf = it & 1, k0 = it * 64;

        float sacc[8][4];
        #pragma unroll
        for (int nt = 0; nt < 8; nt++) {
            int kc = k0 + nt * 8 + 2 * t;
            float2 b0v = *(const float2*)&biasg[(size_t)(wq + g) * NK_ + kc];
            float2 b1v = *(const float2*)&biasg[(size_t)(wq + g + 8) * NK_ + kc];
            sacc[nt][0] = b0v.x; sacc[nt][1] = b0v.y;
            sacc[nt][2] = b1v.x; sacc[nt][3] = b1v.y;
        }

        cp_wait<0>();
        __syncthreads();
        if (it < NK_ / 64 - 1) {
            issueKV(buf ^ 1, k0 + 64);
            cp_commit();
        }

        uint32_t K0_u = sK_u  + (uint32_t)(buf * 64 * STK * 4);
        uint32_t V0_u = sVt_u + (uint32_t)(buf * 64 * SVT * 4);

        #pragma unroll
        for (int kt = 0; kt < 8; kt++) {
            uint32_t kb[4][4];
            #pragma unroll
            for (int n2 = 0; n2 < 4; n2++)
                ldsm4(kb[n2], K0_u +
                      (uint32_t)(((n2 * 16 + brow) * STK + kt * 8 + bcol) * 4));
            #pragma unroll
            for (int nt = 0; nt < 8; nt++)
                mma_tf32(sacc[nt], qf[kt], &kb[nt >> 1][(nt & 1) * 2]);
        }

        float rmax0 = -INFINITY, rmax1 = -INFINITY;
        #pragma unroll
        for (int nt = 0; nt < 8; nt++) {
            int kc = k0 + nt * 8 + 2 * t;
            float2 mk = *(const float2*)&mg[kc];
            if (mk.x != 0.f) { sacc[nt][0] = -INFINITY; sacc[nt][2] = -INFINITY; }
            if (mk.y != 0.f) { sacc[nt][1] = -INFINITY; sacc[nt][3] = -INFINITY; }
            rmax0 = fmaxf(rmax0, fmaxf(sacc[nt][0], sacc[nt][1]));
            rmax1 = fmaxf(rmax1, fmaxf(sacc[nt][2], sacc[nt][3]));
        }
        rmax0 = fmaxf(rmax0, __shfl_xor_sync(0xffffffffu, rmax0, 1));
        rmax0 = fmaxf(rmax0, __shfl_xor_sync(0xffffffffu, rmax0, 2));
        rmax1 = fmaxf(rmax1, __shfl_xor_sync(0xffffffffu, rmax1, 1));
        rmax1 = fmaxf(rmax1, __shfl_xor_sync(0xffffffffu, rmax1, 2));

        float mn0 = fmaxf(mr0, rmax0), mn1 = fmaxf(mr1, rmax1);
        bool dead0 = (mn0 == -INFINITY), dead1 = (mn1 == -INFINITY);
        float al0 = dead0 ? 1.f : __expf(mr0 - mn0);
        float al1 = dead1 ? 1.f : __expf(mr1 - mn1);
        float sum0 = 0.f, sum1 = 0.f;

        #pragma unroll
        for (int nt = 0; nt < 8; nt++) {
            float p00 = dead0 ? 0.f : __expf(sacc[nt][0] - mn0);
            float p01 = dead0 ? 0.f : __expf(sacc[nt][1] - mn0);
            float p10 = dead1 ? 0.f : __expf(sacc[nt][2] - mn1);
            float p11 = dead1 ? 0.f : __expf(sacc[nt][3] - mn1);
            sum0 += p00 + p01;
            sum1 += p10 + p11;
            float2 w0 = make_float2(f2tff(p00), f2tff(p01));
            float2 w1 = make_float2(f2tff(p10), f2tff(p11));
            *(float2*)&sP[(wq + g) * STP + nt * 8 + 2 * t]     = w0;
            *(float2*)&sP[(wq + g + 8) * STP + nt * 8 + 2 * t] = w1;
        }
        sum0 += __shfl_xor_sync(0xffffffffu, sum0, 1);
        sum0 += __shfl_xor_sync(0xffffffffu, sum0, 2);
        sum1 += __shfl_xor_sync(0xffffffffu, sum1, 1);
        sum1 += __shfl_xor_sync(0xffffffffu, sum1, 2);

        mr0 = mn0; mr1 = mn1;
        l0 = l0 * al0 + sum0;
        l1 = l1 * al1 + sum1;
        #pragma unroll
        for (int nt = 0; nt < 8; nt++) {
            oacc[nt][0] *= al0; oacc[nt][1] *= al0;
            oacc[nt][2] *= al1; oacc[nt][3] *= al1;
        }
        __syncwarp();

        #pragma unroll
        for (int kt = 0; kt < 8; kt++) {
            uint32_t pa[4];
            ldsm4(pa, sP_u + (uint32_t)((arow * STP + kt * 8 + acol) * 4));
            uint32_t vb[4][4];
            #pragma unroll
            for (int n2 = 0; n2 < 4; n2++)
                ldsm4(vb[n2], V0_u +
                      (uint32_t)(((n2 * 16 + brow) * SVT + kt * 8 + bcol) * 4));
            #pragma unroll
            for (int nt = 0; nt < 8; nt++)
                mma_tf32(oacc[nt], pa, &vb[nt >> 1][(nt & 1) * 2]);
        }
    }

    float inv0 = 1.f / l0, inv1 = 1.f / l1;
    size_t row0 = (size_t)(b * NQ_ + q0 + wq + g) * D_ + h * HD_;
    size_t row1 = row0 + 8 * D_;
    #pragma unroll
    for (int nt = 0; nt < 8; nt++) {
        int col = nt * 8 + 2 * t;
        float2 o0 = make_float2(f2tff(oacc[nt][0] * inv0), f2tff(oacc[nt][1] * inv0));
        float2 o1 = make_float2(f2tff(oacc[nt][2] * inv1), f2tff(oacc[nt][3] * inv1));
        *(float2*)&ctx[row0 + col] = o0;
        *(float2*)&ctx[row1 + col] = o1;
    }
}

extern "C" void kernel_launch(void* const* d_in, const int* in_sizes, int n_in,
                              void* d_out, int out_size)
{
    const float* q  = (const float*)d_in[0];
    const float* k  = (const float*)d_in[1];
    const float* v  = (const float*)d_in[2];
    const float* ab = (const float*)d_in[3];
    const void*  mk = d_in[4];
    const float* Wq = (const float*)d_in[5];
    const float* bq = (const float*)d_in[6];
    const float* Wk = (const float*)d_in[7];
    const float* bk = (const float*)d_in[8];
    const float* Wv = (const float*)d_in[9];
    const float* bv = (const float*)d_in[10];
    const float* Wo = (const float*)d_in[11];
    const float* bo = (const float*)d_in[12];
    float* out = (float*)d_out;

    static int smem_set = 0;
    if (!smem_set) {
        cudaFuncSetAttribute(qkv_proj_kernel,
                             cudaFuncAttributeMaxDynamicSharedMemorySize, GEMM_SMEM128);
        cudaFuncSetAttribute(oproj_kernel,
                             cudaFuncAttributeMaxDynamicSharedMemorySize, GEMM_SMEM64);
        cudaFuncSetAttribute(attn_tf32_kernel,
                             cudaFuncAttributeMaxDynamicSharedMemorySize, ATTN_SMEM);
        smem_set = 1;
    }

    float* gctx;
    cudaGetSymbolAddress((void**)&gctx, g_ctx);

    detect_mask_kernel<<<1, 256>>>((const unsigned char*)mk);
    prep_mask_kernel<<<B_, 256>>>(mk);
    wtrans_kernel<<<dim3(32, 32, 4), 256>>>(Wq, Wk, Wv, Wo);
    round_x_kernel<<<dim3(256, 3), 256>>>(q, k, v);

    qkv_proj_kernel<<<dim3(8, 80), 256, GEMM_SMEM128>>>(bq, bk, bv);

    vtrans_kernel<<<dim3(NK_ / 32, HD_ / 32, B_ * H_), dim3(32, 8)>>>();

    attn_tf32_kernel<<<dim3(NQ_ / 128, H_, B_), 256, ATTN_SMEM>>>(ab, gctx);

    oproj_kernel<<<dim3(8, 32), 256, GEMM_SMEM64>>>(bo, out);
}

// round 11
// speedup vs baseline: 5.7852x; 1.5681x over previous
#include <cuda_runtime.h>
#include <cuda_fp16.h>
#include <math.h>
#include <stdint.h>

#define B_     2
#define NQ_    1024
#define NK_    2048
#define D_     1024
#define H_     16
#define HD_    64
#define SCALE_ 0.125f

// fp16 operand storage (10-bit mantissa == tf32; all values O(1), range safe)
__device__ __half g_Q[(size_t)B_ * NQ_ * D_];        // pre-scaled by 0.125
__device__ __half g_K[(size_t)B_ * NK_ * D_];
__device__ __half g_V[(size_t)B_ * NK_ * D_];
__device__ __half g_Vt[(size_t)B_ * H_ * HD_ * NK_]; // V^T per (b,h): [d][key]
__device__ __half g_ctx[(size_t)B_ * NQ_ * D_];
__device__ __half g_Wt[(size_t)4 * D_ * D_];         // transposed Wq|Wk|Wv|Wo
__device__ __half g_Xh[(size_t)10240 * D_];          // inputs q|k|v
__device__ float  g_maskf[B_ * NK_];
__device__ int    g_mask_mode;

__device__ __forceinline__ void mma_f16(float* d, const uint32_t* a, const uint32_t* b) {
    asm volatile(
        "mma.sync.aligned.m16n8k16.row.col.f32.f16.f16.f32 "
        "{%0,%1,%2,%3}, {%4,%5,%6,%7}, {%8,%9}, {%0,%1,%2,%3};"
        : "+f"(d[0]), "+f"(d[1]), "+f"(d[2]), "+f"(d[3])
        : "r"(a[0]), "r"(a[1]), "r"(a[2]), "r"(a[3]),
          "r"(b[0]), "r"(b[1]));
}

__device__ __forceinline__ void ldsm4(uint32_t* r, uint32_t addr) {
    asm volatile("ldmatrix.sync.aligned.m8n8.x4.shared.b16 {%0,%1,%2,%3}, [%4];"
                 : "=r"(r[0]), "=r"(r[1]), "=r"(r[2]), "=r"(r[3]) : "r"(addr));
}

__device__ __forceinline__ void cp16(uint32_t dst, const void* src) {
    asm volatile("cp.async.cg.shared.global [%0], [%1], 16;" :: "r"(dst), "l"(src));
}
__device__ __forceinline__ void cp_commit() { asm volatile("cp.async.commit_group;"); }
template <int N> __device__ __forceinline__ void cp_wait() {
    asm volatile("cp.async.wait_group %0;" :: "n"(N));
}

__global__ void detect_mask_kernel(const unsigned char* __restrict__ p) {
    __shared__ int s_nonbin, s_unal;
    int tid = threadIdx.x;
    if (tid == 0) { s_nonbin = 0; s_unal = 0; }
    __syncthreads();
    for (int i = tid; i < B_ * NK_; i += 256) {
        unsigned char v = p[i];
        if (v > 1) s_nonbin = 1;
        else if (v == 1 && (i & 3)) s_unal = 1;
    }
    __syncthreads();
    if (tid == 0) g_mask_mode = s_nonbin ? 2 : (s_unal ? 0 : 1);
}

__global__ void prep_mask_kernel(const void* __restrict__ mptr) {
    int b = blockIdx.x;
    int tid = threadIdx.x;
    __shared__ int anyUnmasked;
    if (tid == 0) anyUnmasked = 0;
    __syncthreads();
    int mode = g_mask_mode;
    float vals[NK_ / 256];
    #pragma unroll
    for (int x = 0; x < NK_ / 256; x++) {
        int i = tid + x * 256;
        float m;
        if (mode == 0)      m = ((const unsigned char*)mptr)[b * NK_ + i] ? 1.f : 0.f;
        else if (mode == 1) m = ((const int*)mptr)[b * NK_ + i] ? 1.f : 0.f;
        else                m = (((const float*)mptr)[b * NK_ + i] != 0.f) ? 1.f : 0.f;
        vals[x] = m;
        if (m == 0.f) anyUnmasked = 1;
    }
    __syncthreads();
    #pragma unroll
    for (int x = 0; x < NK_ / 256; x++) {
        int i = tid + x * 256;
        float m = vals[x];
        if (i == 0 && !anyUnmasked) m = 0.f;
        g_maskf[b * NK_ + i] = m;
    }
}

// Transpose + fp16-round weights: W[k][n] -> Wt[n][k]
__global__ __launch_bounds__(256) void wtrans_kernel(
    const float* __restrict__ w0, const float* __restrict__ w1,
    const float* __restrict__ w2, const float* __restrict__ w3)
{
    __shared__ float tile[32][33];
    int which = blockIdx.z;
    const float* s = (which == 0) ? w0 : (which == 1) ? w1 : (which == 2) ? w2 : w3;
    __half* d = g_Wt + (size_t)which * D_ * D_;
    int k0 = blockIdx.x * 32, n0 = blockIdx.y * 32;
    int tx = threadIdx.x & 31, ty = threadIdx.x >> 5;
    #pragma unroll
    for (int i = 0; i < 4; i++)
        tile[ty + i * 8][tx] = s[(size_t)(k0 + ty + i * 8) * D_ + n0 + tx];
    __syncthreads();
    #pragma unroll
    for (int i = 0; i < 4; i++)
        d[(size_t)(n0 + ty + i * 8) * D_ + k0 + tx] =
            __float2half_rn(tile[tx][ty + i * 8]);
}

// Convert raw q/k/v inputs to fp16
__global__ __launch_bounds__(256) void cvt_x_kernel(
    const float* __restrict__ q, const float* __restrict__ k, const float* __restrict__ v)
{
    int which = blockIdx.y;
    const float* s; __half* d; int n;
    if (which == 0)      { s = q; d = g_Xh;                     n = B_ * NQ_ * D_; }
    else if (which == 1) { s = k; d = g_Xh + (size_t)2048 * D_; n = B_ * NK_ * D_; }
    else                 { s = v; d = g_Xh + (size_t)6144 * D_; n = B_ * NK_ * D_; }
    __half2* dh = (__half2*)d;
    for (int i = blockIdx.x * blockDim.x + threadIdx.x;
         i < n / 4; i += gridDim.x * blockDim.x) {
        float4 x = ((const float4*)s)[i];
        dh[2 * i]     = __floats2half2_rn(x.x, x.y);
        dh[2 * i + 1] = __floats2half2_rn(x.z, x.w);
    }
}

// V transpose per (b,h): g_V[key][h*HD+d] -> g_Vt[(b,h)][d][key]
__global__ __launch_bounds__(256) void vtrans_kernel() {
    __shared__ __half tile[32][40];
    int bh = blockIdx.z, b = bh >> 4, h = bh & 15;
    int k0 = blockIdx.x * 32, d0 = blockIdx.y * 32;
    int tx = threadIdx.x, ty = threadIdx.y;
    #pragma unroll
    for (int i = 0; i < 4; i++)
        tile[ty + i * 8][tx] =
            g_V[(size_t)(b * NK_ + k0 + ty + i * 8) * D_ + h * HD_ + d0 + tx];
    __syncthreads();
    #pragma unroll
    for (int i = 0; i < 4; i++)
        g_Vt[(size_t)(bh * HD_ + d0 + ty + i * 8) * NK_ + k0 + tx] =
            tile[tx][ty + i * 8];
}

// ---------------------------------------------------------------------------
// fp16 GEMM: Y = X[m][k] @ Wt[n][k]^T + bias.  BK=64 halves (128B rows),
// stride 72 halves (144B ≡ 16 mod 128 -> ldmatrix conflict-free).
// m16n8k16 HMMA, fp32 accum. MODE 1: store fp16*(scale); MODE 0: store fp32.
// ---------------------------------------------------------------------------
#define GS   72
#define GSTG 3
#define GEMM_SMEM128 ((GSTG * 128 * GS + GSTG * 128 * GS) * 2)
#define GEMM_SMEM64  ((GSTG * 64  * GS + GSTG * 128 * GS) * 2)

template <int MODE, int MROWS>
__device__ __forceinline__ void gemm_body_f16(
    const __half* __restrict__ X, const __half* __restrict__ Wt,
    const float* __restrict__ bias, void* __restrict__ Yv,
    int m0, int n0, float outScale, __half* sA, __half* sB)
{
    const int K = 1024, N = 1024;
    const int MT = MROWS / 32;
    int tid  = threadIdx.x;
    int lane = tid & 31, warp = tid >> 5;
    int g = lane >> 2, t = lane & 3;
    int wm = (warp >> 2) * (MROWS / 2);
    int wn = (warp & 3) * 32;

    uint32_t sA_u = (uint32_t)__cvta_generic_to_shared(sA);
    uint32_t sB_u = (uint32_t)__cvta_generic_to_shared(sB);

    uint32_t a_base = (uint32_t)(((wm + (lane & 15)) * GS + ((lane & 16) ? 8 : 0)) * 2);
    uint32_t b_base = (uint32_t)(((wn + (lane & 7) + ((lane & 16) >> 1)) * GS
                                  + ((lane & 8) ? 8 : 0)) * 2);

    float acc[MT][4][4];
    #pragma unroll
    for (int i = 0; i < MT; i++)
        #pragma unroll
        for (int j = 0; j < 4; j++)
            #pragma unroll
            for (int c = 0; c < 4; c++) acc[i][j][c] = 0.f;

    auto issue = [&](int buf, int kc) {
        #pragma unroll
        for (int i = 0; i < MROWS / 32; i++) {
            int c = tid + i * 256;
            int row = c >> 3, col = (c & 7) * 8;
            cp16(sA_u + (uint32_t)(((buf * MROWS + row) * GS + col) * 2),
                 X + (size_t)(m0 + row) * K + kc * 64 + col);
        }
        #pragma unroll
        for (int i = 0; i < 4; i++) {
            int c = tid + i * 256;
            int row = c >> 3, col = (c & 7) * 8;
            cp16(sB_u + (uint32_t)(((buf * 128 + row) * GS + col) * 2),
                 Wt + (size_t)(n0 + row) * K + kc * 64 + col);
        }
    };

    issue(0, 0); cp_commit();
    issue(1, 1); cp_commit();

    #pragma unroll 1
    for (int kc = 0; kc < 16; kc++) {
        int buf = kc % GSTG;
        if (kc < 15) cp_wait<1>(); else cp_wait<0>();
        __syncthreads();
        if (kc + 2 < 16) {
            issue((kc + 2) % GSTG, kc + 2);
            cp_commit();
        }

        uint32_t A0 = sA_u + (uint32_t)(buf * MROWS * GS * 2) + a_base;
        uint32_t B0 = sB_u + (uint32_t)(buf * 128 * GS * 2) + b_base;

        #pragma unroll
        for (int kt = 0; kt < 4; kt++) {
            uint32_t a[MT][4], kb[2][4];
            #pragma unroll
            for (int mt = 0; mt < MT; mt++)
                ldsm4(a[mt], A0 + (uint32_t)((mt * 16 * GS + kt * 16) * 2));
            #pragma unroll
            for (int n2 = 0; n2 < 2; n2++)
                ldsm4(kb[n2], B0 + (uint32_t)((n2 * 16 * GS + kt * 16) * 2));
            #pragma unroll
            for (int mt = 0; mt < MT; mt++)
                #pragma unroll
                for (int nt = 0; nt < 4; nt++)
                    mma_f16(acc[mt][nt], a[mt], &kb[nt >> 1][(nt & 1) * 2]);
        }
    }

    #pragma unroll
    for (int mt = 0; mt < MT; mt++) {
        int row = m0 + wm + mt * 16 + g;
        #pragma unroll
        for (int nt = 0; nt < 4; nt++) {
            int col = n0 + wn + nt * 8 + 2 * t;
            float2 bb = *(const float2*)&bias[col];
            if (MODE == 1) {
                __half* Y = (__half*)Yv;
                *(__half2*)&Y[(size_t)row * N + col] =
                    __floats2half2_rn((acc[mt][nt][0] + bb.x) * outScale,
                                      (acc[mt][nt][1] + bb.y) * outScale);
                *(__half2*)&Y[(size_t)(row + 8) * N + col] =
                    __floats2half2_rn((acc[mt][nt][2] + bb.x) * outScale,
                                      (acc[mt][nt][3] + bb.y) * outScale);
            } else {
                float* Y = (float*)Yv;
                float2 o0 = make_float2(acc[mt][nt][0] + bb.x, acc[mt][nt][1] + bb.y);
                float2 o1 = make_float2(acc[mt][nt][2] + bb.x, acc[mt][nt][3] + bb.y);
                *(float2*)&Y[(size_t)row * N + col]       = o0;
                *(float2*)&Y[(size_t)(row + 8) * N + col] = o1;
            }
        }
    }
}

__global__ __launch_bounds__(256, 2) void qkv_proj_kernel(
    const float* __restrict__ bq, const float* __restrict__ bk,
    const float* __restrict__ bv)
{
    extern __shared__ __half smh[];
    int y = blockIdx.y;
    const __half *X, *W; const float* bias; __half* Y; int m0; float sc;
    if (y < 16)      { X = g_Xh;                     W = g_Wt;               bias = bq; Y = g_Q; m0 = y * 128;        sc = SCALE_; }
    else if (y < 48) { X = g_Xh + (size_t)2048 * D_; W = g_Wt + 1 * D_ * D_; bias = bk; Y = g_K; m0 = (y - 16) * 128; sc = 1.0f;   }
    else             { X = g_Xh + (size_t)6144 * D_; W = g_Wt + 2 * D_ * D_; bias = bv; Y = g_V; m0 = (y - 48) * 128; sc = 1.0f;   }
    gemm_body_f16<1, 128>(X, W, bias, Y, m0, blockIdx.x * 128, sc,
                          smh, smh + GSTG * 128 * GS);
}

__global__ __launch_bounds__(256, 2) void oproj_kernel(
    const float* __restrict__ bo, float* __restrict__ out)
{
    extern __shared__ __half smh[];
    gemm_body_f16<0, 64>(g_ctx, g_Wt + 3 * D_ * D_, bo, out,
                         blockIdx.y * 64, blockIdx.x * 128, 1.0f,
                         smh, smh + GSTG * 64 * GS);
}

// ---------------------------------------------------------------------------
// fp16 flash attention. Same structure as R9 but m16n8k16 (half the MMAs).
// ---------------------------------------------------------------------------
#define SH 72
#define ATTN_SMEM ((2 * 64 * SH + 2 * 64 * SH + 128 * SH) * 2)

__global__ __launch_bounds__(256, 2) void attn_f16_kernel(
    const float* __restrict__ bias, __half* __restrict__ ctx)
{
    extern __shared__ __half smh[];
    __half* sK  = smh;                          // [2][64][SH] keys x d
    __half* sVt = smh + 2 * 64 * SH;            // [2][64][SH] d x keys
    __half* sP  = smh + 4 * 64 * SH;            // [128][SH]   Q then P

    int tid = threadIdx.x, lane = tid & 31, warp = tid >> 5;
    int g = lane >> 2, t = lane & 3;
    int b = blockIdx.z, h = blockIdx.y, q0 = blockIdx.x * 128;
    int wq = warp * 16;

    const __half* Qg  = g_Q + (size_t)(b * NQ_ + q0) * D_ + h * HD_;
    const __half* Kg  = g_K + (size_t)b * NK_ * D_ + h * HD_;
    const __half* Vtg = g_Vt + (size_t)(b * H_ + h) * HD_ * NK_;
    const float* biasg = bias + (((size_t)b * H_ + h) * NQ_ + q0) * NK_;
    const float* mg = g_maskf + b * NK_;

    uint32_t sK_u  = (uint32_t)__cvta_generic_to_shared(sK);
    uint32_t sVt_u = (uint32_t)__cvta_generic_to_shared(sVt);
    uint32_t sP_u  = (uint32_t)__cvta_generic_to_shared(sP);

    int arow = wq + (lane & 15);
    int acolh = (lane & 16) ? 8 : 0;
    int brow = (lane & 7) + ((lane & 16) >> 1);
    int bcolh = (lane & 8) ? 8 : 0;

    auto issueKV = [&](int buf, int k0) {
        #pragma unroll
        for (int i = 0; i < 2; i++) {
            int c = tid + i * 256;              // 0..511
            int row = c >> 3, col = (c & 7) * 8;
            cp16(sK_u + (uint32_t)(((buf * 64 + row) * SH + col) * 2),
                 Kg + (size_t)(k0 + row) * D_ + col);
            cp16(sVt_u + (uint32_t)(((buf * 64 + row) * SH + col) * 2),
                 Vtg + (size_t)row * NK_ + k0 + col);
        }
    };

    issueKV(0, 0);
    cp_commit();

    // Stage Q (fp16, pre-scaled) into sP
    #pragma unroll
    for (int i = 0; i < 4; i++) {
        int c = tid + i * 256;                  // 0..1023
        int row = c >> 3, col = (c & 7) * 8;
        *(uint4*)&sP[row * SH + col] = *(const uint4*)&Qg[(size_t)row * D_ + col];
    }
    __syncthreads();

    uint32_t qf[4][4];
    #pragma unroll
    for (int kt = 0; kt < 4; kt++)
        ldsm4(qf[kt], sP_u + (uint32_t)((arow * SH + kt * 16 + acolh) * 2));

    float oacc[8][4];
    #pragma unroll
    for (int nt = 0; nt < 8; nt++)
        #pragma unroll
        for (int c = 0; c < 4; c++) oacc[nt][c] = 0.f;
    float mr0 = -INFINITY, mr1 = -INFINITY, l0 = 0.f, l1 = 0.f;

    #pragma unroll 1
    for (int it = 0; it < NK_ / 64; it++) {
        int buf = it & 1, k0 = it * 64;

        // bias pre-loaded into accumulators; LDG latency hidden by wait+barrier
        float sacc[8][4];
        #pragma unroll
        for (int nt = 0; nt < 8; nt++) {
            int kc = k0 + nt * 8 + 2 * t;
            float2 b0v = *(const float2*)&biasg[(size_t)(wq + g) * NK_ + kc];
            float2 b1v = *(const float2*)&biasg[(size_t)(wq + g + 8) * NK_ + kc];
            sacc[nt][0] = b0v.x; sacc[nt][1] = b0v.y;
            sacc[nt][2] = b1v.x; sacc[nt][3] = b1v.y;
        }

        cp_wait<0>();
        __syncthreads();
        if (it < NK_ / 64 - 1) {
            issueKV(buf ^ 1, k0 + 64);
            cp_commit();
        }

        uint32_t K0_u = sK_u  + (uint32_t)(buf * 64 * SH * 2);
        uint32_t V0_u = sVt_u + (uint32_t)(buf * 64 * SH * 2);

        // S = Q K^T : 4 kt x 8 nt m16n8k16
        #pragma unroll
        for (int kt = 0; kt < 4; kt++) {
            uint32_t kb[4][4];
            #pragma unroll
            for (int n2 = 0; n2 < 4; n2++)
                ldsm4(kb[n2], K0_u +
                      (uint32_t)(((n2 * 16 + brow) * SH + kt * 16 + bcolh) * 2));
            #pragma unroll
            for (int nt = 0; nt < 8; nt++)
                mma_f16(sacc[nt], qf[kt], &kb[nt >> 1][(nt & 1) * 2]);
        }

        float rmax0 = -INFINITY, rmax1 = -INFINITY;
        #pragma unroll
        for (int nt = 0; nt < 8; nt++) {
            int kc = k0 + nt * 8 + 2 * t;
            float2 mk = *(const float2*)&mg[kc];
            if (mk.x != 0.f) { sacc[nt][0] = -INFINITY; sacc[nt][2] = -INFINITY; }
            if (mk.y != 0.f) { sacc[nt][1] = -INFINITY; sacc[nt][3] = -INFINITY; }
            rmax0 = fmaxf(rmax0, fmaxf(sacc[nt][0], sacc[nt][1]));
            rmax1 = fmaxf(rmax1, fmaxf(sacc[nt][2], sacc[nt][3]));
        }
        rmax0 = fmaxf(rmax0, __shfl_xor_sync(0xffffffffu, rmax0, 1));
        rmax0 = fmaxf(rmax0, __shfl_xor_sync(0xffffffffu, rmax0, 2));
        rmax1 = fmaxf(rmax1, __shfl_xor_sync(0xffffffffu, rmax1, 1));
        rmax1 = fmaxf(rmax1, __shfl_xor_sync(0xffffffffu, rmax1, 2));

        float mn0 = fmaxf(mr0, rmax0), mn1 = fmaxf(mr1, rmax1);
        bool dead0 = (mn0 == -INFINITY), dead1 = (mn1 == -INFINITY);
        float al0 = dead0 ? 1.f : __expf(mr0 - mn0);
        float al1 = dead1 ? 1.f : __expf(mr1 - mn1);
        float sum0 = 0.f, sum1 = 0.f;

        #pragma unroll
        for (int nt = 0; nt < 8; nt++) {
            float p00 = dead0 ? 0.f : __expf(sacc[nt][0] - mn0);
            float p01 = dead0 ? 0.f : __expf(sacc[nt][1] - mn0);
            float p10 = dead1 ? 0.f : __expf(sacc[nt][2] - mn1);
            float p11 = dead1 ? 0.f : __expf(sacc[nt][3] - mn1);
            sum0 += p00 + p01;
            sum1 += p10 + p11;
            *(__half2*)&sP[(wq + g) * SH + nt * 8 + 2 * t]     = __floats2half2_rn(p00, p01);
            *(__half2*)&sP[(wq + g + 8) * SH + nt * 8 + 2 * t] = __floats2half2_rn(p10, p11);
        }
        sum0 += __shfl_xor_sync(0xffffffffu, sum0, 1);
        sum0 += __shfl_xor_sync(0xffffffffu, sum0, 2);
        sum1 += __shfl_xor_sync(0xffffffffu, sum1, 1);
        sum1 += __shfl_xor_sync(0xffffffffu, sum1, 2);

        mr0 = mn0; mr1 = mn1;
        l0 = l0 * al0 + sum0;
        l1 = l1 * al1 + sum1;
        #pragma unroll
        for (int nt = 0; nt < 8; nt++) {
            oacc[nt][0] *= al0; oacc[nt][1] *= al0;
            oacc[nt][2] *= al1; oacc[nt][3] *= al1;
        }
        __syncwarp();   // P rows warp-private

        // O += P @ V : 4 kt x 8 nt
        #pragma unroll
        for (int kt = 0; kt < 4; kt++) {
            uint32_t pa[4];
            ldsm4(pa, sP_u + (uint32_t)((arow * SH + kt * 16 + acolh) * 2));
            uint32_t vb[4][4];
            #pragma unroll
            for (int n2 = 0; n2 < 4; n2++)
                ldsm4(vb[n2], V0_u +
                      (uint32_t)(((n2 * 16 + brow) * SH + kt * 16 + bcolh) * 2));
            #pragma unroll
            for (int nt = 0; nt < 8; nt++)
                mma_f16(oacc[nt], pa, &vb[nt >> 1][(nt & 1) * 2]);
        }
    }

    float inv0 = 1.f / l0, inv1 = 1.f / l1;
    size_t row0 = (size_t)(b * NQ_ + q0 + wq + g) * D_ + h * HD_;
    size_t row1 = row0 + 8 * D_;
    #pragma unroll
    for (int nt = 0; nt < 8; nt++) {
        int col = nt * 8 + 2 * t;
        *(__half2*)&ctx[row0 + col] =
            __floats2half2_rn(oacc[nt][0] * inv0, oacc[nt][1] * inv0);
        *(__half2*)&ctx[row1 + col] =
            __floats2half2_rn(oacc[nt][2] * inv1, oacc[nt][3] * inv1);
    }
}

extern "C" void kernel_launch(void* const* d_in, const int* in_sizes, int n_in,
                              void* d_out, int out_size)
{
    const float* q  = (const float*)d_in[0];
    const float* k  = (const float*)d_in[1];
    const float* v  = (const float*)d_in[2];
    const float* ab = (const float*)d_in[3];
    const void*  mk = d_in[4];
    const float* Wq = (const float*)d_in[5];
    const float* bq = (const float*)d_in[6];
    const float* Wk = (const float*)d_in[7];
    const float* bk = (const float*)d_in[8];
    const float* Wv = (const float*)d_in[9];
    const float* bv = (const float*)d_in[10];
    const float* Wo = (const float*)d_in[11];
    const float* bo = (const float*)d_in[12];
    float* out = (float*)d_out;

    static int smem_set = 0;
    if (!smem_set) {
        cudaFuncSetAttribute(qkv_proj_kernel,
                             cudaFuncAttributeMaxDynamicSharedMemorySize, GEMM_SMEM128);
        cudaFuncSetAttribute(oproj_kernel,
                             cudaFuncAttributeMaxDynamicSharedMemorySize, GEMM_SMEM64);
        cudaFuncSetAttribute(attn_f16_kernel,
                             cudaFuncAttributeMaxDynamicSharedMemorySize, ATTN_SMEM);
        smem_set = 1;
    }

    __half* gctx;
    cudaGetSymbolAddress((void**)&gctx, g_ctx);

    detect_mask_kernel<<<1, 256>>>((const unsigned char*)mk);
    prep_mask_kernel<<<B_, 256>>>(mk);
    wtrans_kernel<<<dim3(32, 32, 4), 256>>>(Wq, Wk, Wv, Wo);
    cvt_x_kernel<<<dim3(256, 3), 256>>>(q, k, v);

    qkv_proj_kernel<<<dim3(8, 80), 256, GEMM_SMEM128>>>(bq, bk, bv);

    vtrans_kernel<<<dim3(NK_ / 32, HD_ / 32, B_ * H_), dim3(32, 8)>>>();

    attn_f16_kernel<<<dim3(NQ_ / 128, H_, B_), 256, ATTN_SMEM>>>(ab, gctx);

    oproj_kernel<<<dim3(8, 32), 256, GEMM_SMEM64>>>(bo, out);
}

// round 12
// speedup vs baseline: 5.8281x; 1.0074x over previous
#include <cuda_runtime.h>
#include <cuda_fp16.h>
#include <math.h>
#include <stdint.h>

#define B_     2
#define NQ_    1024
#define NK_    2048
#define D_     1024
#define H_     16
#define HD_    64
#define SCALE_ 0.125f

// fp16 operand storage (10-bit mantissa == tf32; all values O(1), range safe)
__device__ __half g_Q[(size_t)B_ * NQ_ * D_];        // pre-scaled by 0.125
__device__ __half g_K[(size_t)B_ * NK_ * D_];
__device__ __half g_Vt[(size_t)B_ * H_ * HD_ * NK_]; // V^T per (b,h): [d][key]
__device__ __half g_ctx[(size_t)B_ * NQ_ * D_];
__device__ __half g_Wt[(size_t)4 * D_ * D_];         // transposed Wq|Wk|Wv|Wo
__device__ __half g_Xh[(size_t)10240 * D_];          // inputs q|k|v
__device__ float  g_maskf[B_ * NK_];
__device__ int    g_mask_mode;

__device__ __forceinline__ void mma_f16(float* d, const uint32_t* a, const uint32_t* b) {
    asm volatile(
        "mma.sync.aligned.m16n8k16.row.col.f32.f16.f16.f32 "
        "{%0,%1,%2,%3}, {%4,%5,%6,%7}, {%8,%9}, {%0,%1,%2,%3};"
        : "+f"(d[0]), "+f"(d[1]), "+f"(d[2]), "+f"(d[3])
        : "r"(a[0]), "r"(a[1]), "r"(a[2]), "r"(a[3]),
          "r"(b[0]), "r"(b[1]));
}

__device__ __forceinline__ void ldsm4(uint32_t* r, uint32_t addr) {
    asm volatile("ldmatrix.sync.aligned.m8n8.x4.shared.b16 {%0,%1,%2,%3}, [%4];"
                 : "=r"(r[0]), "=r"(r[1]), "=r"(r[2]), "=r"(r[3]) : "r"(addr));
}

__device__ __forceinline__ void cp16(uint32_t dst, const void* src) {
    asm volatile("cp.async.cg.shared.global [%0], [%1], 16;" :: "r"(dst), "l"(src));
}
__device__ __forceinline__ void cp_commit() { asm volatile("cp.async.commit_group;"); }
template <int N> __device__ __forceinline__ void cp_wait() {
    asm volatile("cp.async.wait_group %0;" :: "n"(N));
}

// streaming (evict-first) float2 load for the 256MB bias stream
__device__ __forceinline__ float2 ldcs2(const float* p) {
    float2 v;
    asm volatile("ld.global.cs.v2.f32 {%0,%1}, [%2];"
                 : "=f"(v.x), "=f"(v.y) : "l"(p));
    return v;
}

__global__ void detect_mask_kernel(const unsigned char* __restrict__ p) {
    __shared__ int s_nonbin, s_unal;
    int tid = threadIdx.x;
    if (tid == 0) { s_nonbin = 0; s_unal = 0; }
    __syncthreads();
    for (int i = tid; i < B_ * NK_; i += 256) {
        unsigned char v = p[i];
        if (v > 1) s_nonbin = 1;
        else if (v == 1 && (i & 3)) s_unal = 1;
    }
    __syncthreads();
    if (tid == 0) g_mask_mode = s_nonbin ? 2 : (s_unal ? 0 : 1);
}

__global__ void prep_mask_kernel(const void* __restrict__ mptr) {
    int b = blockIdx.x;
    int tid = threadIdx.x;
    __shared__ int anyUnmasked;
    if (tid == 0) anyUnmasked = 0;
    __syncthreads();
    int mode = g_mask_mode;
    float vals[NK_ / 256];
    #pragma unroll
    for (int x = 0; x < NK_ / 256; x++) {
        int i = tid + x * 256;
        float m;
        if (mode == 0)      m = ((const unsigned char*)mptr)[b * NK_ + i] ? 1.f : 0.f;
        else if (mode == 1) m = ((const int*)mptr)[b * NK_ + i] ? 1.f : 0.f;
        else                m = (((const float*)mptr)[b * NK_ + i] != 0.f) ? 1.f : 0.f;
        vals[x] = m;
        if (m == 0.f) anyUnmasked = 1;
    }
    __syncthreads();
    #pragma unroll
    for (int x = 0; x < NK_ / 256; x++) {
        int i = tid + x * 256;
        float m = vals[x];
        if (i == 0 && !anyUnmasked) m = 0.f;
        g_maskf[b * NK_ + i] = m;
    }
}

// Transpose + fp16-round weights: W[k][n] -> Wt[n][k]
__global__ __launch_bounds__(256) void wtrans_kernel(
    const float* __restrict__ w0, const float* __restrict__ w1,
    const float* __restrict__ w2, const float* __restrict__ w3)
{
    __shared__ float tile[32][33];
    int which = blockIdx.z;
    const float* s = (which == 0) ? w0 : (which == 1) ? w1 : (which == 2) ? w2 : w3;
    __half* d = g_Wt + (size_t)which * D_ * D_;
    int k0 = blockIdx.x * 32, n0 = blockIdx.y * 32;
    int tx = threadIdx.x & 31, ty = threadIdx.x >> 5;
    #pragma unroll
    for (int i = 0; i < 4; i++)
        tile[ty + i * 8][tx] = s[(size_t)(k0 + ty + i * 8) * D_ + n0 + tx];
    __syncthreads();
    #pragma unroll
    for (int i = 0; i < 4; i++)
        d[(size_t)(n0 + ty + i * 8) * D_ + k0 + tx] =
            __float2half_rn(tile[tx][ty + i * 8]);
}

// Convert raw q/k/v inputs to fp16
__global__ __launch_bounds__(256) void cvt_x_kernel(
    const float* __restrict__ q, const float* __restrict__ k, const float* __restrict__ v)
{
    int which = blockIdx.y;
    const float* s; __half* d; int n;
    if (which == 0)      { s = q; d = g_Xh;                     n = B_ * NQ_ * D_; }
    else if (which == 1) { s = k; d = g_Xh + (size_t)2048 * D_; n = B_ * NK_ * D_; }
    else                 { s = v; d = g_Xh + (size_t)6144 * D_; n = B_ * NK_ * D_; }
    __half2* dh = (__half2*)d;
    for (int i = blockIdx.x * blockDim.x + threadIdx.x;
         i < n / 4; i += gridDim.x * blockDim.x) {
        float4 x = ((const float4*)s)[i];
        dh[2 * i]     = __floats2half2_rn(x.x, x.y);
        dh[2 * i + 1] = __floats2half2_rn(x.z, x.w);
    }
}

// ---------------------------------------------------------------------------
// fp16 GEMM: Y = X[m][k] @ Wt[n][k]^T + bias.  BK=64 halves (128B rows),
// stride 72 halves (144B ≡ 16 mod 128 -> ldmatrix conflict-free).
// m16n8k16 HMMA, fp32 accum. 64-row CTA tiles (wave balance).
// mode 0: fp32 store. mode 1: fp16*(scale) store. mode 2: scatter into g_Vt.
// ---------------------------------------------------------------------------
#define GS   72
#define GSTG 3
#define GEMM_SMEM ((GSTG * 64 * GS + GSTG * 128 * GS) * 2)

__device__ __forceinline__ void gemm_body_f16(
    const __half* __restrict__ X, const __half* __restrict__ Wt,
    const float* __restrict__ bias, void* __restrict__ Yv,
    int m0, int n0, float outScale, int mode, __half* sA, __half* sB)
{
    const int K = 1024, N = 1024, MROWS = 64, MT = 2;
    int tid  = threadIdx.x;
    int lane = tid & 31, warp = tid >> 5;
    int g = lane >> 2, t = lane & 3;
    int wm = (warp >> 2) * 32;
    int wn = (warp & 3) * 32;

    uint32_t sA_u = (uint32_t)__cvta_generic_to_shared(sA);
    uint32_t sB_u = (uint32_t)__cvta_generic_to_shared(sB);

    uint32_t a_base = (uint32_t)(((wm + (lane & 15)) * GS + ((lane & 16) ? 8 : 0)) * 2);
    uint32_t b_base = (uint32_t)(((wn + (lane & 7) + ((lane & 16) >> 1)) * GS
                                  + ((lane & 8) ? 8 : 0)) * 2);

    float acc[MT][4][4];
    #pragma unroll
    for (int i = 0; i < MT; i++)
        #pragma unroll
        for (int j = 0; j < 4; j++)
            #pragma unroll
            for (int c = 0; c < 4; c++) acc[i][j][c] = 0.f;

    auto issue = [&](int buf, int kc) {
        #pragma unroll
        for (int i = 0; i < MT; i++) {
            int c = tid + i * 256;
            int row = c >> 3, col = (c & 7) * 8;
            cp16(sA_u + (uint32_t)(((buf * MROWS + row) * GS + col) * 2),
                 X + (size_t)(m0 + row) * K + kc * 64 + col);
        }
        #pragma unroll
        for (int i = 0; i < 4; i++) {
            int c = tid + i * 256;
            int row = c >> 3, col = (c & 7) * 8;
            cp16(sB_u + (uint32_t)(((buf * 128 + row) * GS + col) * 2),
                 Wt + (size_t)(n0 + row) * K + kc * 64 + col);
        }
    };

    issue(0, 0); cp_commit();
    issue(1, 1); cp_commit();

    #pragma unroll 1
    for (int kc = 0; kc < 16; kc++) {
        int buf = kc % GSTG;
        if (kc < 15) cp_wait<1>(); else cp_wait<0>();
        __syncthreads();
        if (kc + 2 < 16) {
            issue((kc + 2) % GSTG, kc + 2);
            cp_commit();
        }

        uint32_t A0 = sA_u + (uint32_t)(buf * MROWS * GS * 2) + a_base;
        uint32_t B0 = sB_u + (uint32_t)(buf * 128 * GS * 2) + b_base;

        #pragma unroll
        for (int kt = 0; kt < 4; kt++) {
            uint32_t a[MT][4], kb[2][4];
            #pragma unroll
            for (int mt = 0; mt < MT; mt++)
                ldsm4(a[mt], A0 + (uint32_t)((mt * 16 * GS + kt * 16) * 2));
            #pragma unroll
            for (int n2 = 0; n2 < 2; n2++)
                ldsm4(kb[n2], B0 + (uint32_t)((n2 * 16 * GS + kt * 16) * 2));
            #pragma unroll
            for (int mt = 0; mt < MT; mt++)
                #pragma unroll
                for (int nt = 0; nt < 4; nt++)
                    mma_f16(acc[mt][nt], a[mt], &kb[nt >> 1][(nt & 1) * 2]);
        }
    }

    #pragma unroll
    for (int mt = 0; mt < MT; mt++) {
        int row = m0 + wm + mt * 16 + g;
        #pragma unroll
        for (int nt = 0; nt < 4; nt++) {
            int col = n0 + wn + nt * 8 + 2 * t;
            float2 bb = *(const float2*)&bias[col];
            if (mode == 1) {
                __half* Y = (__half*)Yv;
                *(__half2*)&Y[(size_t)row * N + col] =
                    __floats2half2_rn((acc[mt][nt][0] + bb.x) * outScale,
                                      (acc[mt][nt][1] + bb.y) * outScale);
                *(__half2*)&Y[(size_t)(row + 8) * N + col] =
                    __floats2half2_rn((acc[mt][nt][2] + bb.x) * outScale,
                                      (acc[mt][nt][3] + bb.y) * outScale);
            } else if (mode == 2) {
                // V projection: scatter directly into g_Vt[(b*16+h)*64+d][key]
                __half* Vt = (__half*)Yv;
                int b   = row >> 11;           // row = b*NK + key
                int key = row & (NK_ - 1);
                int h   = col >> 6, d = col & 63;
                size_t base = ((size_t)((b * H_ + h) * HD_ + d)) * NK_ + key;
                Vt[base]            = __float2half_rn(acc[mt][nt][0] + bb.x);
                Vt[base + NK_]      = __float2half_rn(acc[mt][nt][1] + bb.y);
                Vt[base + 8]        = __float2half_rn(acc[mt][nt][2] + bb.x);
                Vt[base + NK_ + 8]  = __float2half_rn(acc[mt][nt][3] + bb.y);
            } else {
                float* Y = (float*)Yv;
                float2 o0 = make_float2(acc[mt][nt][0] + bb.x, acc[mt][nt][1] + bb.y);
                float2 o1 = make_float2(acc[mt][nt][2] + bb.x, acc[mt][nt][3] + bb.y);
                *(float2*)&Y[(size_t)row * N + col]       = o0;
                *(float2*)&Y[(size_t)(row + 8) * N + col] = o1;
            }
        }
    }
}

__global__ __launch_bounds__(256, 2) void qkv_proj_kernel(
    const float* __restrict__ bq, const float* __restrict__ bk,
    const float* __restrict__ bv)
{
    extern __shared__ __half smh[];
    int y = blockIdx.y;
    const __half *X, *W; const float* bias; void* Y; int m0; float sc; int mode;
    if (y < 32)      { X = g_Xh;                     W = g_Wt;               bias = bq; Y = g_Q;  m0 = y * 64;        sc = SCALE_; mode = 1; }
    else if (y < 96) { X = g_Xh + (size_t)2048 * D_; W = g_Wt + 1 * D_ * D_; bias = bk; Y = g_K;  m0 = (y - 32) * 64; sc = 1.0f;   mode = 1; }
    else             { X = g_Xh + (size_t)6144 * D_; W = g_Wt + 2 * D_ * D_; bias = bv; Y = g_Vt; m0 = (y - 96) * 64; sc = 1.0f;   mode = 2; }
    gemm_body_f16(X, W, bias, Y, m0, blockIdx.x * 128, sc, mode,
                  smh, smh + GSTG * 64 * GS);
}

__global__ __launch_bounds__(256, 2) void oproj_kernel(
    const float* __restrict__ bo, float* __restrict__ out)
{
    extern __shared__ __half smh[];
    gemm_body_f16(g_ctx, g_Wt + 3 * D_ * D_, bo, out,
                  blockIdx.y * 64, blockIdx.x * 128, 1.0f, 0,
                  smh, smh + GSTG * 64 * GS);
}

// ---------------------------------------------------------------------------
// fp16 flash attention (m16n8k16), bias pre-loaded into accumulators with
// streaming (evict-first) loads so the 256MB bias stream doesn't evict K/V.
// ---------------------------------------------------------------------------
#define SH 72
#define ATTN_SMEM ((2 * 64 * SH + 2 * 64 * SH + 128 * SH) * 2)

__global__ __launch_bounds__(256, 2) void attn_f16_kernel(
    const float* __restrict__ bias, __half* __restrict__ ctx)
{
    extern __shared__ __half smh[];
    __half* sK  = smh;                          // [2][64][SH] keys x d
    __half* sVt = smh + 2 * 64 * SH;            // [2][64][SH] d x keys
    __half* sP  = smh + 4 * 64 * SH;            // [128][SH]   Q then P

    int tid = threadIdx.x, lane = tid & 31, warp = tid >> 5;
    int g = lane >> 2, t = lane & 3;
    int b = blockIdx.z, h = blockIdx.y, q0 = blockIdx.x * 128;
    int wq = warp * 16;

    const __half* Qg  = g_Q + (size_t)(b * NQ_ + q0) * D_ + h * HD_;
    const __half* Kg  = g_K + (size_t)b * NK_ * D_ + h * HD_;
    const __half* Vtg = g_Vt + (size_t)(b * H_ + h) * HD_ * NK_;
    const float* biasg = bias + (((size_t)b * H_ + h) * NQ_ + q0) * NK_;
    const float* mg = g_maskf + b * NK_;

    uint32_t sK_u  = (uint32_t)__cvta_generic_to_shared(sK);
    uint32_t sVt_u = (uint32_t)__cvta_generic_to_shared(sVt);
    uint32_t sP_u  = (uint32_t)__cvta_generic_to_shared(sP);

    int arow = wq + (lane & 15);
    int acolh = (lane & 16) ? 8 : 0;
    int brow = (lane & 7) + ((lane & 16) >> 1);
    int bcolh = (lane & 8) ? 8 : 0;

    auto issueKV = [&](int buf, int k0) {
        #pragma unroll
        for (int i = 0; i < 2; i++) {
            int c = tid + i * 256;              // 0..511
            int row = c >> 3, col = (c & 7) * 8;
            cp16(sK_u + (uint32_t)(((buf * 64 + row) * SH + col) * 2),
                 Kg + (size_t)(k0 + row) * D_ + col);
            cp16(sVt_u + (uint32_t)(((buf * 64 + row) * SH + col) * 2),
                 Vtg + (size_t)row * NK_ + k0 + col);
        }
    };

    issueKV(0, 0);
    cp_commit();

    // Stage Q (fp16, pre-scaled) into sP
    #pragma unroll
    for (int i = 0; i < 4; i++) {
        int c = tid + i * 256;                  // 0..1023
        int row = c >> 3, col = (c & 7) * 8;
        *(uint4*)&sP[row * SH + col] = *(const uint4*)&Qg[(size_t)row * D_ + col];
    }
    __syncthreads();

    uint32_t qf[4][4];
    #pragma unroll
    for (int kt = 0; kt < 4; kt++)
        ldsm4(qf[kt], sP_u + (uint32_t)((arow * SH + kt * 16 + acolh) * 2));

    float oacc[8][4];
    #pragma unroll
    for (int nt = 0; nt < 8; nt++)
        #pragma unroll
        for (int c = 0; c < 4; c++) oacc[nt][c] = 0.f;
    float mr0 = -INFINITY, mr1 = -INFINITY, l0 = 0.f, l1 = 0.f;

    #pragma unroll 1
    for (int it = 0; it < NK_ / 64; it++) {
        int buf = it & 1, k0 = it * 64;

        // bias pre-loaded (streaming) into accumulators; latency hidden by
        // the cp.async wait + barrier below.
        float sacc[8][4];
        #pragma unroll
        for (int nt = 0; nt < 8; nt++) {
            int kc = k0 + nt * 8 + 2 * t;
            float2 b0v = ldcs2(&biasg[(size_t)(wq + g) * NK_ + kc]);
            float2 b1v = ldcs2(&biasg[(size_t)(wq + g + 8) * NK_ + kc]);
            sacc[nt][0] = b0v.x; sacc[nt][1] = b0v.y;
            sacc[nt][2] = b1v.x; sacc[nt][3] = b1v.y;
        }

        cp_wait<0>();
        __syncthreads();
        if (it < NK_ / 64 - 1) {
            issueKV(buf ^ 1, k0 + 64);
            cp_commit();
        }

        uint32_t K0_u = sK_u  + (uint32_t)(buf * 64 * SH * 2);
        uint32_t V0_u = sVt_u + (uint32_t)(buf * 64 * SH * 2);

        // S = Q K^T : 4 kt x 8 nt m16n8k16
        #pragma unroll
        for (int kt = 0; kt < 4; kt++) {
            uint32_t kb[4][4];
            #pragma unroll
            for (int n2 = 0; n2 < 4; n2++)
                ldsm4(kb[n2], K0_u +
                      (uint32_t)(((n2 * 16 + brow) * SH + kt * 16 + bcolh) * 2));
            #pragma unroll
            for (int nt = 0; nt < 8; nt++)
                mma_f16(sacc[nt], qf[kt], &kb[nt >> 1][(nt & 1) * 2]);
        }

        float rmax0 = -INFINITY, rmax1 = -INFINITY;
        #pragma unroll
        for (int nt = 0; nt < 8; nt++) {
            int kc = k0 + nt * 8 + 2 * t;
            float2 mk = *(const float2*)&mg[kc];
            if (mk.x != 0.f) { sacc[nt][0] = -INFINITY; sacc[nt][2] = -INFINITY; }
            if (mk.y != 0.f) { sacc[nt][1] = -INFINITY; sacc[nt][3] = -INFINITY; }
            rmax0 = fmaxf(rmax0, fmaxf(sacc[nt][0], sacc[nt][1]));
            rmax1 = fmaxf(rmax1, fmaxf(sacc[nt][2], sacc[nt][3]));
        }
        rmax0 = fmaxf(rmax0, __shfl_xor_sync(0xffffffffu, rmax0, 1));
        rmax0 = fmaxf(rmax0, __shfl_xor_sync(0xffffffffu, rmax0, 2));
        rmax1 = fmaxf(rmax1, __shfl_xor_sync(0xffffffffu, rmax1, 1));
        rmax1 = fmaxf(rmax1, __shfl_xor_sync(0xffffffffu, rmax1, 2));

        float mn0 = fmaxf(mr0, rmax0), mn1 = fmaxf(mr1, rmax1);
        bool dead0 = (mn0 == -INFINITY), dead1 = (mn1 == -INFINITY);
        float al0 = dead0 ? 1.f : __expf(mr0 - mn0);
        float al1 = dead1 ? 1.f : __expf(mr1 - mn1);
        float sum0 = 0.f, sum1 = 0.f;

        #pragma unroll
        for (int nt = 0; nt < 8; nt++) {
            float p00 = dead0 ? 0.f : __expf(sacc[nt][0] - mn0);
            float p01 = dead0 ? 0.f : __expf(sacc[nt][1] - mn0);
            float p10 = dead1 ? 0.f : __expf(sacc[nt][2] - mn1);
            float p11 = dead1 ? 0.f : __expf(sacc[nt][3] - mn1);
            sum0 += p00 + p01;
            sum1 += p10 + p11;
            *(__half2*)&sP[(wq + g) * SH + nt * 8 + 2 * t]     = __floats2half2_rn(p00, p01);
            *(__half2*)&sP[(wq + g + 8) * SH + nt * 8 + 2 * t] = __floats2half2_rn(p10, p11);
        }
        sum0 += __shfl_xor_sync(0xffffffffu, sum0, 1);
        sum0 += __shfl_xor_sync(0xffffffffu, sum0, 2);
        sum1 += __shfl_xor_sync(0xffffffffu, sum1, 1);
        sum1 += __shfl_xor_sync(0xffffffffu, sum1, 2);

        mr0 = mn0; mr1 = mn1;
        l0 = l0 * al0 + sum0;
        l1 = l1 * al1 + sum1;
        #pragma unroll
        for (int nt = 0; nt < 8; nt++) {
            oacc[nt][0] *= al0; oacc[nt][1] *= al0;
            oacc[nt][2] *= al1; oacc[nt][3] *= al1;
        }
        __syncwarp();   // P rows warp-private

        // O += P @ V : 4 kt x 8 nt
        #pragma unroll
        for (int kt = 0; kt < 4; kt++) {
            uint32_t pa[4];
            ldsm4(pa, sP_u + (uint32_t)((arow * SH + kt * 16 + acolh) * 2));
            uint32_t vb[4][4];
            #pragma unroll
            for (int n2 = 0; n2 < 4; n2++)
                ldsm4(vb[n2], V0_u +
                      (uint32_t)(((n2 * 16 + brow) * SH + kt * 16 + bcolh) * 2));
            #pragma unroll
            for (int nt = 0; nt < 8; nt++)
                mma_f16(oacc[nt], pa, &vb[nt >> 1][(nt & 1) * 2]);
        }
    }

    float inv0 = 1.f / l0, inv1 = 1.f / l1;
    size_t row0 = (size_t)(b * NQ_ + q0 + wq + g) * D_ + h * HD_;
    size_t row1 = row0 + 8 * D_;
    #pragma unroll
    for (int nt = 0; nt < 8; nt++) {
        int col = nt * 8 + 2 * t;
        *(__half2*)&ctx[row0 + col] =
            __floats2half2_rn(oacc[nt][0] * inv0, oacc[nt][1] * inv0);
        *(__half2*)&ctx[row1 + col] =
            __floats2half2_rn(oacc[nt][2] * inv1, oacc[nt][3] * inv1);
    }
}

extern "C" void kernel_launch(void* const* d_in, const int* in_sizes, int n_in,
                              void* d_out, int out_size)
{
    const float* q  = (const float*)d_in[0];
    const float* k  = (const float*)d_in[1];
    const float* v  = (const float*)d_in[2];
    const float* ab = (const float*)d_in[3];
    const void*  mk = d_in[4];
    const float* Wq = (const float*)d_in[5];
    const float* bq = (const float*)d_in[6];
    const float* Wk = (const float*)d_in[7];
    const float* bk = (const float*)d_in[8];
    const float* Wv = (const float*)d_in[9];
    const float* bv = (const float*)d_in[10];
    const float* Wo = (const float*)d_in[11];
    const float* bo = (const float*)d_in[12];
    float* out = (float*)d_out;

    static int smem_set = 0;
    if (!smem_set) {
        cudaFuncSetAttribute(qkv_proj_kernel,
                             cudaFuncAttributeMaxDynamicSharedMemorySize, GEMM_SMEM);
        cudaFuncSetAttribute(oproj_kernel,
                             cudaFuncAttributeMaxDynamicSharedMemorySize, GEMM_SMEM);
        cudaFuncSetAttribute(attn_f16_kernel,
                             cudaFuncAttributeMaxDynamicSharedMemorySize, ATTN_SMEM);
        smem_set = 1;
    }

    __half* gctx;
    cudaGetSymbolAddress((void**)&gctx, g_ctx);

    detect_mask_kernel<<<1, 256>>>((const unsigned char*)mk);
    prep_mask_kernel<<<B_, 256>>>(mk);
    wtrans_kernel<<<dim3(32, 32, 4), 256>>>(Wq, Wk, Wv, Wo);
    cvt_x_kernel<<<dim3(256, 3), 256>>>(q, k, v);

    qkv_proj_kernel<<<dim3(8, 160), 256, GEMM_SMEM>>>(bq, bk, bv);

    attn_f16_kernel<<<dim3(NQ_ / 128, H_, B_), 256, ATTN_SMEM>>>(ab, gctx);

    oproj_kernel<<<dim3(8, 32), 256, GEMM_SMEM>>>(bo, out);
}

// round 13
// speedup vs baseline: 5.9912x; 1.0280x over previous
#include <cuda_runtime.h>
#include <cuda_fp16.h>
#include <math.h>
#include <stdint.h>

#define B_     2
#define NQ_    1024
#define NK_    2048
#define D_     1024
#define H_     16
#define HD_    64
#define SCALE_ 0.125f

// fp16 operand storage (10-bit mantissa == tf32; all values O(1), range safe)
__device__ __half g_Q[(size_t)B_ * NQ_ * D_];        // pre-scaled by 0.125
__device__ __half g_K[(size_t)B_ * NK_ * D_];
__device__ __half g_Vt[(size_t)B_ * H_ * HD_ * NK_]; // V^T per (b,h): [d][key]
__device__ __half g_ctx[(size_t)B_ * NQ_ * D_];
__device__ __half g_Wt[(size_t)4 * D_ * D_];         // transposed Wq|Wk|Wv|Wo
__device__ __half g_Xh[(size_t)10240 * D_];          // inputs q|k|v
__device__ float  g_maskf[B_ * NK_];

__device__ __forceinline__ void mma_f16(float* d, const uint32_t* a, const uint32_t* b) {
    asm volatile(
        "mma.sync.aligned.m16n8k16.row.col.f32.f16.f16.f32 "
        "{%0,%1,%2,%3}, {%4,%5,%6,%7}, {%8,%9}, {%0,%1,%2,%3};"
        : "+f"(d[0]), "+f"(d[1]), "+f"(d[2]), "+f"(d[3])
        : "r"(a[0]), "r"(a[1]), "r"(a[2]), "r"(a[3]),
          "r"(b[0]), "r"(b[1]));
}

__device__ __forceinline__ void ldsm4(uint32_t* r, uint32_t addr) {
    asm volatile("ldmatrix.sync.aligned.m8n8.x4.shared.b16 {%0,%1,%2,%3}, [%4];"
                 : "=r"(r[0]), "=r"(r[1]), "=r"(r[2]), "=r"(r[3]) : "r"(addr));
}

__device__ __forceinline__ void cp16(uint32_t dst, const void* src) {
    asm volatile("cp.async.cg.shared.global [%0], [%1], 16;" :: "r"(dst), "l"(src));
}
__device__ __forceinline__ void cp_commit() { asm volatile("cp.async.commit_group;"); }
template <int N> __device__ __forceinline__ void cp_wait() {
    asm volatile("cp.async.wait_group %0;" :: "n"(N));
}

// streaming (evict-first) float2 load for the 256MB bias stream
__device__ __forceinline__ float2 ldcs2(const float* p) {
    float2 v;
    asm volatile("ld.global.cs.v2.f32 {%0,%1}, [%2];"
                 : "=f"(v.x), "=f"(v.y) : "l"(p));
    return v;
}

// Merged mask kernel: each block (one per batch) scans the raw bytes to infer
// dtype (u8 / i32 / f32), then builds the safe float mask for its batch row.
__global__ void prep_mask_kernel(const void* __restrict__ mptr) {
    const unsigned char* p8 = (const unsigned char*)mptr;
    int b = blockIdx.x;
    int tid = threadIdx.x;
    __shared__ int s_nonbin, s_unal, anyUnmasked;
    if (tid == 0) { s_nonbin = 0; s_unal = 0; anyUnmasked = 0; }
    __syncthreads();
    // dtype detection over the first B_*NK_ bytes (safe under all candidates)
    for (int i = tid; i < B_ * NK_; i += 256) {
        unsigned char v = p8[i];
        if (v > 1) s_nonbin = 1;
        else if (v == 1 && (i & 3)) s_unal = 1;
    }
    __syncthreads();
    int mode = s_nonbin ? 2 : (s_unal ? 0 : 1);

    float vals[NK_ / 256];
    #pragma unroll
    for (int x = 0; x < NK_ / 256; x++) {
        int i = tid + x * 256;
        float m;
        if (mode == 0)      m = p8[b * NK_ + i] ? 1.f : 0.f;
        else if (mode == 1) m = ((const int*)mptr)[b * NK_ + i] ? 1.f : 0.f;
        else                m = (((const float*)mptr)[b * NK_ + i] != 0.f) ? 1.f : 0.f;
        vals[x] = m;
        if (m == 0.f) anyUnmasked = 1;
    }
    __syncthreads();
    #pragma unroll
    for (int x = 0; x < NK_ / 256; x++) {
        int i = tid + x * 256;
        float m = vals[x];
        if (i == 0 && !anyUnmasked) m = 0.f;
        g_maskf[b * NK_ + i] = m;
    }
}

// Transpose + fp16-round weights: W[k][n] -> Wt[n][k]
__global__ __launch_bounds__(256) void wtrans_kernel(
    const float* __restrict__ w0, const float* __restrict__ w1,
    const float* __restrict__ w2, const float* __restrict__ w3)
{
    __shared__ float tile[32][33];
    int which = blockIdx.z;
    const float* s = (which == 0) ? w0 : (which == 1) ? w1 : (which == 2) ? w2 : w3;
    __half* d = g_Wt + (size_t)which * D_ * D_;
    int k0 = blockIdx.x * 32, n0 = blockIdx.y * 32;
    int tx = threadIdx.x & 31, ty = threadIdx.x >> 5;
    #pragma unroll
    for (int i = 0; i < 4; i++)
        tile[ty + i * 8][tx] = s[(size_t)(k0 + ty + i * 8) * D_ + n0 + tx];
    __syncthreads();
    #pragma unroll
    for (int i = 0; i < 4; i++)
        d[(size_t)(n0 + ty + i * 8) * D_ + k0 + tx] =
            __float2half_rn(tile[tx][ty + i * 8]);
}

// Convert raw q/k/v inputs to fp16
__global__ __launch_bounds__(256) void cvt_x_kernel(
    const float* __restrict__ q, const float* __restrict__ k, const float* __restrict__ v)
{
    int which = blockIdx.y;
    const float* s; __half* d; int n;
    if (which == 0)      { s = q; d = g_Xh;                     n = B_ * NQ_ * D_; }
    else if (which == 1) { s = k; d = g_Xh + (size_t)2048 * D_; n = B_ * NK_ * D_; }
    else                 { s = v; d = g_Xh + (size_t)6144 * D_; n = B_ * NK_ * D_; }
    __half2* dh = (__half2*)d;
    for (int i = blockIdx.x * blockDim.x + threadIdx.x;
         i < n / 4; i += gridDim.x * blockDim.x) {
        float4 x = ((const float4*)s)[i];
        dh[2 * i]     = __floats2half2_rn(x.x, x.y);
        dh[2 * i + 1] = __floats2half2_rn(x.z, x.w);
    }
}

// ---------------------------------------------------------------------------
// fp16 GEMM: Y = X[m][k] @ Wt[n][k]^T + bias.  BK=64 halves (128B rows),
// stride 72 halves (144B ≡ 16 mod 128 -> ldmatrix conflict-free).
// mode 0: fp32 store. mode 1: fp16*(scale) store. mode 2: scatter into g_Vt.
// ---------------------------------------------------------------------------
#define GS   72
#define GSTG 3
#define GEMM_SMEM ((GSTG * 64 * GS + GSTG * 128 * GS) * 2)

__device__ __forceinline__ void gemm_body_f16(
    const __half* __restrict__ X, const __half* __restrict__ Wt,
    const float* __restrict__ bias, void* __restrict__ Yv,
    int m0, int n0, float outScale, int mode, __half* sA, __half* sB)
{
    const int K = 1024, N = 1024, MROWS = 64, MT = 2;
    int tid  = threadIdx.x;
    int lane = tid & 31, warp = tid >> 5;
    int g = lane >> 2, t = lane & 3;
    int wm = (warp >> 2) * 32;
    int wn = (warp & 3) * 32;

    uint32_t sA_u = (uint32_t)__cvta_generic_to_shared(sA);
    uint32_t sB_u = (uint32_t)__cvta_generic_to_shared(sB);

    uint32_t a_base = (uint32_t)(((wm + (lane & 15)) * GS + ((lane & 16) ? 8 : 0)) * 2);
    uint32_t b_base = (uint32_t)(((wn + (lane & 7) + ((lane & 16) >> 1)) * GS
                                  + ((lane & 8) ? 8 : 0)) * 2);

    float acc[MT][4][4];
    #pragma unroll
    for (int i = 0; i < MT; i++)
        #pragma unroll
        for (int j = 0; j < 4; j++)
            #pragma unroll
            for (int c = 0; c < 4; c++) acc[i][j][c] = 0.f;

    auto issue = [&](int buf, int kc) {
        #pragma unroll
        for (int i = 0; i < MT; i++) {
            int c = tid + i * 256;
            int row = c >> 3, col = (c & 7) * 8;
            cp16(sA_u + (uint32_t)(((buf * MROWS + row) * GS + col) * 2),
                 X + (size_t)(m0 + row) * K + kc * 64 + col);
        }
        #pragma unroll
        for (int i = 0; i < 4; i++) {
            int c = tid + i * 256;
            int row = c >> 3, col = (c & 7) * 8;
            cp16(sB_u + (uint32_t)(((buf * 128 + row) * GS + col) * 2),
                 Wt + (size_t)(n0 + row) * K + kc * 64 + col);
        }
    };

    issue(0, 0); cp_commit();
    issue(1, 1); cp_commit();

    #pragma unroll 1
    for (int kc = 0; kc < 16; kc++) {
        int buf = kc % GSTG;
        if (kc < 15) cp_wait<1>(); else cp_wait<0>();
        __syncthreads();
        if (kc + 2 < 16) {
            issue((kc + 2) % GSTG, kc + 2);
            cp_commit();
        }

        uint32_t A0 = sA_u + (uint32_t)(buf * MROWS * GS * 2) + a_base;
        uint32_t B0 = sB_u + (uint32_t)(buf * 128 * GS * 2) + b_base;

        #pragma unroll
        for (int kt = 0; kt < 4; kt++) {
            uint32_t a[MT][4], kb[2][4];
            #pragma unroll
            for (int mt = 0; mt < MT; mt++)
                ldsm4(a[mt], A0 + (uint32_t)((mt * 16 * GS + kt * 16) * 2));
            #pragma unroll
            for (int n2 = 0; n2 < 2; n2++)
                ldsm4(kb[n2], B0 + (uint32_t)((n2 * 16 * GS + kt * 16) * 2));
            #pragma unroll
            for (int mt = 0; mt < MT; mt++)
                #pragma unroll
                for (int nt = 0; nt < 4; nt++)
                    mma_f16(acc[mt][nt], a[mt], &kb[nt >> 1][(nt & 1) * 2]);
        }
    }

    #pragma unroll
    for (int mt = 0; mt < MT; mt++) {
        int row = m0 + wm + mt * 16 + g;
        #pragma unroll
        for (int nt = 0; nt < 4; nt++) {
            int col = n0 + wn + nt * 8 + 2 * t;
            float2 bb = *(const float2*)&bias[col];
            if (mode == 1) {
                __half* Y = (__half*)Yv;
                *(__half2*)&Y[(size_t)row * N + col] =
                    __floats2half2_rn((acc[mt][nt][0] + bb.x) * outScale,
                                      (acc[mt][nt][1] + bb.y) * outScale);
                *(__half2*)&Y[(size_t)(row + 8) * N + col] =
                    __floats2half2_rn((acc[mt][nt][2] + bb.x) * outScale,
                                      (acc[mt][nt][3] + bb.y) * outScale);
            } else if (mode == 2) {
                __half* Vt = (__half*)Yv;
                int b   = row >> 11;
                int key = row & (NK_ - 1);
                int h   = col >> 6, d = col & 63;
                size_t base = ((size_t)((b * H_ + h) * HD_ + d)) * NK_ + key;
                Vt[base]            = __float2half_rn(acc[mt][nt][0] + bb.x);
                Vt[base + NK_]      = __float2half_rn(acc[mt][nt][1] + bb.y);
                Vt[base + 8]        = __float2half_rn(acc[mt][nt][2] + bb.x);
                Vt[base + NK_ + 8]  = __float2half_rn(acc[mt][nt][3] + bb.y);
            } else {
                float* Y = (float*)Yv;
                float2 o0 = make_float2(acc[mt][nt][0] + bb.x, acc[mt][nt][1] + bb.y);
                float2 o1 = make_float2(acc[mt][nt][2] + bb.x, acc[mt][nt][3] + bb.y);
                *(float2*)&Y[(size_t)row * N + col]       = o0;
                *(float2*)&Y[(size_t)(row + 8) * N + col] = o1;
            }
        }
    }
}

__global__ __launch_bounds__(256, 2) void qkv_proj_kernel(
    const float* __restrict__ bq, const float* __restrict__ bk,
    const float* __restrict__ bv)
{
    extern __shared__ __half smh[];
    int y = blockIdx.y;
    const __half *X, *W; const float* bias; void* Y; int m0; float sc; int mode;
    if (y < 32)      { X = g_Xh;                     W = g_Wt;               bias = bq; Y = g_Q;  m0 = y * 64;        sc = SCALE_; mode = 1; }
    else if (y < 96) { X = g_Xh + (size_t)2048 * D_; W = g_Wt + 1 * D_ * D_; bias = bk; Y = g_K;  m0 = (y - 32) * 64; sc = 1.0f;   mode = 1; }
    else             { X = g_Xh + (size_t)6144 * D_; W = g_Wt + 2 * D_ * D_; bias = bv; Y = g_Vt; m0 = (y - 96) * 64; sc = 1.0f;   mode = 2; }
    gemm_body_f16(X, W, bias, Y, m0, blockIdx.x * 128, sc, mode,
                  smh, smh + GSTG * 64 * GS);
}

__global__ __launch_bounds__(256, 2) void oproj_kernel(
    const float* __restrict__ bo, float* __restrict__ out)
{
    extern __shared__ __half smh[];
    gemm_body_f16(g_ctx, g_Wt + 3 * D_ * D_, bo, out,
                  blockIdx.y * 64, blockIdx.x * 128, 1.0f, 0,
                  smh, smh + GSTG * 64 * GS);
}

// ---------------------------------------------------------------------------
// fp16 flash attention (m16n8k16), 3-stage KV pipeline (wait<1> keeps one
// load in flight), streaming bias loads straight into the S accumulators.
// ---------------------------------------------------------------------------
#define SH 72
#define KVSTG 3
#define ATTN_SMEM ((KVSTG * 64 * SH + KVSTG * 64 * SH + 128 * SH) * 2)

__global__ __launch_bounds__(256, 2) void attn_f16_kernel(
    const float* __restrict__ bias, __half* __restrict__ ctx)
{
    extern __shared__ __half smh[];
    __half* sK  = smh;                               // [3][64][SH]
    __half* sVt = smh + KVSTG * 64 * SH;             // [3][64][SH]
    __half* sP  = smh + 2 * KVSTG * 64 * SH;         // [128][SH]

    int tid = threadIdx.x, lane = tid & 31, warp = tid >> 5;
    int g = lane >> 2, t = lane & 3;
    int b = blockIdx.z, h = blockIdx.y, q0 = blockIdx.x * 128;
    int wq = warp * 16;

    const __half* Qg  = g_Q + (size_t)(b * NQ_ + q0) * D_ + h * HD_;
    const __half* Kg  = g_K + (size_t)b * NK_ * D_ + h * HD_;
    const __half* Vtg = g_Vt + (size_t)(b * H_ + h) * HD_ * NK_;
    const float* biasg = bias + (((size_t)b * H_ + h) * NQ_ + q0) * NK_;
    const float* mg = g_maskf + b * NK_;

    uint32_t sK_u  = (uint32_t)__cvta_generic_to_shared(sK);
    uint32_t sVt_u = (uint32_t)__cvta_generic_to_shared(sVt);
    uint32_t sP_u  = (uint32_t)__cvta_generic_to_shared(sP);

    int arow = wq + (lane & 15);
    int acolh = (lane & 16) ? 8 : 0;
    int brow = (lane & 7) + ((lane & 16) >> 1);
    int bcolh = (lane & 8) ? 8 : 0;

    auto issueKV = [&](int buf, int k0) {
        #pragma unroll
        for (int i = 0; i < 2; i++) {
            int c = tid + i * 256;
            int row = c >> 3, col = (c & 7) * 8;
            cp16(sK_u + (uint32_t)(((buf * 64 + row) * SH + col) * 2),
                 Kg + (size_t)(k0 + row) * D_ + col);
            cp16(sVt_u + (uint32_t)(((buf * 64 + row) * SH + col) * 2),
                 Vtg + (size_t)row * NK_ + k0 + col);
        }
    };

    issueKV(0, 0);   cp_commit();
    issueKV(1, 64);  cp_commit();

    // Stage Q (fp16, pre-scaled) into sP
    #pragma unroll
    for (int i = 0; i < 4; i++) {
        int c = tid + i * 256;
        int row = c >> 3, col = (c & 7) * 8;
        *(uint4*)&sP[row * SH + col] = *(const uint4*)&Qg[(size_t)row * D_ + col];
    }
    __syncthreads();

    uint32_t qf[4][4];
    #pragma unroll
    for (int kt = 0; kt < 4; kt++)
        ldsm4(qf[kt], sP_u + (uint32_t)((arow * SH + kt * 16 + acolh) * 2));

    float oacc[8][4];
    #pragma unroll
    for (int nt = 0; nt < 8; nt++)
        #pragma unroll
        for (int c = 0; c < 4; c++) oacc[nt][c] = 0.f;
    float mr0 = -INFINITY, mr1 = -INFINITY, l0 = 0.f, l1 = 0.f;

    #pragma unroll 1
    for (int it = 0; it < NK_ / 64; it++) {
        int buf = it % KVSTG, k0 = it * 64;

        // bias pre-loaded (streaming) into accumulators
        float sacc[8][4];
        #pragma unroll
        for (int nt = 0; nt < 8; nt++) {
            int kc = k0 + nt * 8 + 2 * t;
            float2 b0v = ldcs2(&biasg[(size_t)(wq + g) * NK_ + kc]);
            float2 b1v = ldcs2(&biasg[(size_t)(wq + g + 8) * NK_ + kc]);
            sacc[nt][0] = b0v.x; sacc[nt][1] = b0v.y;
            sacc[nt][2] = b1v.x; sacc[nt][3] = b1v.y;
        }

        if (it < NK_ / 64 - 1) cp_wait<1>(); else cp_wait<0>();
        __syncthreads();
        if (it + 2 < NK_ / 64) {
            issueKV((it + 2) % KVSTG, k0 + 128);
            cp_commit();
        }

        uint32_t K0_u = sK_u  + (uint32_t)(buf * 64 * SH * 2);
        uint32_t V0_u = sVt_u + (uint32_t)(buf * 64 * SH * 2);

        // S = Q K^T
        #pragma unroll
        for (int kt = 0; kt < 4; kt++) {
            uint32_t kb[4][4];
            #pragma unroll
            for (int n2 = 0; n2 < 4; n2++)
                ldsm4(kb[n2], K0_u +
                      (uint32_t)(((n2 * 16 + brow) * SH + kt * 16 + bcolh) * 2));
            #pragma unroll
            for (int nt = 0; nt < 8; nt++)
                mma_f16(sacc[nt], qf[kt], &kb[nt >> 1][(nt & 1) * 2]);
        }

        float rmax0 = -INFINITY, rmax1 = -INFINITY;
        #pragma unroll
        for (int nt = 0; nt < 8; nt++) {
            int kc = k0 + nt * 8 + 2 * t;
            float2 mk = *(const float2*)&mg[kc];
            if (mk.x != 0.f) { sacc[nt][0] = -INFINITY; sacc[nt][2] = -INFINITY; }
            if (mk.y != 0.f) { sacc[nt][1] = -INFINITY; sacc[nt][3] = -INFINITY; }
            rmax0 = fmaxf(rmax0, fmaxf(sacc[nt][0], sacc[nt][1]));
            rmax1 = fmaxf(rmax1, fmaxf(sacc[nt][2], sacc[nt][3]));
        }
        rmax0 = fmaxf(rmax0, __shfl_xor_sync(0xffffffffu, rmax0, 1));
        rmax0 = fmaxf(rmax0, __shfl_xor_sync(0xffffffffu, rmax0, 2));
        rmax1 = fmaxf(rmax1, __shfl_xor_sync(0xffffffffu, rmax1, 1));
        rmax1 = fmaxf(rmax1, __shfl_xor_sync(0xffffffffu, rmax1, 2));

        float mn0 = fmaxf(mr0, rmax0), mn1 = fmaxf(mr1, rmax1);
        bool dead0 = (mn0 == -INFINITY), dead1 = (mn1 == -INFINITY);
        float al0 = dead0 ? 1.f : __expf(mr0 - mn0);
        float al1 = dead1 ? 1.f : __expf(mr1 - mn1);
        float sum0 = 0.f, sum1 = 0.f;

        #pragma unroll
        for (int nt = 0; nt < 8; nt++) {
            float p00 = dead0 ? 0.f : __expf(sacc[nt][0] - mn0);
            float p01 = dead0 ? 0.f : __expf(sacc[nt][1] - mn0);
            float p10 = dead1 ? 0.f : __expf(sacc[nt][2] - mn1);
            float p11 = dead1 ? 0.f : __expf(sacc[nt][3] - mn1);
            sum0 += p00 + p01;
            sum1 += p10 + p11;
            *(__half2*)&sP[(wq + g) * SH + nt * 8 + 2 * t]     = __floats2half2_rn(p00, p01);
            *(__half2*)&sP[(wq + g + 8) * SH + nt * 8 + 2 * t] = __floats2half2_rn(p10, p11);
        }
        sum0 += __shfl_xor_sync(0xffffffffu, sum0, 1);
        sum0 += __shfl_xor_sync(0xffffffffu, sum0, 2);
        sum1 += __shfl_xor_sync(0xffffffffu, sum1, 1);
        sum1 += __shfl_xor_sync(0xffffffffu, sum1, 2);

        mr0 = mn0; mr1 = mn1;
        l0 = l0 * al0 + sum0;
        l1 = l1 * al1 + sum1;
        #pragma unroll
        for (int nt = 0; nt < 8; nt++) {
            oacc[nt][0] *= al0; oacc[nt][1] *= al0;
            oacc[nt][2] *= al1; oacc[nt][3] *= al1;
        }
        __syncwarp();

        // O += P @ V
        #pragma unroll
        for (int kt = 0; kt < 4; kt++) {
            uint32_t pa[4];
            ldsm4(pa, sP_u + (uint32_t)((arow * SH + kt * 16 + acolh) * 2));
            uint32_t vb[4][4];
            #pragma unroll
            for (int n2 = 0; n2 < 4; n2++)
                ldsm4(vb[n2], V0_u +
                      (uint32_t)(((n2 * 16 + brow) * SH + kt * 16 + bcolh) * 2));
            #pragma unroll
            for (int nt = 0; nt < 8; nt++)
                mma_f16(oacc[nt], pa, &vb[nt >> 1][(nt & 1) * 2]);
        }
    }

    float inv0 = 1.f / l0, inv1 = 1.f / l1;
    size_t row0 = (size_t)(b * NQ_ + q0 + wq + g) * D_ + h * HD_;
    size_t row1 = row0 + 8 * D_;
    #pragma unroll
    for (int nt = 0; nt < 8; nt++) {
        int col = nt * 8 + 2 * t;
        *(__half2*)&ctx[row0 + col] =
            __floats2half2_rn(oacc[nt][0] * inv0, oacc[nt][1] * inv0);
        *(__half2*)&ctx[row1 + col] =
            __floats2half2_rn(oacc[nt][2] * inv1, oacc[nt][3] * inv1);
    }
}

extern "C" void kernel_launch(void* const* d_in, const int* in_sizes, int n_in,
                              void* d_out, int out_size)
{
    const float* q  = (const float*)d_in[0];
    const float* k  = (const float*)d_in[1];
    const float* v  = (const float*)d_in[2];
    const float* ab = (const float*)d_in[3];
    const void*  mk = d_in[4];
    const float* Wq = (const float*)d_in[5];
    const float* bq = (const float*)d_in[6];
    const float* Wk = (const float*)d_in[7];
    const float* bk = (const float*)d_in[8];
    const float* Wv = (const float*)d_in[9];
    const float* bv = (const float*)d_in[10];
    const float* Wo = (const float*)d_in[11];
    const float* bo = (const float*)d_in[12];
    float* out = (float*)d_out;

    static cudaStream_t s1, s2;
    static cudaEvent_t evFork, evJ1, evJ2;
    static int inited = 0;
    if (!inited) {
        cudaFuncSetAttribute(qkv_proj_kernel,
                             cudaFuncAttributeMaxDynamicSharedMemorySize, GEMM_SMEM);
        cudaFuncSetAttribute(oproj_kernel,
                             cudaFuncAttributeMaxDynamicSharedMemorySize, GEMM_SMEM);
        cudaFuncSetAttribute(attn_f16_kernel,
                             cudaFuncAttributeMaxDynamicSharedMemorySize, ATTN_SMEM);
        cudaStreamCreateWithFlags(&s1, cudaStreamNonBlocking);
        cudaStreamCreateWithFlags(&s2, cudaStreamNonBlocking);
        cudaEventCreateWithFlags(&evFork, cudaEventDisableTiming);
        cudaEventCreateWithFlags(&evJ1, cudaEventDisableTiming);
        cudaEventCreateWithFlags(&evJ2, cudaEventDisableTiming);
        inited = 1;
    }

    __half* gctx;
    cudaGetSymbolAddress((void**)&gctx, g_ctx);

    // Fork: prep kernels run concurrently on side streams.
    cudaEventRecord(evFork, 0);
    cudaStreamWaitEvent(s1, evFork, 0);
    cudaStreamWaitEvent(s2, evFork, 0);

    prep_mask_kernel<<<B_, 256, 0, s1>>>(mk);            // needed by attn
    wtrans_kernel<<<dim3(32, 32, 4), 256, 0, s2>>>(Wq, Wk, Wv, Wo);
    cvt_x_kernel<<<dim3(256, 3), 256>>>(q, k, v);        // main stream

    cudaEventRecord(evJ1, s1);
    cudaEventRecord(evJ2, s2);
    cudaStreamWaitEvent(0, evJ2, 0);                      // qkv needs Wt + Xh

    qkv_proj_kernel<<<dim3(8, 160), 256, GEMM_SMEM>>>(bq, bk, bv);

    cudaStreamWaitEvent(0, evJ1, 0);                      // attn needs mask too
    attn_f16_kernel<<<dim3(NQ_ / 128, H_, B_), 256, ATTN_SMEM>>>(ab, gctx);

    oproj_kernel<<<dim3(8, 32), 256, GEMM_SMEM>>>(bo, out);
}

// round 14
// speedup vs baseline: 6.2448x; 1.0423x over previous
#include <cuda_runtime.h>
#include <cuda_fp16.h>
#include <math.h>
#include <stdint.h>

#define B_     2
#define NQ_    1024
#define NK_    2048
#define D_     1024
#define H_     16
#define HD_    64
#define SCALE_ 0.125f

// fp16 operand storage (10-bit mantissa == tf32; all values O(1), range safe)
__device__ __half g_Q[(size_t)B_ * NQ_ * D_];        // pre-scaled by 0.125
__device__ __half g_K[(size_t)B_ * NK_ * D_];
__device__ __half g_Vt[(size_t)B_ * H_ * HD_ * NK_]; // V^T per (b,h): [d][key]
__device__ __half g_ctx[(size_t)B_ * NQ_ * D_];
__device__ __half g_Wt[(size_t)4 * D_ * D_];         // transposed Wq|Wk|Wv|Wo
__device__ __half g_Xh[(size_t)10240 * D_];          // inputs q|k|v
__device__ float  g_maskf[B_ * NK_];

__device__ __forceinline__ void mma_f16(float* d, const uint32_t* a, const uint32_t* b) {
    asm volatile(
        "mma.sync.aligned.m16n8k16.row.col.f32.f16.f16.f32 "
        "{%0,%1,%2,%3}, {%4,%5,%6,%7}, {%8,%9}, {%0,%1,%2,%3};"
        : "+f"(d[0]), "+f"(d[1]), "+f"(d[2]), "+f"(d[3])
        : "r"(a[0]), "r"(a[1]), "r"(a[2]), "r"(a[3]),
          "r"(b[0]), "r"(b[1]));
}

__device__ __forceinline__ void ldsm4(uint32_t* r, uint32_t addr) {
    asm volatile("ldmatrix.sync.aligned.m8n8.x4.shared.b16 {%0,%1,%2,%3}, [%4];"
                 : "=r"(r[0]), "=r"(r[1]), "=r"(r[2]), "=r"(r[3]) : "r"(addr));
}

__device__ __forceinline__ void cp16(uint32_t dst, const void* src) {
    asm volatile("cp.async.cg.shared.global [%0], [%1], 16;" :: "r"(dst), "l"(src));
}
__device__ __forceinline__ void cp_commit() { asm volatile("cp.async.commit_group;"); }
template <int N> __device__ __forceinline__ void cp_wait() {
    asm volatile("cp.async.wait_group %0;" :: "n"(N));
}

// streaming (evict-first) float2 load for the 256MB bias stream
__device__ __forceinline__ float2 ldcs2(const float* p) {
    float2 v;
    asm volatile("ld.global.cs.v2.f32 {%0,%1}, [%2];"
                 : "=f"(v.x), "=f"(v.y) : "l"(p));
    return v;
}

// Merged mask kernel: dtype detection + safe float mask build.
__global__ void prep_mask_kernel(const void* __restrict__ mptr) {
    const unsigned char* p8 = (const unsigned char*)mptr;
    int b = blockIdx.x;
    int tid = threadIdx.x;
    __shared__ int s_nonbin, s_unal, anyUnmasked;
    if (tid == 0) { s_nonbin = 0; s_unal = 0; anyUnmasked = 0; }
    __syncthreads();
    for (int i = tid; i < B_ * NK_; i += 256) {
        unsigned char v = p8[i];
        if (v > 1) s_nonbin = 1;
        else if (v == 1 && (i & 3)) s_unal = 1;
    }
    __syncthreads();
    int mode = s_nonbin ? 2 : (s_unal ? 0 : 1);

    float vals[NK_ / 256];
    #pragma unroll
    for (int x = 0; x < NK_ / 256; x++) {
        int i = tid + x * 256;
        float m;
        if (mode == 0)      m = p8[b * NK_ + i] ? 1.f : 0.f;
        else if (mode == 1) m = ((const int*)mptr)[b * NK_ + i] ? 1.f : 0.f;
        else                m = (((const float*)mptr)[b * NK_ + i] != 0.f) ? 1.f : 0.f;
        vals[x] = m;
        if (m == 0.f) anyUnmasked = 1;
    }
    __syncthreads();
    #pragma unroll
    for (int x = 0; x < NK_ / 256; x++) {
        int i = tid + x * 256;
        float m = vals[x];
        if (i == 0 && !anyUnmasked) m = 0.f;
        g_maskf[b * NK_ + i] = m;
    }
}

// Transpose + fp16-round weights: W[k][n] -> Wt[n][k]
__global__ __launch_bounds__(256) void wtrans_kernel(
    const float* __restrict__ w0, const float* __restrict__ w1,
    const float* __restrict__ w2, const float* __restrict__ w3)
{
    __shared__ float tile[32][33];
    int which = blockIdx.z;
    const float* s = (which == 0) ? w0 : (which == 1) ? w1 : (which == 2) ? w2 : w3;
    __half* d = g_Wt + (size_t)which * D_ * D_;
    int k0 = blockIdx.x * 32, n0 = blockIdx.y * 32;
    int tx = threadIdx.x & 31, ty = threadIdx.x >> 5;
    #pragma unroll
    for (int i = 0; i < 4; i++)
        tile[ty + i * 8][tx] = s[(size_t)(k0 + ty + i * 8) * D_ + n0 + tx];
    __syncthreads();
    #pragma unroll
    for (int i = 0; i < 4; i++)
        d[(size_t)(n0 + ty + i * 8) * D_ + k0 + tx] =
            __float2half_rn(tile[tx][ty + i * 8]);
}

// Convert raw q/k/v inputs to fp16
__global__ __launch_bounds__(256) void cvt_x_kernel(
    const float* __restrict__ q, const float* __restrict__ k, const float* __restrict__ v)
{
    int which = blockIdx.y;
    const float* s; __half* d; int n;
    if (which == 0)      { s = q; d = g_Xh;                     n = B_ * NQ_ * D_; }
    else if (which == 1) { s = k; d = g_Xh + (size_t)2048 * D_; n = B_ * NK_ * D_; }
    else                 { s = v; d = g_Xh + (size_t)6144 * D_; n = B_ * NK_ * D_; }
    __half2* dh = (__half2*)d;
    for (int i = blockIdx.x * blockDim.x + threadIdx.x;
         i < n / 4; i += gridDim.x * blockDim.x) {
        float4 x = ((const float4*)s)[i];
        dh[2 * i]     = __floats2half2_rn(x.x, x.y);
        dh[2 * i + 1] = __floats2half2_rn(x.z, x.w);
    }
}

// ---------------------------------------------------------------------------
// fp16 GEMM: Y = X[m][k] @ Wt[n][k]^T + bias.  BK=64 halves (128B rows),
// stride 72 halves (144B ≡ 16 mod 128 -> ldmatrix conflict-free).
// 2-stage pipeline + 3 CTAs/SM (occupancy over prefetch depth).
// mode 0: fp32 store. mode 1: fp16*(scale) store. mode 2: scatter into g_Vt.
// ---------------------------------------------------------------------------
#define GS   72
#define GSTG 2
#define GEMM_SMEM ((GSTG * 64 * GS + GSTG * 128 * GS) * 2)

__device__ __forceinline__ void gemm_body_f16(
    const __half* __restrict__ X, const __half* __restrict__ Wt,
    const float* __restrict__ bias, void* __restrict__ Yv,
    int m0, int n0, float outScale, int mode, __half* sA, __half* sB)
{
    const int K = 1024, N = 1024, MROWS = 64, MT = 2;
    int tid  = threadIdx.x;
    int lane = tid & 31, warp = tid >> 5;
    int g = lane >> 2, t = lane & 3;
    int wm = (warp >> 2) * 32;
    int wn = (warp & 3) * 32;

    uint32_t sA_u = (uint32_t)__cvta_generic_to_shared(sA);
    uint32_t sB_u = (uint32_t)__cvta_generic_to_shared(sB);

    uint32_t a_base = (uint32_t)(((wm + (lane & 15)) * GS + ((lane & 16) ? 8 : 0)) * 2);
    uint32_t b_base = (uint32_t)(((wn + (lane & 7) + ((lane & 16) >> 1)) * GS
                                  + ((lane & 8) ? 8 : 0)) * 2);

    float acc[MT][4][4];
    #pragma unroll
    for (int i = 0; i < MT; i++)
        #pragma unroll
        for (int j = 0; j < 4; j++)
            #pragma unroll
            for (int c = 0; c < 4; c++) acc[i][j][c] = 0.f;

    auto issue = [&](int buf, int kc) {
        #pragma unroll
        for (int i = 0; i < MT; i++) {
            int c = tid + i * 256;
            int row = c >> 3, col = (c & 7) * 8;
            cp16(sA_u + (uint32_t)(((buf * MROWS + row) * GS + col) * 2),
                 X + (size_t)(m0 + row) * K + kc * 64 + col);
        }
        #pragma unroll
        for (int i = 0; i < 4; i++) {
            int c = tid + i * 256;
            int row = c >> 3, col = (c & 7) * 8;
            cp16(sB_u + (uint32_t)(((buf * 128 + row) * GS + col) * 2),
                 Wt + (size_t)(n0 + row) * K + kc * 64 + col);
        }
    };

    issue(0, 0); cp_commit();

    #pragma unroll 1
    for (int kc = 0; kc < 16; kc++) {
        int buf = kc & 1;
        cp_wait<0>();
        __syncthreads();               // tile kc ready; all warps done with kc-1
        if (kc + 1 < 16) {
            issue(buf ^ 1, kc + 1);
            cp_commit();
        }

        uint32_t A0 = sA_u + (uint32_t)(buf * MROWS * GS * 2) + a_base;
        uint32_t B0 = sB_u + (uint32_t)(buf * 128 * GS * 2) + b_base;

        #pragma unroll
        for (int kt = 0; kt < 4; kt++) {
            uint32_t a[MT][4], kb[2][4];
            #pragma unroll
            for (int mt = 0; mt < MT; mt++)
                ldsm4(a[mt], A0 + (uint32_t)((mt * 16 * GS + kt * 16) * 2));
            #pragma unroll
            for (int n2 = 0; n2 < 2; n2++)
                ldsm4(kb[n2], B0 + (uint32_t)((n2 * 16 * GS + kt * 16) * 2));
            #pragma unroll
            for (int mt = 0; mt < MT; mt++)
                #pragma unroll
                for (int nt = 0; nt < 4; nt++)
                    mma_f16(acc[mt][nt], a[mt], &kb[nt >> 1][(nt & 1) * 2]);
        }
    }

    #pragma unroll
    for (int mt = 0; mt < MT; mt++) {
        int row = m0 + wm + mt * 16 + g;
        #pragma unroll
        for (int nt = 0; nt < 4; nt++) {
            int col = n0 + wn + nt * 8 + 2 * t;
            float2 bb = *(const float2*)&bias[col];
            if (mode == 1) {
                __half* Y = (__half*)Yv;
                *(__half2*)&Y[(size_t)row * N + col] =
                    __floats2half2_rn((acc[mt][nt][0] + bb.x) * outScale,
                                      (acc[mt][nt][1] + bb.y) * outScale);
                *(__half2*)&Y[(size_t)(row + 8) * N + col] =
                    __floats2half2_rn((acc[mt][nt][2] + bb.x) * outScale,
                                      (acc[mt][nt][3] + bb.y) * outScale);
            } else if (mode == 2) {
                __half* Vt = (__half*)Yv;
                int b   = row >> 11;
                int key = row & (NK_ - 1);
                int h   = col >> 6, d = col & 63;
                size_t base = ((size_t)((b * H_ + h) * HD_ + d)) * NK_ + key;
                Vt[base]            = __float2half_rn(acc[mt][nt][0] + bb.x);
                Vt[base + NK_]      = __float2half_rn(acc[mt][nt][1] + bb.y);
                Vt[base + 8]        = __float2half_rn(acc[mt][nt][2] + bb.x);
                Vt[base + NK_ + 8]  = __float2half_rn(acc[mt][nt][3] + bb.y);
            } else {
                float* Y = (float*)Yv;
                float2 o0 = make_float2(acc[mt][nt][0] + bb.x, acc[mt][nt][1] + bb.y);
                float2 o1 = make_float2(acc[mt][nt][2] + bb.x, acc[mt][nt][3] + bb.y);
                *(float2*)&Y[(size_t)row * N + col]       = o0;
                *(float2*)&Y[(size_t)(row + 8) * N + col] = o1;
            }
        }
    }
}

__global__ __launch_bounds__(256, 3) void qkv_proj_kernel(
    const float* __restrict__ bq, const float* __restrict__ bk,
    const float* __restrict__ bv)
{
    extern __shared__ __half smh[];
    int y = blockIdx.y;
    const __half *X, *W; const float* bias; void* Y; int m0; float sc; int mode;
    if (y < 32)      { X = g_Xh;                     W = g_Wt;               bias = bq; Y = g_Q;  m0 = y * 64;        sc = SCALE_; mode = 1; }
    else if (y < 96) { X = g_Xh + (size_t)2048 * D_; W = g_Wt + 1 * D_ * D_; bias = bk; Y = g_K;  m0 = (y - 32) * 64; sc = 1.0f;   mode = 1; }
    else             { X = g_Xh + (size_t)6144 * D_; W = g_Wt + 2 * D_ * D_; bias = bv; Y = g_Vt; m0 = (y - 96) * 64; sc = 1.0f;   mode = 2; }
    gemm_body_f16(X, W, bias, Y, m0, blockIdx.x * 128, sc, mode,
                  smh, smh + GSTG * 64 * GS);
}

__global__ __launch_bounds__(256, 3) void oproj_kernel(
    const float* __restrict__ bo, float* __restrict__ out)
{
    extern __shared__ __half smh[];
    gemm_body_f16(g_ctx, g_Wt + 3 * D_ * D_, bo, out,
                  blockIdx.y * 64, blockIdx.x * 128, 1.0f, 0,
                  smh, smh + GSTG * 64 * GS);
}

// ---------------------------------------------------------------------------
// fp16 flash attention (m16n8k16), 3-stage KV pipeline, streaming bias loads.
// ---------------------------------------------------------------------------
#define SH 72
#define KVSTG 3
#define ATTN_SMEM ((KVSTG * 64 * SH + KVSTG * 64 * SH + 128 * SH) * 2)

__global__ __launch_bounds__(256, 2) void attn_f16_kernel(
    const float* __restrict__ bias, __half* __restrict__ ctx)
{
    extern __shared__ __half smh[];
    __half* sK  = smh;                               // [3][64][SH]
    __half* sVt = smh + KVSTG * 64 * SH;             // [3][64][SH]
    __half* sP  = smh + 2 * KVSTG * 64 * SH;         // [128][SH]

    int tid = threadIdx.x, lane = tid & 31, warp = tid >> 5;
    int g = lane >> 2, t = lane & 3;
    int b = blockIdx.z, h = blockIdx.y, q0 = blockIdx.x * 128;
    int wq = warp * 16;

    const __half* Qg  = g_Q + (size_t)(b * NQ_ + q0) * D_ + h * HD_;
    const __half* Kg  = g_K + (size_t)b * NK_ * D_ + h * HD_;
    const __half* Vtg = g_Vt + (size_t)(b * H_ + h) * HD_ * NK_;
    const float* biasg = bias + (((size_t)b * H_ + h) * NQ_ + q0) * NK_;
    const float* mg = g_maskf + b * NK_;

    uint32_t sK_u  = (uint32_t)__cvta_generic_to_shared(sK);
    uint32_t sVt_u = (uint32_t)__cvta_generic_to_shared(sVt);
    uint32_t sP_u  = (uint32_t)__cvta_generic_to_shared(sP);

    int arow = wq + (lane & 15);
    int acolh = (lane & 16) ? 8 : 0;
    int brow = (lane & 7) + ((lane & 16) >> 1);
    int bcolh = (lane & 8) ? 8 : 0;

    auto issueKV = [&](int buf, int k0) {
        #pragma unroll
        for (int i = 0; i < 2; i++) {
            int c = tid + i * 256;
            int row = c >> 3, col = (c & 7) * 8;
            cp16(sK_u + (uint32_t)(((buf * 64 + row) * SH + col) * 2),
                 Kg + (size_t)(k0 + row) * D_ + col);
            cp16(sVt_u + (uint32_t)(((buf * 64 + row) * SH + col) * 2),
                 Vtg + (size_t)row * NK_ + k0 + col);
        }
    };

    issueKV(0, 0);   cp_commit();
    issueKV(1, 64);  cp_commit();

    // Stage Q (fp16, pre-scaled) into sP
    #pragma unroll
    for (int i = 0; i < 4; i++) {
        int c = tid + i * 256;
        int row = c >> 3, col = (c & 7) * 8;
        *(uint4*)&sP[row * SH + col] = *(const uint4*)&Qg[(size_t)row * D_ + col];
    }
    __syncthreads();

    uint32_t qf[4][4];
    #pragma unroll
    for (int kt = 0; kt < 4; kt++)
        ldsm4(qf[kt], sP_u + (uint32_t)((arow * SH + kt * 16 + acolh) * 2));

    float oacc[8][4];
    #pragma unroll
    for (int nt = 0; nt < 8; nt++)
        #pragma unroll
        for (int c = 0; c < 4; c++) oacc[nt][c] = 0.f;
    float mr0 = -INFINITY, mr1 = -INFINITY, l0 = 0.f, l1 = 0.f;

    #pragma unroll 1
    for (int it = 0; it < NK_ / 64; it++) {
        int buf = it % KVSTG, k0 = it * 64;

        float sacc[8][4];
        #pragma unroll
        for (int nt = 0; nt < 8; nt++) {
            int kc = k0 + nt * 8 + 2 * t;
            float2 b0v = ldcs2(&biasg[(size_t)(wq + g) * NK_ + kc]);
            float2 b1v = ldcs2(&biasg[(size_t)(wq + g + 8) * NK_ + kc]);
            sacc[nt][0] = b0v.x; sacc[nt][1] = b0v.y;
            sacc[nt][2] = b1v.x; sacc[nt][3] = b1v.y;
        }

        if (it < NK_ / 64 - 1) cp_wait<1>(); else cp_wait<0>();
        __syncthreads();
        if (it + 2 < NK_ / 64) {
            issueKV((it + 2) % KVSTG, k0 + 128);
            cp_commit();
        }

        uint32_t K0_u = sK_u  + (uint32_t)(buf * 64 * SH * 2);
        uint32_t V0_u = sVt_u + (uint32_t)(buf * 64 * SH * 2);

        #pragma unroll
        for (int kt = 0; kt < 4; kt++) {
            uint32_t kb[4][4];
            #pragma unroll
            for (int n2 = 0; n2 < 4; n2++)
                ldsm4(kb[n2], K0_u +
                      (uint32_t)(((n2 * 16 + brow) * SH + kt * 16 + bcolh) * 2));
            #pragma unroll
            for (int nt = 0; nt < 8; nt++)
                mma_f16(sacc[nt], qf[kt], &kb[nt >> 1][(nt & 1) * 2]);
        }

        float rmax0 = -INFINITY, rmax1 = -INFINITY;
        #pragma unroll
        for (int nt = 0; nt < 8; nt++) {
            int kc = k0 + nt * 8 + 2 * t;
            float2 mk = *(const float2*)&mg[kc];
            if (mk.x != 0.f) { sacc[nt][0] = -INFINITY; sacc[nt][2] = -INFINITY; }
            if (mk.y != 0.f) { sacc[nt][1] = -INFINITY; sacc[nt][3] = -INFINITY; }
            rmax0 = fmaxf(rmax0, fmaxf(sacc[nt][0], sacc[nt][1]));
            rmax1 = fmaxf(rmax1, fmaxf(sacc[nt][2], sacc[nt][3]));
        }
        rmax0 = fmaxf(rmax0, __shfl_xor_sync(0xffffffffu, rmax0, 1));
        rmax0 = fmaxf(rmax0, __shfl_xor_sync(0xffffffffu, rmax0, 2));
        rmax1 = fmaxf(rmax1, __shfl_xor_sync(0xffffffffu, rmax1, 1));
        rmax1 = fmaxf(rmax1, __shfl_xor_sync(0xffffffffu, rmax1, 2));

        float mn0 = fmaxf(mr0, rmax0), mn1 = fmaxf(mr1, rmax1);
        bool dead0 = (mn0 == -INFINITY), dead1 = (mn1 == -INFINITY);
        float al0 = dead0 ? 1.f : __expf(mr0 - mn0);
        float al1 = dead1 ? 1.f : __expf(mr1 - mn1);
        float sum0 = 0.f, sum1 = 0.f;

        #pragma unroll
        for (int nt = 0; nt < 8; nt++) {
            float p00 = dead0 ? 0.f : __expf(sacc[nt][0] - mn0);
            float p01 = dead0 ? 0.f : __expf(sacc[nt][1] - mn0);
            float p10 = dead1 ? 0.f : __expf(sacc[nt][2] - mn1);
            float p11 = dead1 ? 0.f : __expf(sacc[nt][3] - mn1);
            sum0 += p00 + p01;
            sum1 += p10 + p11;
            *(__half2*)&sP[(wq + g) * SH + nt * 8 + 2 * t]     = __floats2half2_rn(p00, p01);
            *(__half2*)&sP[(wq + g + 8) * SH + nt * 8 + 2 * t] = __floats2half2_rn(p10, p11);
        }
        sum0 += __shfl_xor_sync(0xffffffffu, sum0, 1);
        sum0 += __shfl_xor_sync(0xffffffffu, sum0, 2);
        sum1 += __shfl_xor_sync(0xffffffffu, sum1, 1);
        sum1 += __shfl_xor_sync(0xffffffffu, sum1, 2);

        mr0 = mn0; mr1 = mn1;
        l0 = l0 * al0 + sum0;
        l1 = l1 * al1 + sum1;
        #pragma unroll
        for (int nt = 0; nt < 8; nt++) {
            oacc[nt][0] *= al0; oacc[nt][1] *= al0;
            oacc[nt][2] *= al1; oacc[nt][3] *= al1;
        }
        __syncwarp();

        #pragma unroll
        for (int kt = 0; kt < 4; kt++) {
            uint32_t pa[4];
            ldsm4(pa, sP_u + (uint32_t)((arow * SH + kt * 16 + acolh) * 2));
            uint32_t vb[4][4];
            #pragma unroll
            for (int n2 = 0; n2 < 4; n2++)
                ldsm4(vb[n2], V0_u +
                      (uint32_t)(((n2 * 16 + brow) * SH + kt * 16 + bcolh) * 2));
            #pragma unroll
            for (int nt = 0; nt < 8; nt++)
                mma_f16(oacc[nt], pa, &vb[nt >> 1][(nt & 1) * 2]);
        }
    }

    float inv0 = 1.f / l0, inv1 = 1.f / l1;
    size_t row0 = (size_t)(b * NQ_ + q0 + wq + g) * D_ + h * HD_;
    size_t row1 = row0 + 8 * D_;
    #pragma unroll
    for (int nt = 0; nt < 8; nt++) {
        int col = nt * 8 + 2 * t;
        *(__half2*)&ctx[row0 + col] =
            __floats2half2_rn(oacc[nt][0] * inv0, oacc[nt][1] * inv0);
        *(__half2*)&ctx[row1 + col] =
            __floats2half2_rn(oacc[nt][2] * inv1, oacc[nt][3] * inv1);
    }
}

extern "C" void kernel_launch(void* const* d_in, const int* in_sizes, int n_in,
                              void* d_out, int out_size)
{
    const float* q  = (const float*)d_in[0];
    const float* k  = (const float*)d_in[1];
    const float* v  = (const float*)d_in[2];
    const float* ab = (const float*)d_in[3];
    const void*  mk = d_in[4];
    const float* Wq = (const float*)d_in[5];
    const float* bq = (const float*)d_in[6];
    const float* Wk = (const float*)d_in[7];
    const float* bk = (const float*)d_in[8];
    const float* Wv = (const float*)d_in[9];
    const float* bv = (const float*)d_in[10];
    const float* Wo = (const float*)d_in[11];
    const float* bo = (const float*)d_in[12];
    float* out = (float*)d_out;

    static cudaStream_t s1, s2;
    static cudaEvent_t evFork, evJ1, evJ2;
    static int inited = 0;
    if (!inited) {
        cudaFuncSetAttribute(qkv_proj_kernel,
                             cudaFuncAttributeMaxDynamicSharedMemorySize, GEMM_SMEM);
        cudaFuncSetAttribute(oproj_kernel,
                             cudaFuncAttributeMaxDynamicSharedMemorySize, GEMM_SMEM);
        cudaFuncSetAttribute(attn_f16_kernel,
                             cudaFuncAttributeMaxDynamicSharedMemorySize, ATTN_SMEM);
        cudaStreamCreateWithFlags(&s1, cudaStreamNonBlocking);
        cudaStreamCreateWithFlags(&s2, cudaStreamNonBlocking);
        cudaEventCreateWithFlags(&evFork, cudaEventDisableTiming);
        cudaEventCreateWithFlags(&evJ1, cudaEventDisableTiming);
        cudaEventCreateWithFlags(&evJ2, cudaEventDisableTiming);
        inited = 1;
    }

    __half* gctx;
    cudaGetSymbolAddress((void**)&gctx, g_ctx);

    // Fork: prep kernels run concurrently on side streams.
    cudaEventRecord(evFork, 0);
    cudaStreamWaitEvent(s1, evFork, 0);
    cudaStreamWaitEvent(s2, evFork, 0);

    prep_mask_kernel<<<B_, 256, 0, s1>>>(mk);
    wtrans_kernel<<<dim3(32, 32, 4), 256, 0, s2>>>(Wq, Wk, Wv, Wo);
    cvt_x_kernel<<<dim3(256, 3), 256>>>(q, k, v);

    cudaEventRecord(evJ1, s1);
    cudaEventRecord(evJ2, s2);
    cudaStreamWaitEvent(0, evJ2, 0);

    qkv_proj_kernel<<<dim3(8, 160), 256, GEMM_SMEM>>>(bq, bk, bv);

    cudaStreamWaitEvent(0, evJ1, 0);
    attn_f16_kernel<<<dim3(NQ_ / 128, H_, B_), 256, ATTN_SMEM>>>(ab, gctx);

    oproj_kernel<<<dim3(8, 32), 256, GEMM_SMEM>>>(bo, out);
}